// round 1
// baseline (speedup 1.0000x reference)
#include <cuda_runtime.h>

#define BATCH 16384
#define HB 120
#define BD 9
#define NSEQ (BATCH*BD)   /* 147456 */
#define NS 32
#define NF 15

// scratch (no cudaMalloc allowed)
__device__ float g_buf1[NSEQ*HB];      // attn2 output, transposed: [(b*9+d)*120 + s]
__device__ float g_buf2[NSEQ*HB];      // attn4 output: [n*120 + t]
__device__ float g_wT[4*HB*HB];        // transposed wq4,wk4,wv4,wo4

__device__ __forceinline__ float sigf(float x){ return 1.0f/(1.0f+__expf(-x)); }
__device__ __forceinline__ float tanhe(float x){ return 1.0f - 2.0f/(__expf(2.0f*x)+1.0f); }
__device__ __forceinline__ float phif(float x){ return x>0.0f ? x+1.0f : __expf(x); }

// ---------------------------------------------------------------- weights transpose
__global__ void k_transpose_w(const float* __restrict__ wq, const float* __restrict__ wk,
                              const float* __restrict__ wv, const float* __restrict__ wo){
    int idx = blockIdx.x*blockDim.x + threadIdx.x;
    if (idx >= 4*HB*HB) return;
    int m = idx/(HB*HB); int i = idx - m*(HB*HB);
    int a = i/HB, b = i - a*HB;
    const float* src = (m==0)?wq : (m==1)?wk : (m==2)?wv : wo;
    g_wT[idx] = src[b*HB + a];
}

// ---------------------------------------------------------------- BN + lin_attn_2 + transpose
__global__ __launch_bounds__(128) void k_attn2(
    const float* __restrict__ x,
    const float* __restrict__ bng, const float* __restrict__ bnb,
    const float* __restrict__ bnm, const float* __restrict__ bnv,
    const float* __restrict__ wq, const float* __restrict__ wk,
    const float* __restrict__ wv, const float* __restrict__ wo,
    const float* __restrict__ bo, const float* __restrict__ lg,
    const float* __restrict__ lb)
{
    __shared__ float xs[HB*13], qs[HB*13], ks[HB*13], vs[HB*13];
    __shared__ float wqs[81], wks[81], wvs[81], wos[81];
    __shared__ float kvs[81], ksum[9], bos[9], lgs[9], lbs[9];
    int b = blockIdx.x, tid = threadIdx.x;

    for (int i = tid; i < 1080; i += 128){
        float val = (x[(size_t)b*1080 + i] - bnm[i]) * rsqrtf(bnv[i] + 1e-5f) * bng[i] + bnb[i];
        xs[(i/9)*13 + (i%9)] = val;
    }
    if (tid < 81){ wqs[tid]=wq[tid]; wks[tid]=wk[tid]; wvs[tid]=wv[tid]; wos[tid]=wo[tid]; }
    if (tid < 9){ bos[tid]=bo[tid]; lgs[tid]=lg[tid]; lbs[tid]=lb[tid]; }
    __syncthreads();

    if (tid < HB){
        float xr[9];
        #pragma unroll
        for (int d=0; d<9; d++) xr[d] = xs[tid*13+d];
        #pragma unroll
        for (int e=0; e<9; e++){
            float aq=0.f, ak=0.f, av=0.f;
            #pragma unroll
            for (int d=0; d<9; d++){
                aq = fmaf(xr[d], wqs[e*9+d], aq);
                ak = fmaf(xr[d], wks[e*9+d], ak);
                av = fmaf(xr[d], wvs[e*9+d], av);
            }
            qs[tid*13+e] = phif(aq);
            ks[tid*13+e] = phif(ak);
            vs[tid*13+e] = av;
        }
    }
    __syncthreads();

    if (tid < 81){
        int d = tid/9, e = tid%9;
        float acc = 0.f;
        for (int s=0; s<HB; s++) acc = fmaf(ks[s*13+d], vs[s*13+e], acc);
        kvs[tid] = acc;
    } else if (tid < 90){
        int e = tid - 81;
        float acc = 0.f;
        for (int s=0; s<HB; s++) acc += ks[s*13+e];
        ksum[e] = acc;
    }
    __syncthreads();

    if (tid < HB){
        float q[9], o[9];
        float den = 0.f;
        #pragma unroll
        for (int e=0; e<9; e++){ q[e] = qs[tid*13+e]; den = fmaf(q[e], ksum[e], den); }
        float inv = 1.0f / fmaxf(den, 1e-6f);
        #pragma unroll
        for (int e=0; e<9; e++){
            float num = 0.f;
            #pragma unroll
            for (int d=0; d<9; d++) num = fmaf(q[d], kvs[d*9+e], num);
            o[e] = num * inv;
        }
        float y[9]; float mu = 0.f;
        #pragma unroll
        for (int f=0; f<9; f++){
            float acc = bos[f] + o[f];
            #pragma unroll
            for (int e=0; e<9; e++) acc = fmaf(o[e], wos[f*9+e], acc);
            y[f] = acc; mu += acc;
        }
        mu *= (1.0f/9.0f);
        float var = 0.f;
        #pragma unroll
        for (int f=0; f<9; f++){ float dd = y[f]-mu; var = fmaf(dd, dd, var); }
        var *= (1.0f/9.0f);
        float rs = rsqrtf(var + 1e-5f);
        #pragma unroll
        for (int f=0; f<9; f++){
            g_buf1[(size_t)b*1080 + f*HB + tid] = (y[f]-mu)*rs*lgs[f] + lbs[f];
        }
    }
}

// ---------------------------------------------------------------- lin_attn_4 (S=1 collapsed)
__global__ __launch_bounds__(128) void k_attn4(
    const float* __restrict__ bo4, const float* __restrict__ lg4,
    const float* __restrict__ lb4)
{
    __shared__ float xsT[HB*20];
    __shared__ float vsT[HB*20];
    __shared__ float red1[4*16], red2[4*16];
    __shared__ float fac[16], mus[16], rss[16];
    int tid = threadIdx.x;
    int base = blockIdx.x * 16;

    for (int i = tid; i < 16*HB; i += 128){
        int r = i / HB, d = i - r*HB;
        xsT[d*20 + r] = g_buf1[(size_t)(base + r)*HB + d];
    }
    __syncthreads();

    bool valid = tid < HB;
    int e = valid ? tid : 0;
    const float* wqT = g_wT;
    const float* wkT = g_wT + HB*HB;
    const float* wvT = g_wT + 2*HB*HB;
    const float* woT = g_wT + 3*HB*HB;

    float qa[16], ka[16], va[16];
    #pragma unroll
    for (int r=0; r<16; r++){ qa[r]=0.f; ka[r]=0.f; va[r]=0.f; }

    const float4* xp4 = (const float4*)xsT;
    #pragma unroll 2
    for (int d=0; d<HB; d++){
        float wqv = wqT[d*HB + e];
        float wkv = wkT[d*HB + e];
        float wvv = wvT[d*HB + e];
        float4 x0 = xp4[d*5+0], x1 = xp4[d*5+1], x2 = xp4[d*5+2], x3 = xp4[d*5+3];
        float xv[16];
        xv[0]=x0.x; xv[1]=x0.y; xv[2]=x0.z; xv[3]=x0.w;
        xv[4]=x1.x; xv[5]=x1.y; xv[6]=x1.z; xv[7]=x1.w;
        xv[8]=x2.x; xv[9]=x2.y; xv[10]=x2.z; xv[11]=x2.w;
        xv[12]=x3.x; xv[13]=x3.y; xv[14]=x3.z; xv[15]=x3.w;
        #pragma unroll
        for (int r=0; r<16; r++){
            qa[r] = fmaf(wqv, xv[r], qa[r]);
            ka[r] = fmaf(wkv, xv[r], ka[r]);
            va[r] = fmaf(wvv, xv[r], va[r]);
        }
    }

    float qk[16];
    #pragma unroll
    for (int r=0; r<16; r++) qk[r] = valid ? phif(qa[r])*phif(ka[r]) : 0.0f;

    if (valid){
        float4* vp4 = (float4*)&vsT[e*20];
        vp4[0] = make_float4(va[0],va[1],va[2],va[3]);
        vp4[1] = make_float4(va[4],va[5],va[6],va[7]);
        vp4[2] = make_float4(va[8],va[9],va[10],va[11]);
        vp4[3] = make_float4(va[12],va[13],va[14],va[15]);
    }

    // reduce qk over threads (sum over e)
    #pragma unroll
    for (int off=16; off>0; off>>=1){
        #pragma unroll
        for (int r=0; r<16; r++) qk[r] += __shfl_down_sync(0xffffffffu, qk[r], off);
    }
    int w = tid >> 5, lane = tid & 31;
    if (lane == 0){
        #pragma unroll
        for (int r=0; r<16; r++) red1[w*16 + r] = qk[r];
    }
    __syncthreads();
    if (tid < 16){
        float s = red1[tid] + red1[16+tid] + red1[32+tid] + red1[48+tid];
        fac[tid] = s / fmaxf(s, 1e-6f);
    }
    __syncthreads();

    // phase 2: y_f = fac*(V@wo4 + V_f) + bo4[f], then LN over 120
    float ma[16];
    #pragma unroll
    for (int r=0; r<16; r++) ma[r] = 0.f;
    const float4* vp4c = (const float4*)vsT;
    #pragma unroll 2
    for (int ee=0; ee<HB; ee++){
        float wov = woT[ee*HB + e];
        float4 v0 = vp4c[ee*5+0], v1 = vp4c[ee*5+1], v2 = vp4c[ee*5+2], v3 = vp4c[ee*5+3];
        float vv[16];
        vv[0]=v0.x; vv[1]=v0.y; vv[2]=v0.z; vv[3]=v0.w;
        vv[4]=v1.x; vv[5]=v1.y; vv[6]=v1.z; vv[7]=v1.w;
        vv[8]=v2.x; vv[9]=v2.y; vv[10]=v2.z; vv[11]=v2.w;
        vv[12]=v3.x; vv[13]=v3.y; vv[14]=v3.z; vv[15]=v3.w;
        #pragma unroll
        for (int r=0; r<16; r++) ma[r] = fmaf(wov, vv[r], ma[r]);
    }
    float bov = bo4[e];
    float y[16], s1[16], s2[16];
    #pragma unroll
    for (int r=0; r<16; r++){
        y[r] = fmaf(fac[r], ma[r] + va[r], bov);
        s1[r] = valid ? y[r] : 0.f;
        s2[r] = valid ? y[r]*y[r] : 0.f;
    }
    #pragma unroll
    for (int off=16; off>0; off>>=1){
        #pragma unroll
        for (int r=0; r<16; r++){
            s1[r] += __shfl_down_sync(0xffffffffu, s1[r], off);
            s2[r] += __shfl_down_sync(0xffffffffu, s2[r], off);
        }
    }
    if (lane == 0){
        #pragma unroll
        for (int r=0; r<16; r++){ red1[w*16+r] = s1[r]; red2[w*16+r] = s2[r]; }
    }
    __syncthreads();
    if (tid < 16){
        float sy  = red1[tid]+red1[16+tid]+red1[32+tid]+red1[48+tid];
        float sy2 = red2[tid]+red2[16+tid]+red2[32+tid]+red2[48+tid];
        float mu = sy * (1.0f/120.0f);
        float var = sy2 * (1.0f/120.0f) - mu*mu;
        mus[tid] = mu;
        rss[tid] = rsqrtf(var + 1e-5f);
    }
    __syncthreads();
    if (valid){
        float lgv = lg4[e], lbv = lb4[e];
        #pragma unroll
        for (int r=0; r<16; r++){
            float yn = (y[r] - mus[r]) * rss[r];
            g_buf2[(size_t)(base + r)*HB + e] = yn*lgv + lbv;
        }
    }
}

// ---------------------------------------------------------------- CGLSTM (120 steps)
__global__ __launch_bounds__(256) void k_cglstm(
    const float* __restrict__ w_ih, const float* __restrict__ w_hh,
    const float* __restrict__ b_ih, const float* __restrict__ b_hh,
    const float* __restrict__ cg_w, const float* __restrict__ cg_uw,
    const float* __restrict__ cg_ub,
    float* __restrict__ outh)
{
    __shared__ float wifgs[96*36];   // i,f,g rows of w_hh, stride 36 (conflict-free)
    __shared__ float wcgs[32*36];    // cg_uw rows
    __shared__ float bifg[96], wihs[96], cgws[32], cgbs[32];
    __shared__ float hsm[32*36];
    __shared__ float xsm[32*HB];
    int tid = threadIdx.x;

    for (int i = tid; i < 96*32; i += 256) wifgs[(i>>5)*36 + (i&31)] = w_hh[i];
    for (int i = tid; i < 32*32; i += 256) wcgs[(i>>5)*36 + (i&31)] = cg_uw[i];
    if (tid < 96){ bifg[tid] = b_ih[tid] + b_hh[tid]; wihs[tid] = w_ih[tid]; }
    if (tid < 32){ cgws[tid] = cg_w[tid]; cgbs[tid] = cg_ub[tid]; }
    for (int i = tid; i < 32*36; i += 256) hsm[i] = 0.0f;
    int seqbase = blockIdx.x * 32;
    for (int i = tid; i < 32*HB; i += 256) xsm[i] = g_buf2[(size_t)seqbase*HB + i];
    __syncthreads();

    int seq = tid >> 3, lane8 = tid & 7;
    const float4* hp = (const float4*)&hsm[seq*36];
    float c[4] = {0.f, 0.f, 0.f, 0.f};
    float hn[4] = {0.f, 0.f, 0.f, 0.f};

    for (int t = 0; t < HB; t++){
        float hr[32];
        #pragma unroll
        for (int q=0; q<8; q++){
            float4 hv = hp[q];
            hr[4*q]=hv.x; hr[4*q+1]=hv.y; hr[4*q+2]=hv.z; hr[4*q+3]=hv.w;
        }
        float xv = xsm[seq*HB + t];
        #pragma unroll
        for (int m=0; m<4; m++){
            int j = lane8 + 8*m;
            float ai = fmaf(xv, wihs[j],    bifg[j]);
            float af = fmaf(xv, wihs[32+j], bifg[32+j]);
            float ag = fmaf(xv, wihs[64+j], bifg[64+j]);
            float ac = fmaf(xv, cgws[j],    cgbs[j]);
            const float4* wi = (const float4*)&wifgs[j*36];
            const float4* wf = (const float4*)&wifgs[(32+j)*36];
            const float4* wg = (const float4*)&wifgs[(64+j)*36];
            const float4* wc = (const float4*)&wcgs[j*36];
            #pragma unroll
            for (int q=0; q<8; q++){
                float4 a = wi[q], b = wf[q], g4 = wg[q], d4 = wc[q];
                ai = fmaf(a.x, hr[4*q],   ai); ai = fmaf(a.y, hr[4*q+1], ai);
                ai = fmaf(a.z, hr[4*q+2], ai); ai = fmaf(a.w, hr[4*q+3], ai);
                af = fmaf(b.x, hr[4*q],   af); af = fmaf(b.y, hr[4*q+1], af);
                af = fmaf(b.z, hr[4*q+2], af); af = fmaf(b.w, hr[4*q+3], af);
                ag = fmaf(g4.x, hr[4*q],   ag); ag = fmaf(g4.y, hr[4*q+1], ag);
                ag = fmaf(g4.z, hr[4*q+2], ag); ag = fmaf(g4.w, hr[4*q+3], ag);
                ac = fmaf(d4.x, hr[4*q],   ac); ac = fmaf(d4.y, hr[4*q+1], ac);
                ac = fmaf(d4.z, hr[4*q+2], ac); ac = fmaf(d4.w, hr[4*q+3], ac);
            }
            float cn = sigf(af)*c[m] + sigf(ai)*tanhe(ag);
            c[m] = cn;
            hn[m] = sigf(ac)*tanhe(cn);
        }
        #pragma unroll
        for (int m=0; m<4; m++) hsm[seq*36 + lane8 + 8*m] = hn[m];
        __syncwarp();
    }

    int n = seqbase + seq;
    #pragma unroll
    for (int m=0; m<4; m++) outh[(size_t)n*32 + lane8 + 8*m] = hn[m];
}

// ---------------------------------------------------------------- conv6/7 + permute + RevIN
__global__ __launch_bounds__(160) void k_head(
    const float* __restrict__ w6, const float* __restrict__ b6,
    const float* __restrict__ w7, const float* __restrict__ b7,
    const float* __restrict__ rev_w, const float* __restrict__ rev_b,
    const float* __restrict__ hin, float* __restrict__ enc)
{
    __shared__ float hs[288], w6s[60*32], w7s[15*60], b6s[60], b7s[15];
    __shared__ float t60s[9*60], t135[135];
    __shared__ float smu, sinv;
    __shared__ float part1[5], part2[5];
    int b = blockIdx.x, tid = threadIdx.x;

    for (int i = tid; i < 60*32; i += 160) w6s[i] = w6[i];
    for (int i = tid; i < 15*60; i += 160) w7s[i] = w7[i];
    if (tid < 60) b6s[tid] = b6[tid];
    if (tid < 15) b7s[tid] = b7[tid];
    for (int i = tid; i < 288; i += 160) hs[i] = hin[(size_t)b*288 + i];
    __syncthreads();

    for (int i = tid; i < 540; i += 160){
        int dd = i/60, u = i - dd*60;
        float acc = b6s[u];
        #pragma unroll 8
        for (int k=0; k<32; k++) acc = fmaf(w6s[u*32+k], hs[dd*32+k], acc);
        // stable softplus
        t60s[i] = fmaxf(acc, 0.0f) + log1pf(__expf(-fabsf(acc)));
    }
    __syncthreads();
    if (tid < 135){
        int dd = tid/15, f = tid - dd*15;
        float acc = b7s[f];
        #pragma unroll 6
        for (int u=0; u<60; u++) acc = fmaf(w7s[f*60+u], t60s[dd*60+u], acc);
        t135[tid] = tanhf(acc);
    }
    __syncthreads();
    float v  = (tid < 135) ? t135[tid] : 0.0f;
    float v2 = v*v;
    #pragma unroll
    for (int off=16; off>0; off>>=1){
        v  += __shfl_down_sync(0xffffffffu, v,  off);
        v2 += __shfl_down_sync(0xffffffffu, v2, off);
    }
    if ((tid & 31) == 0){ part1[tid>>5] = v; part2[tid>>5] = v2; }
    __syncthreads();
    if (tid == 0){
        float s1 = 0.f, s2 = 0.f;
        #pragma unroll
        for (int w=0; w<5; w++){ s1 += part1[w]; s2 += part2[w]; }
        float mu = s1 * (1.0f/135.0f);
        float var = fmaxf((s2 - 135.0f*mu*mu) * (1.0f/134.0f), 0.0f);
        float sd = fmaxf(sqrtf(var), 1e-5f);
        smu = mu; sinv = 1.0f/sd;
    }
    __syncthreads();
    if (tid < 135){
        int dp = tid/15, fp = tid - dp*15;
        float yv = t135[fp*9 + dp];       // transpose_8
        enc[(size_t)b*135 + tid] = (yv - smu)*sinv*rev_w[tid] + rev_b[tid];
    }
}

// ---------------------------------------------------------------- launch
extern "C" void kernel_launch(void* const* d_in, const int* in_sizes, int n_in,
                              void* d_out, int out_size)
{
    const float* x     = (const float*)d_in[0];
    const float* bn_g  = (const float*)d_in[1];
    const float* bn_b  = (const float*)d_in[2];
    const float* bn_m  = (const float*)d_in[3];
    const float* bn_v  = (const float*)d_in[4];
    const float* wq2   = (const float*)d_in[5];
    const float* wk2   = (const float*)d_in[6];
    const float* wv2   = (const float*)d_in[7];
    const float* wo2   = (const float*)d_in[8];
    const float* bo2   = (const float*)d_in[9];
    const float* ln2g  = (const float*)d_in[10];
    const float* ln2b  = (const float*)d_in[11];
    const float* wq4   = (const float*)d_in[12];
    const float* wk4   = (const float*)d_in[13];
    const float* wv4   = (const float*)d_in[14];
    const float* wo4   = (const float*)d_in[15];
    const float* bo4   = (const float*)d_in[16];
    const float* ln4g  = (const float*)d_in[17];
    const float* ln4b  = (const float*)d_in[18];
    const float* w_ih  = (const float*)d_in[19];
    const float* w_hh  = (const float*)d_in[20];
    const float* b_ih  = (const float*)d_in[21];
    const float* b_hh  = (const float*)d_in[22];
    const float* cg_w  = (const float*)d_in[23];
    const float* cg_uw = (const float*)d_in[24];
    const float* cg_ub = (const float*)d_in[25];
    const float* w6    = (const float*)d_in[26];
    const float* b6    = (const float*)d_in[27];
    const float* w7    = (const float*)d_in[28];
    const float* b7    = (const float*)d_in[29];
    const float* rev_w = (const float*)d_in[30];
    const float* rev_b = (const float*)d_in[31];
    float* out = (float*)d_out;

    k_transpose_w<<<(4*HB*HB + 255)/256, 256>>>(wq4, wk4, wv4, wo4);
    k_attn2<<<BATCH, 128>>>(x, bn_g, bn_b, bn_m, bn_v, wq2, wk2, wv2, wo2, bo2, ln2g, ln2b);
    k_attn4<<<NSEQ/16, 128>>>(bo4, ln4g, ln4b);
    k_cglstm<<<NSEQ/32, 256>>>(w_ih, w_hh, b_ih, b_hh, cg_w, cg_uw, cg_ub, out);
    k_head<<<BATCH, 160>>>(w6, b6, w7, b7, rev_w, rev_b, out, out + (size_t)BATCH*288);
}

// round 2
// speedup vs baseline: 1.1011x; 1.1011x over previous
#include <cuda_runtime.h>

#define BATCH 16384
#define HB 120
#define BD 9
#define NSEQ (BATCH*BD)   /* 147456 */
#define NS 32
#define NF 15

// scratch (no cudaMalloc allowed)
__device__ float g_buf1[NSEQ*HB];      // attn2 output, transposed: [(b*9+d)*120 + s]
__device__ float g_buf2[NSEQ*HB];      // attn4 output: [n*120 + t]
__device__ float g_wT[4*HB*HB];        // transposed wq4,wk4,wv4,wo4

__device__ __forceinline__ float sigf(float x){ return 1.0f/(1.0f+__expf(-x)); }
__device__ __forceinline__ float tanhe(float x){ return 1.0f - 2.0f/(__expf(2.0f*x)+1.0f); }
__device__ __forceinline__ float phif(float x){ return x>0.0f ? x+1.0f : __expf(x); }

// ---------------------------------------------------------------- weights transpose
__global__ void k_transpose_w(const float* __restrict__ wq, const float* __restrict__ wk,
                              const float* __restrict__ wv, const float* __restrict__ wo){
    int idx = blockIdx.x*blockDim.x + threadIdx.x;
    if (idx >= 4*HB*HB) return;
    int m = idx/(HB*HB); int i = idx - m*(HB*HB);
    int a = i/HB, b = i - a*HB;
    const float* src = (m==0)?wq : (m==1)?wk : (m==2)?wv : wo;
    g_wT[idx] = src[b*HB + a];
}

// ---------------------------------------------------------------- BN + lin_attn_2 + transpose
__global__ __launch_bounds__(128) void k_attn2(
    const float* __restrict__ x,
    const float* __restrict__ bng, const float* __restrict__ bnb,
    const float* __restrict__ bnm, const float* __restrict__ bnv,
    const float* __restrict__ wq, const float* __restrict__ wk,
    const float* __restrict__ wv, const float* __restrict__ wo,
    const float* __restrict__ bo, const float* __restrict__ lg,
    const float* __restrict__ lb)
{
    __shared__ float xs[HB*13], qs[HB*13], ks[HB*13], vs[HB*13];
    __shared__ float wqs[81], wks[81], wvs[81], wos[81];
    __shared__ float kvs[81], ksum[9], bos[9], lgs[9], lbs[9];
    int b = blockIdx.x, tid = threadIdx.x;

    for (int i = tid; i < 1080; i += 128){
        float val = (x[(size_t)b*1080 + i] - bnm[i]) * rsqrtf(bnv[i] + 1e-5f) * bng[i] + bnb[i];
        xs[(i/9)*13 + (i%9)] = val;
    }
    if (tid < 81){ wqs[tid]=wq[tid]; wks[tid]=wk[tid]; wvs[tid]=wv[tid]; wos[tid]=wo[tid]; }
    if (tid < 9){ bos[tid]=bo[tid]; lgs[tid]=lg[tid]; lbs[tid]=lb[tid]; }
    __syncthreads();

    if (tid < HB){
        float xr[9];
        #pragma unroll
        for (int d=0; d<9; d++) xr[d] = xs[tid*13+d];
        #pragma unroll
        for (int e=0; e<9; e++){
            float aq=0.f, ak=0.f, av=0.f;
            #pragma unroll
            for (int d=0; d<9; d++){
                aq = fmaf(xr[d], wqs[e*9+d], aq);
                ak = fmaf(xr[d], wks[e*9+d], ak);
                av = fmaf(xr[d], wvs[e*9+d], av);
            }
            qs[tid*13+e] = phif(aq);
            ks[tid*13+e] = phif(ak);
            vs[tid*13+e] = av;
        }
    }
    __syncthreads();

    if (tid < 81){
        int d = tid/9, e = tid%9;
        float acc = 0.f;
        for (int s=0; s<HB; s++) acc = fmaf(ks[s*13+d], vs[s*13+e], acc);
        kvs[tid] = acc;
    } else if (tid < 90){
        int e = tid - 81;
        float acc = 0.f;
        for (int s=0; s<HB; s++) acc += ks[s*13+e];
        ksum[e] = acc;
    }
    __syncthreads();

    if (tid < HB){
        float q[9], o[9];
        float den = 0.f;
        #pragma unroll
        for (int e=0; e<9; e++){ q[e] = qs[tid*13+e]; den = fmaf(q[e], ksum[e], den); }
        float inv = 1.0f / fmaxf(den, 1e-6f);
        #pragma unroll
        for (int e=0; e<9; e++){
            float num = 0.f;
            #pragma unroll
            for (int d=0; d<9; d++) num = fmaf(q[d], kvs[d*9+e], num);
            o[e] = num * inv;
        }
        float y[9]; float mu = 0.f;
        #pragma unroll
        for (int f=0; f<9; f++){
            float acc = bos[f] + o[f];
            #pragma unroll
            for (int e=0; e<9; e++) acc = fmaf(o[e], wos[f*9+e], acc);
            y[f] = acc; mu += acc;
        }
        mu *= (1.0f/9.0f);
        float var = 0.f;
        #pragma unroll
        for (int f=0; f<9; f++){ float dd = y[f]-mu; var = fmaf(dd, dd, var); }
        var *= (1.0f/9.0f);
        float rs = rsqrtf(var + 1e-5f);
        #pragma unroll
        for (int f=0; f<9; f++){
            g_buf1[(size_t)b*1080 + f*HB + tid] = (y[f]-mu)*rs*lgs[f] + lbs[f];
        }
    }
}

// ---------------------------------------------------------------- lin_attn_4 (S=1 collapsed)
__global__ __launch_bounds__(128) void k_attn4(
    const float* __restrict__ bo4, const float* __restrict__ lg4,
    const float* __restrict__ lb4)
{
    __shared__ float xsT[HB*20];
    __shared__ float vsT[HB*20];
    __shared__ float red1[4*16], red2[4*16];
    __shared__ float fac[16], mus[16], rss[16];
    int tid = threadIdx.x;
    int base = blockIdx.x * 16;

    for (int i = tid; i < 16*HB; i += 128){
        int r = i / HB, d = i - r*HB;
        xsT[d*20 + r] = g_buf1[(size_t)(base + r)*HB + d];
    }
    __syncthreads();

    bool valid = tid < HB;
    int e = valid ? tid : 0;
    const float* wqT = g_wT;
    const float* wkT = g_wT + HB*HB;
    const float* wvT = g_wT + 2*HB*HB;
    const float* woT = g_wT + 3*HB*HB;

    float qa[16], ka[16], va[16];
    #pragma unroll
    for (int r=0; r<16; r++){ qa[r]=0.f; ka[r]=0.f; va[r]=0.f; }

    const float4* xp4 = (const float4*)xsT;
    #pragma unroll 2
    for (int d=0; d<HB; d++){
        float wqv = wqT[d*HB + e];
        float wkv = wkT[d*HB + e];
        float wvv = wvT[d*HB + e];
        float4 x0 = xp4[d*5+0], x1 = xp4[d*5+1], x2 = xp4[d*5+2], x3 = xp4[d*5+3];
        float xv[16];
        xv[0]=x0.x; xv[1]=x0.y; xv[2]=x0.z; xv[3]=x0.w;
        xv[4]=x1.x; xv[5]=x1.y; xv[6]=x1.z; xv[7]=x1.w;
        xv[8]=x2.x; xv[9]=x2.y; xv[10]=x2.z; xv[11]=x2.w;
        xv[12]=x3.x; xv[13]=x3.y; xv[14]=x3.z; xv[15]=x3.w;
        #pragma unroll
        for (int r=0; r<16; r++){
            qa[r] = fmaf(wqv, xv[r], qa[r]);
            ka[r] = fmaf(wkv, xv[r], ka[r]);
            va[r] = fmaf(wvv, xv[r], va[r]);
        }
    }

    float qk[16];
    #pragma unroll
    for (int r=0; r<16; r++) qk[r] = valid ? phif(qa[r])*phif(ka[r]) : 0.0f;

    if (valid){
        float4* vp4 = (float4*)&vsT[e*20];
        vp4[0] = make_float4(va[0],va[1],va[2],va[3]);
        vp4[1] = make_float4(va[4],va[5],va[6],va[7]);
        vp4[2] = make_float4(va[8],va[9],va[10],va[11]);
        vp4[3] = make_float4(va[12],va[13],va[14],va[15]);
    }

    // reduce qk over threads (sum over e)
    #pragma unroll
    for (int off=16; off>0; off>>=1){
        #pragma unroll
        for (int r=0; r<16; r++) qk[r] += __shfl_down_sync(0xffffffffu, qk[r], off);
    }
    int w = tid >> 5, lane = tid & 31;
    if (lane == 0){
        #pragma unroll
        for (int r=0; r<16; r++) red1[w*16 + r] = qk[r];
    }
    __syncthreads();
    if (tid < 16){
        float s = red1[tid] + red1[16+tid] + red1[32+tid] + red1[48+tid];
        fac[tid] = s / fmaxf(s, 1e-6f);
    }
    __syncthreads();

    // phase 2: y_f = fac*(V@wo4 + V_f) + bo4[f], then LN over 120
    float ma[16];
    #pragma unroll
    for (int r=0; r<16; r++) ma[r] = 0.f;
    const float4* vp4c = (const float4*)vsT;
    #pragma unroll 2
    for (int ee=0; ee<HB; ee++){
        float wov = woT[ee*HB + e];
        float4 v0 = vp4c[ee*5+0], v1 = vp4c[ee*5+1], v2 = vp4c[ee*5+2], v3 = vp4c[ee*5+3];
        float vv[16];
        vv[0]=v0.x; vv[1]=v0.y; vv[2]=v0.z; vv[3]=v0.w;
        vv[4]=v1.x; vv[5]=v1.y; vv[6]=v1.z; vv[7]=v1.w;
        vv[8]=v2.x; vv[9]=v2.y; vv[10]=v2.z; vv[11]=v2.w;
        vv[12]=v3.x; vv[13]=v3.y; vv[14]=v3.z; vv[15]=v3.w;
        #pragma unroll
        for (int r=0; r<16; r++) ma[r] = fmaf(wov, vv[r], ma[r]);
    }
    float bov = bo4[e];
    float y[16], s1[16], s2[16];
    #pragma unroll
    for (int r=0; r<16; r++){
        y[r] = fmaf(fac[r], ma[r] + va[r], bov);
        s1[r] = valid ? y[r] : 0.f;
        s2[r] = valid ? y[r]*y[r] : 0.f;
    }
    #pragma unroll
    for (int off=16; off>0; off>>=1){
        #pragma unroll
        for (int r=0; r<16; r++){
            s1[r] += __shfl_down_sync(0xffffffffu, s1[r], off);
            s2[r] += __shfl_down_sync(0xffffffffu, s2[r], off);
        }
    }
    if (lane == 0){
        #pragma unroll
        for (int r=0; r<16; r++){ red1[w*16+r] = s1[r]; red2[w*16+r] = s2[r]; }
    }
    __syncthreads();
    if (tid < 16){
        float sy  = red1[tid]+red1[16+tid]+red1[32+tid]+red1[48+tid];
        float sy2 = red2[tid]+red2[16+tid]+red2[32+tid]+red2[48+tid];
        float mu = sy * (1.0f/120.0f);
        float var = sy2 * (1.0f/120.0f) - mu*mu;
        mus[tid] = mu;
        rss[tid] = rsqrtf(var + 1e-5f);
    }
    __syncthreads();
    if (valid){
        float lgv = lg4[e], lbv = lb4[e];
        #pragma unroll
        for (int r=0; r<16; r++){
            float yn = (y[r] - mus[r]) * rss[r];
            g_buf2[(size_t)(base + r)*HB + e] = yn*lgv + lbv;
        }
    }
}

// ---------------------------------------------------------------- CGLSTM (120 steps)
// One warp per sequence; thread j owns hidden unit j with all its weight rows
// register-resident. Per-step SMEM traffic: 1 STS.32 + 8 broadcast LDS.128.
__global__ __launch_bounds__(256, 1) void k_cglstm(
    const float* __restrict__ w_ih, const float* __restrict__ w_hh,
    const float* __restrict__ b_ih, const float* __restrict__ b_hh,
    const float* __restrict__ cg_w, const float* __restrict__ cg_uw,
    const float* __restrict__ cg_ub,
    float* __restrict__ outh)
{
    __shared__ float wsm[96*33];     // i,f,g rows of w_hh (stride 33: conflict-free row reads)
    __shared__ float cgsm[32*33];    // cg_uw rows
    __shared__ float xsm[8*HB];
    __shared__ float hbuf[2][8][32]; // double-buffered h per warp
    int tid = threadIdx.x, warp = tid >> 5, lane = tid & 31;

    for (int i = tid; i < 96*32; i += 256) wsm[(i>>5)*33 + (i&31)] = w_hh[i];
    for (int i = tid; i < 32*32; i += 256) cgsm[(i>>5)*33 + (i&31)] = cg_uw[i];
    for (int i = tid; i < 8*HB; i += 256) xsm[i] = g_buf2[(size_t)blockIdx.x*8*HB + i];
    hbuf[0][warp][lane] = 0.0f;
    __syncthreads();

    // register-resident weight rows for hidden unit `lane`
    float wi[32], wf[32], wg[32], wc[32];
    #pragma unroll
    for (int k = 0; k < 32; k++){
        wi[k] = wsm[lane*33 + k];
        wf[k] = wsm[(32+lane)*33 + k];
        wg[k] = wsm[(64+lane)*33 + k];
        wc[k] = cgsm[lane*33 + k];
    }
    float wx_i = w_ih[lane], wx_f = w_ih[32+lane], wx_g = w_ih[64+lane];
    float bi = b_ih[lane] + b_hh[lane];
    float bf = b_ih[32+lane] + b_hh[32+lane];
    float bg = b_ih[64+lane] + b_hh[64+lane];
    float wx_c = cg_w[lane], bc = cg_ub[lane];

    float c = 0.0f, hn = 0.0f;
    int p = 0;
    const float* xrow = &xsm[warp*HB];

    for (int t = 0; t < HB; t++){
        const float4* hp = (const float4*)&hbuf[p][warp][0];
        float4 h4[8];
        #pragma unroll
        for (int q = 0; q < 8; q++) h4[q] = hp[q];

        float xv = xrow[t];
        float ai = fmaf(xv, wx_i, bi);
        float af = fmaf(xv, wx_f, bf);
        float ag = fmaf(xv, wx_g, bg);
        float ac = fmaf(xv, wx_c, bc);

        #pragma unroll
        for (int q = 0; q < 8; q++){
            float4 h = h4[q];
            ai = fmaf(wi[4*q],   h.x, ai); ai = fmaf(wi[4*q+1], h.y, ai);
            ai = fmaf(wi[4*q+2], h.z, ai); ai = fmaf(wi[4*q+3], h.w, ai);
            af = fmaf(wf[4*q],   h.x, af); af = fmaf(wf[4*q+1], h.y, af);
            af = fmaf(wf[4*q+2], h.z, af); af = fmaf(wf[4*q+3], h.w, af);
            ag = fmaf(wg[4*q],   h.x, ag); ag = fmaf(wg[4*q+1], h.y, ag);
            ag = fmaf(wg[4*q+2], h.z, ag); ag = fmaf(wg[4*q+3], h.w, ag);
            ac = fmaf(wc[4*q],   h.x, ac); ac = fmaf(wc[4*q+1], h.y, ac);
            ac = fmaf(wc[4*q+2], h.z, ac); ac = fmaf(wc[4*q+3], h.w, ac);
        }

        c = sigf(af)*c + sigf(ai)*tanhe(ag);
        hn = sigf(ac)*tanhe(c);

        hbuf[1-p][warp][lane] = hn;
        __syncwarp();
        p ^= 1;
    }

    int n = blockIdx.x*8 + warp;
    outh[(size_t)n*32 + lane] = hn;
}

// ---------------------------------------------------------------- conv6/7 + permute + RevIN
__global__ __launch_bounds__(160) void k_head(
    const float* __restrict__ w6, const float* __restrict__ b6,
    const float* __restrict__ w7, const float* __restrict__ b7,
    const float* __restrict__ rev_w, const float* __restrict__ rev_b,
    const float* __restrict__ hin, float* __restrict__ enc)
{
    __shared__ float hs[288], w6s[60*32], w7s[15*60], b6s[60], b7s[15];
    __shared__ float t60s[9*60], t135[135];
    __shared__ float smu, sinv;
    __shared__ float part1[5], part2[5];
    int b = blockIdx.x, tid = threadIdx.x;

    for (int i = tid; i < 60*32; i += 160) w6s[i] = w6[i];
    for (int i = tid; i < 15*60; i += 160) w7s[i] = w7[i];
    if (tid < 60) b6s[tid] = b6[tid];
    if (tid < 15) b7s[tid] = b7[tid];
    for (int i = tid; i < 288; i += 160) hs[i] = hin[(size_t)b*288 + i];
    __syncthreads();

    for (int i = tid; i < 540; i += 160){
        int dd = i/60, u = i - dd*60;
        float acc = b6s[u];
        #pragma unroll 8
        for (int k=0; k<32; k++) acc = fmaf(w6s[u*32+k], hs[dd*32+k], acc);
        t60s[i] = fmaxf(acc, 0.0f) + log1pf(__expf(-fabsf(acc)));
    }
    __syncthreads();
    if (tid < 135){
        int dd = tid/15, f = tid - dd*15;
        float acc = b7s[f];
        #pragma unroll 6
        for (int u=0; u<60; u++) acc = fmaf(w7s[f*60+u], t60s[dd*60+u], acc);
        t135[tid] = tanhf(acc);
    }
    __syncthreads();
    float v  = (tid < 135) ? t135[tid] : 0.0f;
    float v2 = v*v;
    #pragma unroll
    for (int off=16; off>0; off>>=1){
        v  += __shfl_down_sync(0xffffffffu, v,  off);
        v2 += __shfl_down_sync(0xffffffffu, v2, off);
    }
    if ((tid & 31) == 0){ part1[tid>>5] = v; part2[tid>>5] = v2; }
    __syncthreads();
    if (tid == 0){
        float s1 = 0.f, s2 = 0.f;
        #pragma unroll
        for (int w=0; w<5; w++){ s1 += part1[w]; s2 += part2[w]; }
        float mu = s1 * (1.0f/135.0f);
        float var = fmaxf((s2 - 135.0f*mu*mu) * (1.0f/134.0f), 0.0f);
        float sd = fmaxf(sqrtf(var), 1e-5f);
        smu = mu; sinv = 1.0f/sd;
    }
    __syncthreads();
    if (tid < 135){
        int dp = tid/15, fp = tid - dp*15;
        float yv = t135[fp*9 + dp];       // transpose_8
        enc[(size_t)b*135 + tid] = (yv - smu)*sinv*rev_w[tid] + rev_b[tid];
    }
}

// ---------------------------------------------------------------- launch
extern "C" void kernel_launch(void* const* d_in, const int* in_sizes, int n_in,
                              void* d_out, int out_size)
{
    const float* x     = (const float*)d_in[0];
    const float* bn_g  = (const float*)d_in[1];
    const float* bn_b  = (const float*)d_in[2];
    const float* bn_m  = (const float*)d_in[3];
    const float* bn_v  = (const float*)d_in[4];
    const float* wq2   = (const float*)d_in[5];
    const float* wk2   = (const float*)d_in[6];
    const float* wv2   = (const float*)d_in[7];
    const float* wo2   = (const float*)d_in[8];
    const float* bo2   = (const float*)d_in[9];
    const float* ln2g  = (const float*)d_in[10];
    const float* ln2b  = (const float*)d_in[11];
    const float* wq4   = (const float*)d_in[12];
    const float* wk4   = (const float*)d_in[13];
    const float* wv4   = (const float*)d_in[14];
    const float* wo4   = (const float*)d_in[15];
    const float* bo4   = (const float*)d_in[16];
    const float* ln4g  = (const float*)d_in[17];
    const float* ln4b  = (const float*)d_in[18];
    const float* w_ih  = (const float*)d_in[19];
    const float* w_hh  = (const float*)d_in[20];
    const float* b_ih  = (const float*)d_in[21];
    const float* b_hh  = (const float*)d_in[22];
    const float* cg_w  = (const float*)d_in[23];
    const float* cg_uw = (const float*)d_in[24];
    const float* cg_ub = (const float*)d_in[25];
    const float* w6    = (const float*)d_in[26];
    const float* b6    = (const float*)d_in[27];
    const float* w7    = (const float*)d_in[28];
    const float* b7    = (const float*)d_in[29];
    const float* rev_w = (const float*)d_in[30];
    const float* rev_b = (const float*)d_in[31];
    float* out = (float*)d_out;

    k_transpose_w<<<(4*HB*HB + 255)/256, 256>>>(wq4, wk4, wv4, wo4);
    k_attn2<<<BATCH, 128>>>(x, bn_g, bn_b, bn_m, bn_v, wq2, wk2, wv2, wo2, bo2, ln2g, ln2b);
    k_attn4<<<NSEQ/16, 128>>>(bo4, ln4g, ln4b);
    k_cglstm<<<NSEQ/8, 256>>>(w_ih, w_hh, b_ih, b_hh, cg_w, cg_uw, cg_ub, out);
    k_head<<<BATCH, 160>>>(w6, b6, w7, b7, rev_w, rev_b, out, out + (size_t)BATCH*288);
}

// round 3
// speedup vs baseline: 1.1752x; 1.0673x over previous
#include <cuda_runtime.h>

#define BATCH 16384
#define HB 120
#define BD 9
#define NSEQ (BATCH*BD)   /* 147456 */
#define NS 32
#define NF 15

// scratch (no cudaMalloc allowed)
__device__ float g_buf1[NSEQ*HB];      // attn2 output, transposed: [(b*9+d)*120 + s]
__device__ float g_buf2[NSEQ*HB];      // attn4 output: [n*120 + t]
__device__ float g_wT[4*HB*HB];        // transposed wq4,wk4,wv4,wo4

__device__ __forceinline__ float sigf(float x){ return 1.0f/(1.0f+__expf(-x)); }
__device__ __forceinline__ float tanhe(float x){ return 1.0f - 2.0f/(__expf(2.0f*x)+1.0f); }
__device__ __forceinline__ float phif(float x){ return x>0.0f ? x+1.0f : __expf(x); }

typedef unsigned long long ull;
__device__ __forceinline__ ull pack2(float lo, float hi){
    ull r; asm("mov.b64 %0, {%1, %2};" : "=l"(r) : "f"(lo), "f"(hi)); return r;
}
__device__ __forceinline__ float2 unpack2(ull v){
    float2 f; asm("mov.b64 {%0, %1}, %2;" : "=f"(f.x), "=f"(f.y) : "l"(v)); return f;
}
__device__ __forceinline__ void ffma2(ull &d, ull a, ull b){
    asm("fma.rn.f32x2 %0, %1, %2, %0;" : "+l"(d) : "l"(a), "l"(b));
}

// ---------------------------------------------------------------- weights transpose
__global__ void k_transpose_w(const float* __restrict__ wq, const float* __restrict__ wk,
                              const float* __restrict__ wv, const float* __restrict__ wo){
    int idx = blockIdx.x*blockDim.x + threadIdx.x;
    if (idx >= 4*HB*HB) return;
    int m = idx/(HB*HB); int i = idx - m*(HB*HB);
    int a = i/HB, b = i - a*HB;
    const float* src = (m==0)?wq : (m==1)?wk : (m==2)?wv : wo;
    g_wT[idx] = src[b*HB + a];
}

// ---------------------------------------------------------------- BN + lin_attn_2 + transpose
__global__ __launch_bounds__(128) void k_attn2(
    const float* __restrict__ x,
    const float* __restrict__ bng, const float* __restrict__ bnb,
    const float* __restrict__ bnm, const float* __restrict__ bnv,
    const float* __restrict__ wq, const float* __restrict__ wk,
    const float* __restrict__ wv, const float* __restrict__ wo,
    const float* __restrict__ bo, const float* __restrict__ lg,
    const float* __restrict__ lb)
{
    __shared__ float xs[HB*13], qs[HB*13], ks[HB*13], vs[HB*13];
    __shared__ float wqs[81], wks[81], wvs[81], wos[81];
    __shared__ float kvs[81], ksum[9], bos[9], lgs[9], lbs[9];
    int b = blockIdx.x, tid = threadIdx.x;

    for (int i = tid; i < 1080; i += 128){
        float val = (x[(size_t)b*1080 + i] - bnm[i]) * rsqrtf(bnv[i] + 1e-5f) * bng[i] + bnb[i];
        xs[(i/9)*13 + (i%9)] = val;
    }
    if (tid < 81){ wqs[tid]=wq[tid]; wks[tid]=wk[tid]; wvs[tid]=wv[tid]; wos[tid]=wo[tid]; }
    if (tid < 9){ bos[tid]=bo[tid]; lgs[tid]=lg[tid]; lbs[tid]=lb[tid]; }
    __syncthreads();

    if (tid < HB){
        float xr[9];
        #pragma unroll
        for (int d=0; d<9; d++) xr[d] = xs[tid*13+d];
        #pragma unroll
        for (int e=0; e<9; e++){
            float aq=0.f, ak=0.f, av=0.f;
            #pragma unroll
            for (int d=0; d<9; d++){
                aq = fmaf(xr[d], wqs[e*9+d], aq);
                ak = fmaf(xr[d], wks[e*9+d], ak);
                av = fmaf(xr[d], wvs[e*9+d], av);
            }
            qs[tid*13+e] = phif(aq);
            ks[tid*13+e] = phif(ak);
            vs[tid*13+e] = av;
        }
    }
    __syncthreads();

    if (tid < 81){
        int d = tid/9, e = tid%9;
        float acc = 0.f;
        for (int s=0; s<HB; s++) acc = fmaf(ks[s*13+d], vs[s*13+e], acc);
        kvs[tid] = acc;
    } else if (tid < 90){
        int e = tid - 81;
        float acc = 0.f;
        for (int s=0; s<HB; s++) acc += ks[s*13+e];
        ksum[e] = acc;
    }
    __syncthreads();

    if (tid < HB){
        float q[9], o[9];
        float den = 0.f;
        #pragma unroll
        for (int e=0; e<9; e++){ q[e] = qs[tid*13+e]; den = fmaf(q[e], ksum[e], den); }
        float inv = 1.0f / fmaxf(den, 1e-6f);
        #pragma unroll
        for (int e=0; e<9; e++){
            float num = 0.f;
            #pragma unroll
            for (int d=0; d<9; d++) num = fmaf(q[d], kvs[d*9+e], num);
            o[e] = num * inv;
        }
        float y[9]; float mu = 0.f;
        #pragma unroll
        for (int f=0; f<9; f++){
            float acc = bos[f] + o[f];
            #pragma unroll
            for (int e=0; e<9; e++) acc = fmaf(o[e], wos[f*9+e], acc);
            y[f] = acc; mu += acc;
        }
        mu *= (1.0f/9.0f);
        float var = 0.f;
        #pragma unroll
        for (int f=0; f<9; f++){ float dd = y[f]-mu; var = fmaf(dd, dd, var); }
        var *= (1.0f/9.0f);
        float rs = rsqrtf(var + 1e-5f);
        #pragma unroll
        for (int f=0; f<9; f++){
            g_buf1[(size_t)b*1080 + f*HB + tid] = (y[f]-mu)*rs*lgs[f] + lbs[f];
        }
    }
}

// ---------------------------------------------------------------- lin_attn_4 (S=1 collapsed)
__global__ __launch_bounds__(128) void k_attn4(
    const float* __restrict__ bo4, const float* __restrict__ lg4,
    const float* __restrict__ lb4)
{
    __shared__ float xsT[HB*20];
    __shared__ float vsT[HB*20];
    __shared__ float red1[4*16], red2[4*16];
    __shared__ float fac[16], mus[16], rss[16];
    int tid = threadIdx.x;
    int base = blockIdx.x * 16;

    for (int i = tid; i < 16*HB; i += 128){
        int r = i / HB, d = i - r*HB;
        xsT[d*20 + r] = g_buf1[(size_t)(base + r)*HB + d];
    }
    __syncthreads();

    bool valid = tid < HB;
    int e = valid ? tid : 0;
    const float* wqT = g_wT;
    const float* wkT = g_wT + HB*HB;
    const float* wvT = g_wT + 2*HB*HB;
    const float* woT = g_wT + 3*HB*HB;

    float qa[16], ka[16], va[16];
    #pragma unroll
    for (int r=0; r<16; r++){ qa[r]=0.f; ka[r]=0.f; va[r]=0.f; }

    const float4* xp4 = (const float4*)xsT;
    #pragma unroll 2
    for (int d=0; d<HB; d++){
        float wqv = wqT[d*HB + e];
        float wkv = wkT[d*HB + e];
        float wvv = wvT[d*HB + e];
        float4 x0 = xp4[d*5+0], x1 = xp4[d*5+1], x2 = xp4[d*5+2], x3 = xp4[d*5+3];
        float xv[16];
        xv[0]=x0.x; xv[1]=x0.y; xv[2]=x0.z; xv[3]=x0.w;
        xv[4]=x1.x; xv[5]=x1.y; xv[6]=x1.z; xv[7]=x1.w;
        xv[8]=x2.x; xv[9]=x2.y; xv[10]=x2.z; xv[11]=x2.w;
        xv[12]=x3.x; xv[13]=x3.y; xv[14]=x3.z; xv[15]=x3.w;
        #pragma unroll
        for (int r=0; r<16; r++){
            qa[r] = fmaf(wqv, xv[r], qa[r]);
            ka[r] = fmaf(wkv, xv[r], ka[r]);
            va[r] = fmaf(wvv, xv[r], va[r]);
        }
    }

    float qk[16];
    #pragma unroll
    for (int r=0; r<16; r++) qk[r] = valid ? phif(qa[r])*phif(ka[r]) : 0.0f;

    if (valid){
        float4* vp4 = (float4*)&vsT[e*20];
        vp4[0] = make_float4(va[0],va[1],va[2],va[3]);
        vp4[1] = make_float4(va[4],va[5],va[6],va[7]);
        vp4[2] = make_float4(va[8],va[9],va[10],va[11]);
        vp4[3] = make_float4(va[12],va[13],va[14],va[15]);
    }

    #pragma unroll
    for (int off=16; off>0; off>>=1){
        #pragma unroll
        for (int r=0; r<16; r++) qk[r] += __shfl_down_sync(0xffffffffu, qk[r], off);
    }
    int w = tid >> 5, lane = tid & 31;
    if (lane == 0){
        #pragma unroll
        for (int r=0; r<16; r++) red1[w*16 + r] = qk[r];
    }
    __syncthreads();
    if (tid < 16){
        float s = red1[tid] + red1[16+tid] + red1[32+tid] + red1[48+tid];
        fac[tid] = s / fmaxf(s, 1e-6f);
    }
    __syncthreads();

    float ma[16];
    #pragma unroll
    for (int r=0; r<16; r++) ma[r] = 0.f;
    const float4* vp4c = (const float4*)vsT;
    #pragma unroll 2
    for (int ee=0; ee<HB; ee++){
        float wov = woT[ee*HB + e];
        float4 v0 = vp4c[ee*5+0], v1 = vp4c[ee*5+1], v2 = vp4c[ee*5+2], v3 = vp4c[ee*5+3];
        float vv[16];
        vv[0]=v0.x; vv[1]=v0.y; vv[2]=v0.z; vv[3]=v0.w;
        vv[4]=v1.x; vv[5]=v1.y; vv[6]=v1.z; vv[7]=v1.w;
        vv[8]=v2.x; vv[9]=v2.y; vv[10]=v2.z; vv[11]=v2.w;
        vv[12]=v3.x; vv[13]=v3.y; vv[14]=v3.z; vv[15]=v3.w;
        #pragma unroll
        for (int r=0; r<16; r++) ma[r] = fmaf(wov, vv[r], ma[r]);
    }
    float bov = bo4[e];
    float y[16], s1[16], s2[16];
    #pragma unroll
    for (int r=0; r<16; r++){
        y[r] = fmaf(fac[r], ma[r] + va[r], bov);
        s1[r] = valid ? y[r] : 0.f;
        s2[r] = valid ? y[r]*y[r] : 0.f;
    }
    #pragma unroll
    for (int off=16; off>0; off>>=1){
        #pragma unroll
        for (int r=0; r<16; r++){
            s1[r] += __shfl_down_sync(0xffffffffu, s1[r], off);
            s2[r] += __shfl_down_sync(0xffffffffu, s2[r], off);
        }
    }
    if (lane == 0){
        #pragma unroll
        for (int r=0; r<16; r++){ red1[w*16+r] = s1[r]; red2[w*16+r] = s2[r]; }
    }
    __syncthreads();
    if (tid < 16){
        float sy  = red1[tid]+red1[16+tid]+red1[32+tid]+red1[48+tid];
        float sy2 = red2[tid]+red2[16+tid]+red2[32+tid]+red2[48+tid];
        float mu = sy * (1.0f/120.0f);
        float var = sy2 * (1.0f/120.0f) - mu*mu;
        mus[tid] = mu;
        rss[tid] = rsqrtf(var + 1e-5f);
    }
    __syncthreads();
    if (valid){
        float lgv = lg4[e], lbv = lb4[e];
        #pragma unroll
        for (int r=0; r<16; r++){
            float yn = (y[r] - mus[r]) * rss[r];
            g_buf2[(size_t)(base + r)*HB + e] = yn*lgv + lbv;
        }
    }
}

// ---------------------------------------------------------------- CGLSTM (120 steps)
// One warp per sequence; thread j owns hidden unit j. Weight rows register-
// resident as f32x2 pairs; matvec uses fma.rn.f32x2 (FFMA2) — 64 packed FMAs
// per thread per step instead of 128 scalar.
__global__ __launch_bounds__(256, 1) void k_cglstm(
    const float* __restrict__ w_ih, const float* __restrict__ w_hh,
    const float* __restrict__ b_ih, const float* __restrict__ b_hh,
    const float* __restrict__ cg_w, const float* __restrict__ cg_uw,
    const float* __restrict__ cg_ub,
    float* __restrict__ outh)
{
    __shared__ float wsm[96*34];     // i,f,g rows of w_hh (stride 34: 8B-aligned rows)
    __shared__ float cgsm[32*34];    // cg_uw rows
    __shared__ float xsm[8*HB];
    __shared__ __align__(16) float hbuf[2][8][32]; // double-buffered h per warp
    int tid = threadIdx.x, warp = tid >> 5, lane = tid & 31;

    for (int i = tid; i < 96*32; i += 256) wsm[(i>>5)*34 + (i&31)] = w_hh[i];
    for (int i = tid; i < 32*32; i += 256) cgsm[(i>>5)*34 + (i&31)] = cg_uw[i];
    for (int i = tid; i < 8*HB; i += 256) xsm[i] = g_buf2[(size_t)blockIdx.x*8*HB + i];
    hbuf[0][warp][lane] = 0.0f;
    __syncthreads();

    // register-resident weight rows (packed along k) for hidden unit `lane`
    ull wi2[16], wf2[16], wg2[16], wc2[16];
    {
        const ull* ri = (const ull*)&wsm[lane*34];
        const ull* rf = (const ull*)&wsm[(32+lane)*34];
        const ull* rg = (const ull*)&wsm[(64+lane)*34];
        const ull* rc = (const ull*)&cgsm[lane*34];
        #pragma unroll
        for (int q = 0; q < 16; q++){
            wi2[q] = ri[q]; wf2[q] = rf[q]; wg2[q] = rg[q]; wc2[q] = rc[q];
        }
    }
    float wx_i = w_ih[lane], wx_f = w_ih[32+lane], wx_g = w_ih[64+lane];
    float bi = b_ih[lane] + b_hh[lane];
    float bf = b_ih[32+lane] + b_hh[32+lane];
    float bg = b_ih[64+lane] + b_hh[64+lane];
    float wx_c = cg_w[lane], bc = cg_ub[lane];

    float c = 0.0f, hn = 0.0f;
    int p = 0;
    const float* xrow = &xsm[warp*HB];

    for (int t = 0; t < HB; t++){
        const ull* hp = (const ull*)&hbuf[p][warp][0];
        ull h2[16];
        #pragma unroll
        for (int q = 0; q < 16; q++) h2[q] = hp[q];

        float xv = xrow[t];
        ull Ai = pack2(fmaf(xv, wx_i, bi), 0.0f);
        ull Af = pack2(fmaf(xv, wx_f, bf), 0.0f);
        ull Ag = pack2(fmaf(xv, wx_g, bg), 0.0f);
        ull Ac = pack2(fmaf(xv, wx_c, bc), 0.0f);

        #pragma unroll
        for (int q = 0; q < 16; q++){
            ffma2(Ai, wi2[q], h2[q]);
            ffma2(Af, wf2[q], h2[q]);
            ffma2(Ag, wg2[q], h2[q]);
            ffma2(Ac, wc2[q], h2[q]);
        }

        float2 vi = unpack2(Ai), vf = unpack2(Af), vg = unpack2(Ag), vc = unpack2(Ac);
        float ai = vi.x + vi.y;
        float af = vf.x + vf.y;
        float ag = vg.x + vg.y;
        float ac = vc.x + vc.y;

        c = sigf(af)*c + sigf(ai)*tanhe(ag);
        hn = sigf(ac)*tanhe(c);

        hbuf[1-p][warp][lane] = hn;
        __syncwarp();
        p ^= 1;
    }

    int n = blockIdx.x*8 + warp;
    outh[(size_t)n*32 + lane] = hn;
}

// ---------------------------------------------------------------- conv6/7 + permute + RevIN
__global__ __launch_bounds__(160) void k_head(
    const float* __restrict__ w6, const float* __restrict__ b6,
    const float* __restrict__ w7, const float* __restrict__ b7,
    const float* __restrict__ rev_w, const float* __restrict__ rev_b,
    const float* __restrict__ hin, float* __restrict__ enc)
{
    __shared__ float hs[288], w6s[60*32], w7s[15*60], b6s[60], b7s[15];
    __shared__ float t60s[9*60], t135[135];
    __shared__ float smu, sinv;
    __shared__ float part1[5], part2[5];
    int b = blockIdx.x, tid = threadIdx.x;

    for (int i = tid; i < 60*32; i += 160) w6s[i] = w6[i];
    for (int i = tid; i < 15*60; i += 160) w7s[i] = w7[i];
    if (tid < 60) b6s[tid] = b6[tid];
    if (tid < 15) b7s[tid] = b7[tid];
    for (int i = tid; i < 288; i += 160) hs[i] = hin[(size_t)b*288 + i];
    __syncthreads();

    for (int i = tid; i < 540; i += 160){
        int dd = i/60, u = i - dd*60;
        float acc = b6s[u];
        #pragma unroll 8
        for (int k=0; k<32; k++) acc = fmaf(w6s[u*32+k], hs[dd*32+k], acc);
        t60s[i] = fmaxf(acc, 0.0f) + log1pf(__expf(-fabsf(acc)));
    }
    __syncthreads();
    if (tid < 135){
        int dd = tid/15, f = tid - dd*15;
        float acc = b7s[f];
        #pragma unroll 6
        for (int u=0; u<60; u++) acc = fmaf(w7s[f*60+u], t60s[dd*60+u], acc);
        t135[tid] = tanhf(acc);
    }
    __syncthreads();
    float v  = (tid < 135) ? t135[tid] : 0.0f;
    float v2 = v*v;
    #pragma unroll
    for (int off=16; off>0; off>>=1){
        v  += __shfl_down_sync(0xffffffffu, v,  off);
        v2 += __shfl_down_sync(0xffffffffu, v2, off);
    }
    if ((tid & 31) == 0){ part1[tid>>5] = v; part2[tid>>5] = v2; }
    __syncthreads();
    if (tid == 0){
        float s1 = 0.f, s2 = 0.f;
        #pragma unroll
        for (int w=0; w<5; w++){ s1 += part1[w]; s2 += part2[w]; }
        float mu = s1 * (1.0f/135.0f);
        float var = fmaxf((s2 - 135.0f*mu*mu) * (1.0f/134.0f), 0.0f);
        float sd = fmaxf(sqrtf(var), 1e-5f);
        smu = mu; sinv = 1.0f/sd;
    }
    __syncthreads();
    if (tid < 135){
        int dp = tid/15, fp = tid - dp*15;
        float yv = t135[fp*9 + dp];       // transpose_8
        enc[(size_t)b*135 + tid] = (yv - smu)*sinv*rev_w[tid] + rev_b[tid];
    }
}

// ---------------------------------------------------------------- launch
extern "C" void kernel_launch(void* const* d_in, const int* in_sizes, int n_in,
                              void* d_out, int out_size)
{
    const float* x     = (const float*)d_in[0];
    const float* bn_g  = (const float*)d_in[1];
    const float* bn_b  = (const float*)d_in[2];
    const float* bn_m  = (const float*)d_in[3];
    const float* bn_v  = (const float*)d_in[4];
    const float* wq2   = (const float*)d_in[5];
    const float* wk2   = (const float*)d_in[6];
    const float* wv2   = (const float*)d_in[7];
    const float* wo2   = (const float*)d_in[8];
    const float* bo2   = (const float*)d_in[9];
    const float* ln2g  = (const float*)d_in[10];
    const float* ln2b  = (const float*)d_in[11];
    const float* wq4   = (const float*)d_in[12];
    const float* wk4   = (const float*)d_in[13];
    const float* wv4   = (const float*)d_in[14];
    const float* wo4   = (const float*)d_in[15];
    const float* bo4   = (const float*)d_in[16];
    const float* ln4g  = (const float*)d_in[17];
    const float* ln4b  = (const float*)d_in[18];
    const float* w_ih  = (const float*)d_in[19];
    const float* w_hh  = (const float*)d_in[20];
    const float* b_ih  = (const float*)d_in[21];
    const float* b_hh  = (const float*)d_in[22];
    const float* cg_w  = (const float*)d_in[23];
    const float* cg_uw = (const float*)d_in[24];
    const float* cg_ub = (const float*)d_in[25];
    const float* w6    = (const float*)d_in[26];
    const float* b6    = (const float*)d_in[27];
    const float* w7    = (const float*)d_in[28];
    const float* b7    = (const float*)d_in[29];
    const float* rev_w = (const float*)d_in[30];
    const float* rev_b = (const float*)d_in[31];
    float* out = (float*)d_out;

    k_transpose_w<<<(4*HB*HB + 255)/256, 256>>>(wq4, wk4, wv4, wo4);
    k_attn2<<<BATCH, 128>>>(x, bn_g, bn_b, bn_m, bn_v, wq2, wk2, wv2, wo2, bo2, ln2g, ln2b);
    k_attn4<<<NSEQ/16, 128>>>(bo4, ln4g, ln4b);
    k_cglstm<<<NSEQ/8, 256>>>(w_ih, w_hh, b_ih, b_hh, cg_w, cg_uw, cg_ub, out);
    k_head<<<BATCH, 160>>>(w6, b6, w7, b7, rev_w, rev_b, out, out + (size_t)BATCH*288);
}

// round 4
// speedup vs baseline: 1.6372x; 1.3932x over previous
#include <cuda_runtime.h>

#define BATCH 16384
#define HB 120
#define BD 9
#define NSEQ (BATCH*BD)   /* 147456 */
#define NS 32
#define NF 15

// scratch (no cudaMalloc allowed)
__device__ float g_buf1[NSEQ*HB];      // attn2 output, transposed: [(b*9+d)*120 + s]
__device__ float g_buf2[NSEQ*HB];      // attn4 output: [n*120 + t]
__device__ float g_wT[4*HB*HB];        // transposed wq4,wk4,wv4,wo4

__device__ __forceinline__ float sigf(float x){ return 1.0f/(1.0f+__expf(-x)); }
__device__ __forceinline__ float tanhe(float x){ return 1.0f - 2.0f/(__expf(2.0f*x)+1.0f); }
__device__ __forceinline__ float phif(float x){ return x>0.0f ? x+1.0f : __expf(x); }
// fast sigmoid via MUFU.TANH: sig(x) = 0.5 + 0.5*tanh(x/2)   (1 MUFU instead of 2)
__device__ __forceinline__ float sigt(float x){
    float t;
    asm("tanh.approx.f32 %0, %1;" : "=f"(t) : "f"(0.5f*x));
    return fmaf(0.5f, t, 0.5f);
}

typedef unsigned long long ull;
__device__ __forceinline__ ull pack2(float lo, float hi){
    ull r; asm("mov.b64 %0, {%1, %2};" : "=l"(r) : "f"(lo), "f"(hi)); return r;
}
__device__ __forceinline__ float2 unpack2(ull v){
    float2 f; asm("mov.b64 {%0, %1}, %2;" : "=f"(f.x), "=f"(f.y) : "l"(v)); return f;
}
__device__ __forceinline__ void ffma2(ull &d, ull a, ull b){
    asm("fma.rn.f32x2 %0, %1, %2, %0;" : "+l"(d) : "l"(a), "l"(b));
}

// ---------------------------------------------------------------- weights transpose
__global__ void k_transpose_w(const float* __restrict__ wq, const float* __restrict__ wk,
                              const float* __restrict__ wv, const float* __restrict__ wo){
    int idx = blockIdx.x*blockDim.x + threadIdx.x;
    if (idx >= 4*HB*HB) return;
    int m = idx/(HB*HB); int i = idx - m*(HB*HB);
    int a = i/HB, b = i - a*HB;
    const float* src = (m==0)?wq : (m==1)?wk : (m==2)?wv : wo;
    g_wT[idx] = src[b*HB + a];
}

// ---------------------------------------------------------------- BN + lin_attn_2 + transpose
__global__ __launch_bounds__(128) void k_attn2(
    const float* __restrict__ x,
    const float* __restrict__ bng, const float* __restrict__ bnb,
    const float* __restrict__ bnm, const float* __restrict__ bnv,
    const float* __restrict__ wq, const float* __restrict__ wk,
    const float* __restrict__ wv, const float* __restrict__ wo,
    const float* __restrict__ bo, const float* __restrict__ lg,
    const float* __restrict__ lb)
{
    __shared__ float xs[HB*13], qs[HB*13], ks[HB*13], vs[HB*13];
    __shared__ float wqs[81], wks[81], wvs[81], wos[81];
    __shared__ float kvs[81], ksum[9], bos[9], lgs[9], lbs[9];
    int b = blockIdx.x, tid = threadIdx.x;

    for (int i = tid; i < 1080; i += 128){
        float val = (x[(size_t)b*1080 + i] - bnm[i]) * rsqrtf(bnv[i] + 1e-5f) * bng[i] + bnb[i];
        xs[(i/9)*13 + (i%9)] = val;
    }
    if (tid < 81){ wqs[tid]=wq[tid]; wks[tid]=wk[tid]; wvs[tid]=wv[tid]; wos[tid]=wo[tid]; }
    if (tid < 9){ bos[tid]=bo[tid]; lgs[tid]=lg[tid]; lbs[tid]=lb[tid]; }
    __syncthreads();

    if (tid < HB){
        float xr[9];
        #pragma unroll
        for (int d=0; d<9; d++) xr[d] = xs[tid*13+d];
        #pragma unroll
        for (int e=0; e<9; e++){
            float aq=0.f, ak=0.f, av=0.f;
            #pragma unroll
            for (int d=0; d<9; d++){
                aq = fmaf(xr[d], wqs[e*9+d], aq);
                ak = fmaf(xr[d], wks[e*9+d], ak);
                av = fmaf(xr[d], wvs[e*9+d], av);
            }
            qs[tid*13+e] = phif(aq);
            ks[tid*13+e] = phif(ak);
            vs[tid*13+e] = av;
        }
    }
    __syncthreads();

    if (tid < 81){
        int d = tid/9, e = tid%9;
        float acc = 0.f;
        for (int s=0; s<HB; s++) acc = fmaf(ks[s*13+d], vs[s*13+e], acc);
        kvs[tid] = acc;
    } else if (tid < 90){
        int e = tid - 81;
        float acc = 0.f;
        for (int s=0; s<HB; s++) acc += ks[s*13+e];
        ksum[e] = acc;
    }
    __syncthreads();

    if (tid < HB){
        float q[9], o[9];
        float den = 0.f;
        #pragma unroll
        for (int e=0; e<9; e++){ q[e] = qs[tid*13+e]; den = fmaf(q[e], ksum[e], den); }
        float inv = 1.0f / fmaxf(den, 1e-6f);
        #pragma unroll
        for (int e=0; e<9; e++){
            float num = 0.f;
            #pragma unroll
            for (int d=0; d<9; d++) num = fmaf(q[d], kvs[d*9+e], num);
            o[e] = num * inv;
        }
        float y[9]; float mu = 0.f;
        #pragma unroll
        for (int f=0; f<9; f++){
            float acc = bos[f] + o[f];
            #pragma unroll
            for (int e=0; e<9; e++) acc = fmaf(o[e], wos[f*9+e], acc);
            y[f] = acc; mu += acc;
        }
        mu *= (1.0f/9.0f);
        float var = 0.f;
        #pragma unroll
        for (int f=0; f<9; f++){ float dd = y[f]-mu; var = fmaf(dd, dd, var); }
        var *= (1.0f/9.0f);
        float rs = rsqrtf(var + 1e-5f);
        #pragma unroll
        for (int f=0; f<9; f++){
            g_buf1[(size_t)b*1080 + f*HB + tid] = (y[f]-mu)*rs*lgs[f] + lbs[f];
        }
    }
}

// ---------------------------------------------------------------- lin_attn_4 (S=1 collapsed)
__global__ __launch_bounds__(128) void k_attn4(
    const float* __restrict__ bo4, const float* __restrict__ lg4,
    const float* __restrict__ lb4)
{
    __shared__ float xsT[HB*20];
    __shared__ float vsT[HB*20];
    __shared__ float red1[4*16], red2[4*16];
    __shared__ float fac[16], mus[16], rss[16];
    int tid = threadIdx.x;
    int base = blockIdx.x * 16;

    for (int i = tid; i < 16*HB; i += 128){
        int r = i / HB, d = i - r*HB;
        xsT[d*20 + r] = g_buf1[(size_t)(base + r)*HB + d];
    }
    __syncthreads();

    bool valid = tid < HB;
    int e = valid ? tid : 0;
    const float* wqT = g_wT;
    const float* wkT = g_wT + HB*HB;
    const float* wvT = g_wT + 2*HB*HB;
    const float* woT = g_wT + 3*HB*HB;

    float qa[16], ka[16], va[16];
    #pragma unroll
    for (int r=0; r<16; r++){ qa[r]=0.f; ka[r]=0.f; va[r]=0.f; }

    const float4* xp4 = (const float4*)xsT;
    #pragma unroll 2
    for (int d=0; d<HB; d++){
        float wqv = wqT[d*HB + e];
        float wkv = wkT[d*HB + e];
        float wvv = wvT[d*HB + e];
        float4 x0 = xp4[d*5+0], x1 = xp4[d*5+1], x2 = xp4[d*5+2], x3 = xp4[d*5+3];
        float xv[16];
        xv[0]=x0.x; xv[1]=x0.y; xv[2]=x0.z; xv[3]=x0.w;
        xv[4]=x1.x; xv[5]=x1.y; xv[6]=x1.z; xv[7]=x1.w;
        xv[8]=x2.x; xv[9]=x2.y; xv[10]=x2.z; xv[11]=x2.w;
        xv[12]=x3.x; xv[13]=x3.y; xv[14]=x3.z; xv[15]=x3.w;
        #pragma unroll
        for (int r=0; r<16; r++){
            qa[r] = fmaf(wqv, xv[r], qa[r]);
            ka[r] = fmaf(wkv, xv[r], ka[r]);
            va[r] = fmaf(wvv, xv[r], va[r]);
        }
    }

    float qk[16];
    #pragma unroll
    for (int r=0; r<16; r++) qk[r] = valid ? phif(qa[r])*phif(ka[r]) : 0.0f;

    if (valid){
        float4* vp4 = (float4*)&vsT[e*20];
        vp4[0] = make_float4(va[0],va[1],va[2],va[3]);
        vp4[1] = make_float4(va[4],va[5],va[6],va[7]);
        vp4[2] = make_float4(va[8],va[9],va[10],va[11]);
        vp4[3] = make_float4(va[12],va[13],va[14],va[15]);
    }

    #pragma unroll
    for (int off=16; off>0; off>>=1){
        #pragma unroll
        for (int r=0; r<16; r++) qk[r] += __shfl_down_sync(0xffffffffu, qk[r], off);
    }
    int w = tid >> 5, lane = tid & 31;
    if (lane == 0){
        #pragma unroll
        for (int r=0; r<16; r++) red1[w*16 + r] = qk[r];
    }
    __syncthreads();
    if (tid < 16){
        float s = red1[tid] + red1[16+tid] + red1[32+tid] + red1[48+tid];
        fac[tid] = s / fmaxf(s, 1e-6f);
    }
    __syncthreads();

    float ma[16];
    #pragma unroll
    for (int r=0; r<16; r++) ma[r] = 0.f;
    const float4* vp4c = (const float4*)vsT;
    #pragma unroll 2
    for (int ee=0; ee<HB; ee++){
        float wov = woT[ee*HB + e];
        float4 v0 = vp4c[ee*5+0], v1 = vp4c[ee*5+1], v2 = vp4c[ee*5+2], v3 = vp4c[ee*5+3];
        float vv[16];
        vv[0]=v0.x; vv[1]=v0.y; vv[2]=v0.z; vv[3]=v0.w;
        vv[4]=v1.x; vv[5]=v1.y; vv[6]=v1.z; vv[7]=v1.w;
        vv[8]=v2.x; vv[9]=v2.y; vv[10]=v2.z; vv[11]=v2.w;
        vv[12]=v3.x; vv[13]=v3.y; vv[14]=v3.z; vv[15]=v3.w;
        #pragma unroll
        for (int r=0; r<16; r++) ma[r] = fmaf(wov, vv[r], ma[r]);
    }
    float bov = bo4[e];
    float y[16], s1[16], s2[16];
    #pragma unroll
    for (int r=0; r<16; r++){
        y[r] = fmaf(fac[r], ma[r] + va[r], bov);
        s1[r] = valid ? y[r] : 0.f;
        s2[r] = valid ? y[r]*y[r] : 0.f;
    }
    #pragma unroll
    for (int off=16; off>0; off>>=1){
        #pragma unroll
        for (int r=0; r<16; r++){
            s1[r] += __shfl_down_sync(0xffffffffu, s1[r], off);
            s2[r] += __shfl_down_sync(0xffffffffu, s2[r], off);
        }
    }
    if (lane == 0){
        #pragma unroll
        for (int r=0; r<16; r++){ red1[w*16+r] = s1[r]; red2[w*16+r] = s2[r]; }
    }
    __syncthreads();
    if (tid < 16){
        float sy  = red1[tid]+red1[16+tid]+red1[32+tid]+red1[48+tid];
        float sy2 = red2[tid]+red2[16+tid]+red2[32+tid]+red2[48+tid];
        float mu = sy * (1.0f/120.0f);
        float var = sy2 * (1.0f/120.0f) - mu*mu;
        mus[tid] = mu;
        rss[tid] = rsqrtf(var + 1e-5f);
    }
    __syncthreads();
    if (valid){
        float lgv = lg4[e], lbv = lb4[e];
        #pragma unroll
        for (int r=0; r<16; r++){
            float yn = (y[r] - mus[r]) * rss[r];
            g_buf2[(size_t)(base + r)*HB + e] = yn*lgv + lbv;
        }
    }
}

// ---------------------------------------------------------------- CGLSTM (120 steps)
// One warp per TWO sequences; thread j owns hidden unit j of both, sharing the
// register-resident weight rows. 8 independent FFMA2 chains per step give full
// latency hiding; sigmoids use MUFU.TANH (1 MUFU), tanh stays exact.
__global__ __launch_bounds__(256, 1) void k_cglstm(
    const float* __restrict__ w_ih, const float* __restrict__ w_hh,
    const float* __restrict__ b_ih, const float* __restrict__ b_hh,
    const float* __restrict__ cg_w, const float* __restrict__ cg_uw,
    const float* __restrict__ cg_ub,
    float* __restrict__ outh)
{
    __shared__ float wsm[96*34];     // i,f,g rows of w_hh (stride 34: 8B-aligned rows)
    __shared__ float cgsm[32*34];    // cg_uw rows
    __shared__ float xsm[16*HB];
    __shared__ __align__(16) float hbuf[2][16][32]; // double-buffered h per sequence
    int tid = threadIdx.x, warp = tid >> 5, lane = tid & 31;

    for (int i = tid; i < 96*32; i += 256) wsm[(i>>5)*34 + (i&31)] = w_hh[i];
    for (int i = tid; i < 32*32; i += 256) cgsm[(i>>5)*34 + (i&31)] = cg_uw[i];
    for (int i = tid; i < 16*HB; i += 256) xsm[i] = g_buf2[(size_t)blockIdx.x*16*HB + i];
    hbuf[0][2*warp][lane] = 0.0f;
    hbuf[0][2*warp+1][lane] = 0.0f;
    __syncthreads();

    // register-resident weight rows (packed along k) for hidden unit `lane`
    ull wi2[16], wf2[16], wg2[16], wc2[16];
    {
        const ull* ri = (const ull*)&wsm[lane*34];
        const ull* rf = (const ull*)&wsm[(32+lane)*34];
        const ull* rg = (const ull*)&wsm[(64+lane)*34];
        const ull* rc = (const ull*)&cgsm[lane*34];
        #pragma unroll
        for (int q = 0; q < 16; q++){
            wi2[q] = ri[q]; wf2[q] = rf[q]; wg2[q] = rg[q]; wc2[q] = rc[q];
        }
    }
    float wx_i = w_ih[lane], wx_f = w_ih[32+lane], wx_g = w_ih[64+lane];
    float bi = b_ih[lane] + b_hh[lane];
    float bf = b_ih[32+lane] + b_hh[32+lane];
    float bg = b_ih[64+lane] + b_hh[64+lane];
    float wx_c = cg_w[lane], bc = cg_ub[lane];

    int sA = 2*warp, sB = 2*warp + 1;
    float cA = 0.0f, cB = 0.0f, hnA = 0.0f, hnB = 0.0f;
    int p = 0;
    const float* xrowA = &xsm[sA*HB];
    const float* xrowB = &xsm[sB*HB];

    for (int t = 0; t < HB; t++){
        const ull* hpA = (const ull*)&hbuf[p][sA][0];
        const ull* hpB = (const ull*)&hbuf[p][sB][0];

        float xa = xrowA[t], xb = xrowB[t];
        ull AiA = pack2(fmaf(xa, wx_i, bi), 0.0f);
        ull AfA = pack2(fmaf(xa, wx_f, bf), 0.0f);
        ull AgA = pack2(fmaf(xa, wx_g, bg), 0.0f);
        ull AcA = pack2(fmaf(xa, wx_c, bc), 0.0f);
        ull AiB = pack2(fmaf(xb, wx_i, bi), 0.0f);
        ull AfB = pack2(fmaf(xb, wx_f, bf), 0.0f);
        ull AgB = pack2(fmaf(xb, wx_g, bg), 0.0f);
        ull AcB = pack2(fmaf(xb, wx_c, bc), 0.0f);

        #pragma unroll
        for (int q = 0; q < 16; q++){
            ull hA = hpA[q];
            ull hB = hpB[q];
            ffma2(AiA, wi2[q], hA); ffma2(AiB, wi2[q], hB);
            ffma2(AfA, wf2[q], hA); ffma2(AfB, wf2[q], hB);
            ffma2(AgA, wg2[q], hA); ffma2(AgB, wg2[q], hB);
            ffma2(AcA, wc2[q], hA); ffma2(AcB, wc2[q], hB);
        }

        float2 viA = unpack2(AiA), vfA = unpack2(AfA), vgA = unpack2(AgA), vcA = unpack2(AcA);
        float2 viB = unpack2(AiB), vfB = unpack2(AfB), vgB = unpack2(AgB), vcB = unpack2(AcB);

        float aiA = viA.x + viA.y, afA = vfA.x + vfA.y;
        float agA = vgA.x + vgA.y, acA = vcA.x + vcA.y;
        float aiB = viB.x + viB.y, afB = vfB.x + vfB.y;
        float agB = vgB.x + vgB.y, acB = vcB.x + vcB.y;

        cA = sigt(afA)*cA + sigt(aiA)*tanhe(agA);
        cB = sigt(afB)*cB + sigt(aiB)*tanhe(agB);
        hnA = sigt(acA)*tanhe(cA);
        hnB = sigt(acB)*tanhe(cB);

        hbuf[1-p][sA][lane] = hnA;
        hbuf[1-p][sB][lane] = hnB;
        __syncwarp();
        p ^= 1;
    }

    int nA = blockIdx.x*16 + sA;
    int nB = blockIdx.x*16 + sB;
    outh[(size_t)nA*32 + lane] = hnA;
    outh[(size_t)nB*32 + lane] = hnB;
}

// ---------------------------------------------------------------- conv6/7 + permute + RevIN
__global__ __launch_bounds__(160) void k_head(
    const float* __restrict__ w6, const float* __restrict__ b6,
    const float* __restrict__ w7, const float* __restrict__ b7,
    const float* __restrict__ rev_w, const float* __restrict__ rev_b,
    const float* __restrict__ hin, float* __restrict__ enc)
{
    __shared__ float hs[288], w6s[60*32], w7s[15*60], b6s[60], b7s[15];
    __shared__ float t60s[9*60], t135[135];
    __shared__ float smu, sinv;
    __shared__ float part1[5], part2[5];
    int b = blockIdx.x, tid = threadIdx.x;

    for (int i = tid; i < 60*32; i += 160) w6s[i] = w6[i];
    for (int i = tid; i < 15*60; i += 160) w7s[i] = w7[i];
    if (tid < 60) b6s[tid] = b6[tid];
    if (tid < 15) b7s[tid] = b7[tid];
    for (int i = tid; i < 288; i += 160) hs[i] = hin[(size_t)b*288 + i];
    __syncthreads();

    for (int i = tid; i < 540; i += 160){
        int dd = i/60, u = i - dd*60;
        float acc = b6s[u];
        #pragma unroll 8
        for (int k=0; k<32; k++) acc = fmaf(w6s[u*32+k], hs[dd*32+k], acc);
        t60s[i] = fmaxf(acc, 0.0f) + log1pf(__expf(-fabsf(acc)));
    }
    __syncthreads();
    if (tid < 135){
        int dd = tid/15, f = tid - dd*15;
        float acc = b7s[f];
        #pragma unroll 6
        for (int u=0; u<60; u++) acc = fmaf(w7s[f*60+u], t60s[dd*60+u], acc);
        t135[tid] = tanhf(acc);
    }
    __syncthreads();
    float v  = (tid < 135) ? t135[tid] : 0.0f;
    float v2 = v*v;
    #pragma unroll
    for (int off=16; off>0; off>>=1){
        v  += __shfl_down_sync(0xffffffffu, v,  off);
        v2 += __shfl_down_sync(0xffffffffu, v2, off);
    }
    if ((tid & 31) == 0){ part1[tid>>5] = v; part2[tid>>5] = v2; }
    __syncthreads();
    if (tid == 0){
        float s1 = 0.f, s2 = 0.f;
        #pragma unroll
        for (int w=0; w<5; w++){ s1 += part1[w]; s2 += part2[w]; }
        float mu = s1 * (1.0f/135.0f);
        float var = fmaxf((s2 - 135.0f*mu*mu) * (1.0f/134.0f), 0.0f);
        float sd = fmaxf(sqrtf(var), 1e-5f);
        smu = mu; sinv = 1.0f/sd;
    }
    __syncthreads();
    if (tid < 135){
        int dp = tid/15, fp = tid - dp*15;
        float yv = t135[fp*9 + dp];       // transpose_8
        enc[(size_t)b*135 + tid] = (yv - smu)*sinv*rev_w[tid] + rev_b[tid];
    }
}

// ---------------------------------------------------------------- launch
extern "C" void kernel_launch(void* const* d_in, const int* in_sizes, int n_in,
                              void* d_out, int out_size)
{
    const float* x     = (const float*)d_in[0];
    const float* bn_g  = (const float*)d_in[1];
    const float* bn_b  = (const float*)d_in[2];
    const float* bn_m  = (const float*)d_in[3];
    const float* bn_v  = (const float*)d_in[4];
    const float* wq2   = (const float*)d_in[5];
    const float* wk2   = (const float*)d_in[6];
    const float* wv2   = (const float*)d_in[7];
    const float* wo2   = (const float*)d_in[8];
    const float* bo2   = (const float*)d_in[9];
    const float* ln2g  = (const float*)d_in[10];
    const float* ln2b  = (const float*)d_in[11];
    const float* wq4   = (const float*)d_in[12];
    const float* wk4   = (const float*)d_in[13];
    const float* wv4   = (const float*)d_in[14];
    const float* wo4   = (const float*)d_in[15];
    const float* bo4   = (const float*)d_in[16];
    const float* ln4g  = (const float*)d_in[17];
    const float* ln4b  = (const float*)d_in[18];
    const float* w_ih  = (const float*)d_in[19];
    const float* w_hh  = (const float*)d_in[20];
    const float* b_ih  = (const float*)d_in[21];
    const float* b_hh  = (const float*)d_in[22];
    const float* cg_w  = (const float*)d_in[23];
    const float* cg_uw = (const float*)d_in[24];
    const float* cg_ub = (const float*)d_in[25];
    const float* w6    = (const float*)d_in[26];
    const float* b6    = (const float*)d_in[27];
    const float* w7    = (const float*)d_in[28];
    const float* b7    = (const float*)d_in[29];
    const float* rev_w = (const float*)d_in[30];
    const float* rev_b = (const float*)d_in[31];
    float* out = (float*)d_out;

    k_transpose_w<<<(4*HB*HB + 255)/256, 256>>>(wq4, wk4, wv4, wo4);
    k_attn2<<<BATCH, 128>>>(x, bn_g, bn_b, bn_m, bn_v, wq2, wk2, wv2, wo2, bo2, ln2g, ln2b);
    k_attn4<<<NSEQ/16, 128>>>(bo4, ln4g, ln4b);
    k_cglstm<<<NSEQ/16, 256>>>(w_ih, w_hh, b_ih, b_hh, cg_w, cg_uw, cg_ub, out);
    k_head<<<BATCH, 160>>>(w6, b6, w7, b7, rev_w, rev_b, out, out + (size_t)BATCH*288);
}

// round 5
// speedup vs baseline: 1.7489x; 1.0682x over previous
#include <cuda_runtime.h>

#define BATCH 16384
#define HB 120
#define BD 9
#define NSEQ (BATCH*BD)   /* 147456 */
#define NS 32
#define NF 15

// scratch (no cudaMalloc allowed)
__device__ float g_buf1[NSEQ*HB];      // attn2 output, transposed: [(b*9+d)*120 + s]
__device__ float g_buf2[NSEQ*HB];      // attn4 output: [n*120 + t]
__device__ float g_wT[4*HB*HB];        // transposed wq4,wk4,wv4,wo4

__device__ __forceinline__ float sigf(float x){ return 1.0f/(1.0f+__expf(-x)); }
__device__ __forceinline__ float tanhe(float x){ return 1.0f - 2.0f/(__expf(2.0f*x)+1.0f); }
__device__ __forceinline__ float phif(float x){ return x>0.0f ? x+1.0f : __expf(x); }
// fast sigmoid via MUFU.TANH: sig(x) = 0.5 + 0.5*tanh(x/2)
__device__ __forceinline__ float sigt(float x){
    float t;
    asm("tanh.approx.f32 %0, %1;" : "=f"(t) : "f"(0.5f*x));
    return fmaf(0.5f, t, 0.5f);
}
__device__ __forceinline__ float tanht(float x){
    float t;
    asm("tanh.approx.f32 %0, %1;" : "=f"(t) : "f"(x));
    return t;
}

typedef unsigned long long ull;
__device__ __forceinline__ ull pack2(float lo, float hi){
    ull r; asm("mov.b64 %0, {%1, %2};" : "=l"(r) : "f"(lo), "f"(hi)); return r;
}
__device__ __forceinline__ float2 unpack2(ull v){
    float2 f; asm("mov.b64 {%0, %1}, %2;" : "=f"(f.x), "=f"(f.y) : "l"(v)); return f;
}
__device__ __forceinline__ void ffma2(ull &d, ull a, ull b){
    asm("fma.rn.f32x2 %0, %1, %2, %0;" : "+l"(d) : "l"(a), "l"(b));
}

// ---------------------------------------------------------------- weights transpose
__global__ void k_transpose_w(const float* __restrict__ wq, const float* __restrict__ wk,
                              const float* __restrict__ wv, const float* __restrict__ wo){
    int idx = blockIdx.x*blockDim.x + threadIdx.x;
    if (idx >= 4*HB*HB) return;
    int m = idx/(HB*HB); int i = idx - m*(HB*HB);
    int a = i/HB, b = i - a*HB;
    const float* src = (m==0)?wq : (m==1)?wk : (m==2)?wv : wo;
    g_wT[idx] = src[b*HB + a];
}

// ---------------------------------------------------------------- BN + lin_attn_2 + transpose
__global__ __launch_bounds__(128) void k_attn2(
    const float* __restrict__ x,
    const float* __restrict__ bng, const float* __restrict__ bnb,
    const float* __restrict__ bnm, const float* __restrict__ bnv,
    const float* __restrict__ wq, const float* __restrict__ wk,
    const float* __restrict__ wv, const float* __restrict__ wo,
    const float* __restrict__ bo, const float* __restrict__ lg,
    const float* __restrict__ lb)
{
    __shared__ float xs[HB*13], qs[HB*13], ks[HB*13], vs[HB*13];
    __shared__ float wqs[81], wks[81], wvs[81], wos[81];
    __shared__ float kvs[81], ksum[9], bos[9], lgs[9], lbs[9];
    int b = blockIdx.x, tid = threadIdx.x;

    for (int i = tid; i < 1080; i += 128){
        float val = (x[(size_t)b*1080 + i] - bnm[i]) * rsqrtf(bnv[i] + 1e-5f) * bng[i] + bnb[i];
        xs[(i/9)*13 + (i%9)] = val;
    }
    if (tid < 81){ wqs[tid]=wq[tid]; wks[tid]=wk[tid]; wvs[tid]=wv[tid]; wos[tid]=wo[tid]; }
    if (tid < 9){ bos[tid]=bo[tid]; lgs[tid]=lg[tid]; lbs[tid]=lb[tid]; }
    __syncthreads();

    if (tid < HB){
        float xr[9];
        #pragma unroll
        for (int d=0; d<9; d++) xr[d] = xs[tid*13+d];
        #pragma unroll
        for (int e=0; e<9; e++){
            float aq=0.f, ak=0.f, av=0.f;
            #pragma unroll
            for (int d=0; d<9; d++){
                aq = fmaf(xr[d], wqs[e*9+d], aq);
                ak = fmaf(xr[d], wks[e*9+d], ak);
                av = fmaf(xr[d], wvs[e*9+d], av);
            }
            qs[tid*13+e] = phif(aq);
            ks[tid*13+e] = phif(ak);
            vs[tid*13+e] = av;
        }
    }
    __syncthreads();

    if (tid < 81){
        int d = tid/9, e = tid%9;
        float acc = 0.f;
        for (int s=0; s<HB; s++) acc = fmaf(ks[s*13+d], vs[s*13+e], acc);
        kvs[tid] = acc;
    } else if (tid < 90){
        int e = tid - 81;
        float acc = 0.f;
        for (int s=0; s<HB; s++) acc += ks[s*13+e];
        ksum[e] = acc;
    }
    __syncthreads();

    if (tid < HB){
        float q[9], o[9];
        float den = 0.f;
        #pragma unroll
        for (int e=0; e<9; e++){ q[e] = qs[tid*13+e]; den = fmaf(q[e], ksum[e], den); }
        float inv = 1.0f / fmaxf(den, 1e-6f);
        #pragma unroll
        for (int e=0; e<9; e++){
            float num = 0.f;
            #pragma unroll
            for (int d=0; d<9; d++) num = fmaf(q[d], kvs[d*9+e], num);
            o[e] = num * inv;
        }
        float y[9]; float mu = 0.f;
        #pragma unroll
        for (int f=0; f<9; f++){
            float acc = bos[f] + o[f];
            #pragma unroll
            for (int e=0; e<9; e++) acc = fmaf(o[e], wos[f*9+e], acc);
            y[f] = acc; mu += acc;
        }
        mu *= (1.0f/9.0f);
        float var = 0.f;
        #pragma unroll
        for (int f=0; f<9; f++){ float dd = y[f]-mu; var = fmaf(dd, dd, var); }
        var *= (1.0f/9.0f);
        float rs = rsqrtf(var + 1e-5f);
        #pragma unroll
        for (int f=0; f<9; f++){
            g_buf1[(size_t)b*1080 + f*HB + tid] = (y[f]-mu)*rs*lgs[f] + lbs[f];
        }
    }
}

// ---------------------------------------------------------------- lin_attn_4 (S=1 collapsed)
__global__ __launch_bounds__(128) void k_attn4(
    const float* __restrict__ bo4, const float* __restrict__ lg4,
    const float* __restrict__ lb4)
{
    __shared__ float xsT[HB*20];
    __shared__ float vsT[HB*20];
    __shared__ float red1[4*16], red2[4*16];
    __shared__ float fac[16], mus[16], rss[16];
    int tid = threadIdx.x;
    int base = blockIdx.x * 16;

    for (int i = tid; i < 16*HB; i += 128){
        int r = i / HB, d = i - r*HB;
        xsT[d*20 + r] = g_buf1[(size_t)(base + r)*HB + d];
    }
    __syncthreads();

    bool valid = tid < HB;
    int e = valid ? tid : 0;
    const float* wqT = g_wT;
    const float* wkT = g_wT + HB*HB;
    const float* wvT = g_wT + 2*HB*HB;
    const float* woT = g_wT + 3*HB*HB;

    float qa[16], ka[16], va[16];
    #pragma unroll
    for (int r=0; r<16; r++){ qa[r]=0.f; ka[r]=0.f; va[r]=0.f; }

    const float4* xp4 = (const float4*)xsT;
    #pragma unroll 2
    for (int d=0; d<HB; d++){
        float wqv = wqT[d*HB + e];
        float wkv = wkT[d*HB + e];
        float wvv = wvT[d*HB + e];
        float4 x0 = xp4[d*5+0], x1 = xp4[d*5+1], x2 = xp4[d*5+2], x3 = xp4[d*5+3];
        float xv[16];
        xv[0]=x0.x; xv[1]=x0.y; xv[2]=x0.z; xv[3]=x0.w;
        xv[4]=x1.x; xv[5]=x1.y; xv[6]=x1.z; xv[7]=x1.w;
        xv[8]=x2.x; xv[9]=x2.y; xv[10]=x2.z; xv[11]=x2.w;
        xv[12]=x3.x; xv[13]=x3.y; xv[14]=x3.z; xv[15]=x3.w;
        #pragma unroll
        for (int r=0; r<16; r++){
            qa[r] = fmaf(wqv, xv[r], qa[r]);
            ka[r] = fmaf(wkv, xv[r], ka[r]);
            va[r] = fmaf(wvv, xv[r], va[r]);
        }
    }

    float qk[16];
    #pragma unroll
    for (int r=0; r<16; r++) qk[r] = valid ? phif(qa[r])*phif(ka[r]) : 0.0f;

    if (valid){
        float4* vp4 = (float4*)&vsT[e*20];
        vp4[0] = make_float4(va[0],va[1],va[2],va[3]);
        vp4[1] = make_float4(va[4],va[5],va[6],va[7]);
        vp4[2] = make_float4(va[8],va[9],va[10],va[11]);
        vp4[3] = make_float4(va[12],va[13],va[14],va[15]);
    }

    #pragma unroll
    for (int off=16; off>0; off>>=1){
        #pragma unroll
        for (int r=0; r<16; r++) qk[r] += __shfl_down_sync(0xffffffffu, qk[r], off);
    }
    int w = tid >> 5, lane = tid & 31;
    if (lane == 0){
        #pragma unroll
        for (int r=0; r<16; r++) red1[w*16 + r] = qk[r];
    }
    __syncthreads();
    if (tid < 16){
        float s = red1[tid] + red1[16+tid] + red1[32+tid] + red1[48+tid];
        fac[tid] = s / fmaxf(s, 1e-6f);
    }
    __syncthreads();

    float ma[16];
    #pragma unroll
    for (int r=0; r<16; r++) ma[r] = 0.f;
    const float4* vp4c = (const float4*)vsT;
    #pragma unroll 2
    for (int ee=0; ee<HB; ee++){
        float wov = woT[ee*HB + e];
        float4 v0 = vp4c[ee*5+0], v1 = vp4c[ee*5+1], v2 = vp4c[ee*5+2], v3 = vp4c[ee*5+3];
        float vv[16];
        vv[0]=v0.x; vv[1]=v0.y; vv[2]=v0.z; vv[3]=v0.w;
        vv[4]=v1.x; vv[5]=v1.y; vv[6]=v1.z; vv[7]=v1.w;
        vv[8]=v2.x; vv[9]=v2.y; vv[10]=v2.z; vv[11]=v2.w;
        vv[12]=v3.x; vv[13]=v3.y; vv[14]=v3.z; vv[15]=v3.w;
        #pragma unroll
        for (int r=0; r<16; r++) ma[r] = fmaf(wov, vv[r], ma[r]);
    }
    float bov = bo4[e];
    float y[16], s1[16], s2[16];
    #pragma unroll
    for (int r=0; r<16; r++){
        y[r] = fmaf(fac[r], ma[r] + va[r], bov);
        s1[r] = valid ? y[r] : 0.f;
        s2[r] = valid ? y[r]*y[r] : 0.f;
    }
    #pragma unroll
    for (int off=16; off>0; off>>=1){
        #pragma unroll
        for (int r=0; r<16; r++){
            s1[r] += __shfl_down_sync(0xffffffffu, s1[r], off);
            s2[r] += __shfl_down_sync(0xffffffffu, s2[r], off);
        }
    }
    if (lane == 0){
        #pragma unroll
        for (int r=0; r<16; r++){ red1[w*16+r] = s1[r]; red2[w*16+r] = s2[r]; }
    }
    __syncthreads();
    if (tid < 16){
        float sy  = red1[tid]+red1[16+tid]+red1[32+tid]+red1[48+tid];
        float sy2 = red2[tid]+red2[16+tid]+red2[32+tid]+red2[48+tid];
        float mu = sy * (1.0f/120.0f);
        float var = sy2 * (1.0f/120.0f) - mu*mu;
        mus[tid] = mu;
        rss[tid] = rsqrtf(var + 1e-5f);
    }
    __syncthreads();
    if (valid){
        float lgv = lg4[e], lbv = lb4[e];
        #pragma unroll
        for (int r=0; r<16; r++){
            float yn = (y[r] - mus[r]) * rss[r];
            g_buf2[(size_t)(base + r)*HB + e] = yn*lgv + lbv;
        }
    }
}

// ---------------------------------------------------------------- CGLSTM (120 steps)
// One warp per FOUR sequences; thread j owns hidden unit j of all four, sharing
// the register-resident weight rows. 16 independent FFMA2 chains per step.
__global__ __launch_bounds__(256, 1) void k_cglstm(
    const float* __restrict__ w_ih, const float* __restrict__ w_hh,
    const float* __restrict__ b_ih, const float* __restrict__ b_hh,
    const float* __restrict__ cg_w, const float* __restrict__ cg_uw,
    const float* __restrict__ cg_ub,
    float* __restrict__ outh)
{
    __shared__ float wsm[96*34];     // i,f,g rows of w_hh (stride 34: 8B-aligned rows)
    __shared__ float cgsm[32*34];    // cg_uw rows
    __shared__ float xsm[32*HB];
    __shared__ __align__(16) float hbuf[2][32][32]; // double-buffered h per sequence
    int tid = threadIdx.x, warp = tid >> 5, lane = tid & 31;

    for (int i = tid; i < 96*32; i += 256) wsm[(i>>5)*34 + (i&31)] = w_hh[i];
    for (int i = tid; i < 32*32; i += 256) cgsm[(i>>5)*34 + (i&31)] = cg_uw[i];
    for (int i = tid; i < 32*HB; i += 256) xsm[i] = g_buf2[(size_t)blockIdx.x*32*HB + i];
    #pragma unroll
    for (int s = 0; s < 4; s++) hbuf[0][4*warp + s][lane] = 0.0f;
    __syncthreads();

    // register-resident weight rows (packed along k) for hidden unit `lane`
    ull wi2[16], wf2[16], wg2[16], wc2[16];
    {
        const ull* ri = (const ull*)&wsm[lane*34];
        const ull* rf = (const ull*)&wsm[(32+lane)*34];
        const ull* rg = (const ull*)&wsm[(64+lane)*34];
        const ull* rc = (const ull*)&cgsm[lane*34];
        #pragma unroll
        for (int q = 0; q < 16; q++){
            wi2[q] = ri[q]; wf2[q] = rf[q]; wg2[q] = rg[q]; wc2[q] = rc[q];
        }
    }
    float wx_i = w_ih[lane], wx_f = w_ih[32+lane], wx_g = w_ih[64+lane];
    float bi = b_ih[lane] + b_hh[lane];
    float bf = b_ih[32+lane] + b_hh[32+lane];
    float bg = b_ih[64+lane] + b_hh[64+lane];
    float wx_c = cg_w[lane], bc = cg_ub[lane];

    float cS[4] = {0.f,0.f,0.f,0.f};
    float hnS[4] = {0.f,0.f,0.f,0.f};
    int p = 0;
    int s0 = 4*warp;

    for (int t = 0; t < HB; t++){
        ull Ai[4], Af[4], Ag[4], Ac[4];
        #pragma unroll
        for (int s = 0; s < 4; s++){
            float xv = xsm[(s0+s)*HB + t];
            Ai[s] = pack2(fmaf(xv, wx_i, bi), 0.0f);
            Af[s] = pack2(fmaf(xv, wx_f, bf), 0.0f);
            Ag[s] = pack2(fmaf(xv, wx_g, bg), 0.0f);
            Ac[s] = pack2(fmaf(xv, wx_c, bc), 0.0f);
        }

        const ull* hp0 = (const ull*)&hbuf[p][s0+0][0];
        const ull* hp1 = (const ull*)&hbuf[p][s0+1][0];
        const ull* hp2 = (const ull*)&hbuf[p][s0+2][0];
        const ull* hp3 = (const ull*)&hbuf[p][s0+3][0];

        #pragma unroll
        for (int q = 0; q < 16; q++){
            ull h0 = hp0[q], h1 = hp1[q], h2v = hp2[q], h3 = hp3[q];
            ffma2(Ai[0], wi2[q], h0); ffma2(Ai[1], wi2[q], h1);
            ffma2(Ai[2], wi2[q], h2v); ffma2(Ai[3], wi2[q], h3);
            ffma2(Af[0], wf2[q], h0); ffma2(Af[1], wf2[q], h1);
            ffma2(Af[2], wf2[q], h2v); ffma2(Af[3], wf2[q], h3);
            ffma2(Ag[0], wg2[q], h0); ffma2(Ag[1], wg2[q], h1);
            ffma2(Ag[2], wg2[q], h2v); ffma2(Ag[3], wg2[q], h3);
            ffma2(Ac[0], wc2[q], h0); ffma2(Ac[1], wc2[q], h1);
            ffma2(Ac[2], wc2[q], h2v); ffma2(Ac[3], wc2[q], h3);
        }

        #pragma unroll
        for (int s = 0; s < 4; s++){
            float2 vi = unpack2(Ai[s]), vf = unpack2(Af[s]);
            float2 vg = unpack2(Ag[s]), vc = unpack2(Ac[s]);
            float ai = vi.x + vi.y, af = vf.x + vf.y;
            float ag = vg.x + vg.y, ac = vc.x + vc.y;
            float cn = sigt(af)*cS[s] + sigt(ai)*tanht(ag);
            cS[s] = cn;
            hnS[s] = sigt(ac)*tanhe(cn);
            hbuf[1-p][s0+s][lane] = hnS[s];
        }
        __syncwarp();
        p ^= 1;
    }

    #pragma unroll
    for (int s = 0; s < 4; s++){
        int n = blockIdx.x*32 + s0 + s;
        outh[(size_t)n*32 + lane] = hnS[s];
    }
}

// ---------------------------------------------------------------- conv6/7 + permute + RevIN
__global__ __launch_bounds__(160) void k_head(
    const float* __restrict__ w6, const float* __restrict__ b6,
    const float* __restrict__ w7, const float* __restrict__ b7,
    const float* __restrict__ rev_w, const float* __restrict__ rev_b,
    const float* __restrict__ hin, float* __restrict__ enc)
{
    __shared__ float hs[288], w6s[60*32], w7s[15*60], b6s[60], b7s[15];
    __shared__ float t60s[9*60], t135[135];
    __shared__ float smu, sinv;
    __shared__ float part1[5], part2[5];
    int b = blockIdx.x, tid = threadIdx.x;

    for (int i = tid; i < 60*32; i += 160) w6s[i] = w6[i];
    for (int i = tid; i < 15*60; i += 160) w7s[i] = w7[i];
    if (tid < 60) b6s[tid] = b6[tid];
    if (tid < 15) b7s[tid] = b7[tid];
    for (int i = tid; i < 288; i += 160) hs[i] = hin[(size_t)b*288 + i];
    __syncthreads();

    for (int i = tid; i < 540; i += 160){
        int dd = i/60, u = i - dd*60;
        float acc = b6s[u];
        #pragma unroll 8
        for (int k=0; k<32; k++) acc = fmaf(w6s[u*32+k], hs[dd*32+k], acc);
        t60s[i] = fmaxf(acc, 0.0f) + log1pf(__expf(-fabsf(acc)));
    }
    __syncthreads();
    if (tid < 135){
        int dd = tid/15, f = tid - dd*15;
        float acc = b7s[f];
        #pragma unroll 6
        for (int u=0; u<60; u++) acc = fmaf(w7s[f*60+u], t60s[dd*60+u], acc);
        t135[tid] = tanhf(acc);
    }
    __syncthreads();
    float v  = (tid < 135) ? t135[tid] : 0.0f;
    float v2 = v*v;
    #pragma unroll
    for (int off=16; off>0; off>>=1){
        v  += __shfl_down_sync(0xffffffffu, v,  off);
        v2 += __shfl_down_sync(0xffffffffu, v2, off);
    }
    if ((tid & 31) == 0){ part1[tid>>5] = v; part2[tid>>5] = v2; }
    __syncthreads();
    if (tid == 0){
        float s1 = 0.f, s2 = 0.f;
        #pragma unroll
        for (int w=0; w<5; w++){ s1 += part1[w]; s2 += part2[w]; }
        float mu = s1 * (1.0f/135.0f);
        float var = fmaxf((s2 - 135.0f*mu*mu) * (1.0f/134.0f), 0.0f);
        float sd = fmaxf(sqrtf(var), 1e-5f);
        smu = mu; sinv = 1.0f/sd;
    }
    __syncthreads();
    if (tid < 135){
        int dp = tid/15, fp = tid - dp*15;
        float yv = t135[fp*9 + dp];       // transpose_8
        enc[(size_t)b*135 + tid] = (yv - smu)*sinv*rev_w[tid] + rev_b[tid];
    }
}

// ---------------------------------------------------------------- launch
extern "C" void kernel_launch(void* const* d_in, const int* in_sizes, int n_in,
                              void* d_out, int out_size)
{
    const float* x     = (const float*)d_in[0];
    const float* bn_g  = (const float*)d_in[1];
    const float* bn_b  = (const float*)d_in[2];
    const float* bn_m  = (const float*)d_in[3];
    const float* bn_v  = (const float*)d_in[4];
    const float* wq2   = (const float*)d_in[5];
    const float* wk2   = (const float*)d_in[6];
    const float* wv2   = (const float*)d_in[7];
    const float* wo2   = (const float*)d_in[8];
    const float* bo2   = (const float*)d_in[9];
    const float* ln2g  = (const float*)d_in[10];
    const float* ln2b  = (const float*)d_in[11];
    const float* wq4   = (const float*)d_in[12];
    const float* wk4   = (const float*)d_in[13];
    const float* wv4   = (const float*)d_in[14];
    const float* wo4   = (const float*)d_in[15];
    const float* bo4   = (const float*)d_in[16];
    const float* ln4g  = (const float*)d_in[17];
    const float* ln4b  = (const float*)d_in[18];
    const float* w_ih  = (const float*)d_in[19];
    const float* w_hh  = (const float*)d_in[20];
    const float* b_ih  = (const float*)d_in[21];
    const float* b_hh  = (const float*)d_in[22];
    const float* cg_w  = (const float*)d_in[23];
    const float* cg_uw = (const float*)d_in[24];
    const float* cg_ub = (const float*)d_in[25];
    const float* w6    = (const float*)d_in[26];
    const float* b6    = (const float*)d_in[27];
    const float* w7    = (const float*)d_in[28];
    const float* b7    = (const float*)d_in[29];
    const float* rev_w = (const float*)d_in[30];
    const float* rev_b = (const float*)d_in[31];
    float* out = (float*)d_out;

    k_transpose_w<<<(4*HB*HB + 255)/256, 256>>>(wq4, wk4, wv4, wo4);
    k_attn2<<<BATCH, 128>>>(x, bn_g, bn_b, bn_m, bn_v, wq2, wk2, wv2, wo2, bo2, ln2g, ln2b);
    k_attn4<<<NSEQ/16, 128>>>(bo4, ln4g, ln4b);
    k_cglstm<<<NSEQ/32, 256>>>(w_ih, w_hh, b_ih, b_hh, cg_w, cg_uw, cg_ub, out);
    k_head<<<BATCH, 160>>>(w6, b6, w7, b7, rev_w, rev_b, out, out + (size_t)BATCH*288);
}

// round 6
// speedup vs baseline: 2.0885x; 1.1941x over previous
#include <cuda_runtime.h>

#define BATCH 16384
#define HB 120
#define BD 9
#define NSEQ (BATCH*BD)   /* 147456 */
#define NS 32
#define NF 15

// scratch (no cudaMalloc allowed)
__device__ float g_buf1[NSEQ*HB];      // attn2 output, transposed: [(b*9+d)*120 + s]
__device__ float g_buf2[NSEQ*HB];      // attn4 output: [n*120 + t]
__device__ float g_wT[4*HB*HB];        // transposed wq4,wk4,wv4,wo4

__device__ __forceinline__ float sigf(float x){ return 1.0f/(1.0f+__expf(-x)); }
__device__ __forceinline__ float phif(float x){ return x>0.0f ? x+1.0f : __expf(x); }
// fast sigmoid via MUFU.TANH: sig(x) = 0.5 + 0.5*tanh(x/2)
__device__ __forceinline__ float sigt(float x){
    float t;
    asm("tanh.approx.f32 %0, %1;" : "=f"(t) : "f"(0.5f*x));
    return fmaf(0.5f, t, 0.5f);
}
__device__ __forceinline__ float tanht(float x){
    float t;
    asm("tanh.approx.f32 %0, %1;" : "=f"(t) : "f"(x));
    return t;
}

typedef unsigned long long ull;
__device__ __forceinline__ ull pack2(float lo, float hi){
    ull r; asm("mov.b64 %0, {%1, %2};" : "=l"(r) : "f"(lo), "f"(hi)); return r;
}
__device__ __forceinline__ float2 unpack2(ull v){
    float2 f; asm("mov.b64 {%0, %1}, %2;" : "=f"(f.x), "=f"(f.y) : "l"(v)); return f;
}
__device__ __forceinline__ void ffma2(ull &d, ull a, ull b){
    asm("fma.rn.f32x2 %0, %1, %2, %0;" : "+l"(d) : "l"(a), "l"(b));
}

// ---------------------------------------------------------------- weights transpose
__global__ void k_transpose_w(const float* __restrict__ wq, const float* __restrict__ wk,
                              const float* __restrict__ wv, const float* __restrict__ wo){
    int idx = blockIdx.x*blockDim.x + threadIdx.x;
    if (idx >= 4*HB*HB) return;
    int m = idx/(HB*HB); int i = idx - m*(HB*HB);
    int a = i/HB, b = i - a*HB;
    const float* src = (m==0)?wq : (m==1)?wk : (m==2)?wv : wo;
    g_wT[idx] = src[b*HB + a];
}

// ---------------------------------------------------------------- BN + lin_attn_2 + transpose
__global__ __launch_bounds__(128) void k_attn2(
    const float* __restrict__ x,
    const float* __restrict__ bng, const float* __restrict__ bnb,
    const float* __restrict__ bnm, const float* __restrict__ bnv,
    const float* __restrict__ wq, const float* __restrict__ wk,
    const float* __restrict__ wv, const float* __restrict__ wo,
    const float* __restrict__ bo, const float* __restrict__ lg,
    const float* __restrict__ lb)
{
    __shared__ float xs[HB*13], qs[HB*13], ks[HB*13], vs[HB*13];
    __shared__ float wqs[81], wks[81], wvs[81], wos[81];
    __shared__ float kvs[81], ksum[9], bos[9], lgs[9], lbs[9];
    int b = blockIdx.x, tid = threadIdx.x;

    for (int i = tid; i < 1080; i += 128){
        float val = (x[(size_t)b*1080 + i] - bnm[i]) * rsqrtf(bnv[i] + 1e-5f) * bng[i] + bnb[i];
        xs[(i/9)*13 + (i%9)] = val;
    }
    if (tid < 81){ wqs[tid]=wq[tid]; wks[tid]=wk[tid]; wvs[tid]=wv[tid]; wos[tid]=wo[tid]; }
    if (tid < 9){ bos[tid]=bo[tid]; lgs[tid]=lg[tid]; lbs[tid]=lb[tid]; }
    __syncthreads();

    if (tid < HB){
        float xr[9];
        #pragma unroll
        for (int d=0; d<9; d++) xr[d] = xs[tid*13+d];
        #pragma unroll
        for (int e=0; e<9; e++){
            float aq=0.f, ak=0.f, av=0.f;
            #pragma unroll
            for (int d=0; d<9; d++){
                aq = fmaf(xr[d], wqs[e*9+d], aq);
                ak = fmaf(xr[d], wks[e*9+d], ak);
                av = fmaf(xr[d], wvs[e*9+d], av);
            }
            qs[tid*13+e] = phif(aq);
            ks[tid*13+e] = phif(ak);
            vs[tid*13+e] = av;
        }
    }
    __syncthreads();

    if (tid < 81){
        int d = tid/9, e = tid%9;
        float acc = 0.f;
        for (int s=0; s<HB; s++) acc = fmaf(ks[s*13+d], vs[s*13+e], acc);
        kvs[tid] = acc;
    } else if (tid < 90){
        int e = tid - 81;
        float acc = 0.f;
        for (int s=0; s<HB; s++) acc += ks[s*13+e];
        ksum[e] = acc;
    }
    __syncthreads();

    if (tid < HB){
        float q[9], o[9];
        float den = 0.f;
        #pragma unroll
        for (int e=0; e<9; e++){ q[e] = qs[tid*13+e]; den = fmaf(q[e], ksum[e], den); }
        float inv = 1.0f / fmaxf(den, 1e-6f);
        #pragma unroll
        for (int e=0; e<9; e++){
            float num = 0.f;
            #pragma unroll
            for (int d=0; d<9; d++) num = fmaf(q[d], kvs[d*9+e], num);
            o[e] = num * inv;
        }
        float y[9]; float mu = 0.f;
        #pragma unroll
        for (int f=0; f<9; f++){
            float acc = bos[f] + o[f];
            #pragma unroll
            for (int e=0; e<9; e++) acc = fmaf(o[e], wos[f*9+e], acc);
            y[f] = acc; mu += acc;
        }
        mu *= (1.0f/9.0f);
        float var = 0.f;
        #pragma unroll
        for (int f=0; f<9; f++){ float dd = y[f]-mu; var = fmaf(dd, dd, var); }
        var *= (1.0f/9.0f);
        float rs = rsqrtf(var + 1e-5f);
        #pragma unroll
        for (int f=0; f<9; f++){
            g_buf1[(size_t)b*1080 + f*HB + tid] = (y[f]-mu)*rs*lgs[f] + lbs[f];
        }
    }
}

// ---------------------------------------------------------------- lin_attn_4 (S=1 collapsed)
__global__ __launch_bounds__(128) void k_attn4(
    const float* __restrict__ bo4, const float* __restrict__ lg4,
    const float* __restrict__ lb4)
{
    __shared__ __align__(16) float xsT[HB*20];
    __shared__ __align__(16) float vsT[HB*20];
    __shared__ float red1[4*16], red2[4*16];
    __shared__ float fac[16], mus[16], rss[16];
    int tid = threadIdx.x;
    int base = blockIdx.x * 16;

    for (int i = tid; i < 16*HB; i += 128){
        int r = i / HB, d = i - r*HB;
        xsT[d*20 + r] = g_buf1[(size_t)(base + r)*HB + d];
    }
    __syncthreads();

    bool valid = tid < HB;
    int e = valid ? tid : 0;
    const float* wqT = g_wT;
    const float* wkT = g_wT + HB*HB;
    const float* wvT = g_wT + 2*HB*HB;
    const float* woT = g_wT + 3*HB*HB;

    ull qa2[8], ka2[8], va2[8];
    #pragma unroll
    for (int r=0; r<8; r++){ qa2[r]=0ull; ka2[r]=0ull; va2[r]=0ull; }

    const ull* xp2 = (const ull*)xsT;
    #pragma unroll 2
    for (int d=0; d<HB; d++){
        ull wq2p = pack2(wqT[d*HB + e], wqT[d*HB + e]);
        ull wk2p = pack2(wkT[d*HB + e], wkT[d*HB + e]);
        ull wv2p = pack2(wvT[d*HB + e], wvT[d*HB + e]);
        #pragma unroll
        for (int r=0; r<8; r++){
            ull xv = xp2[d*10 + r];
            ffma2(qa2[r], wq2p, xv);
            ffma2(ka2[r], wk2p, xv);
            ffma2(va2[r], wv2p, xv);
        }
    }

    float qa[16], ka[16], va[16];
    #pragma unroll
    for (int r=0; r<8; r++){
        float2 q = unpack2(qa2[r]), k = unpack2(ka2[r]), v = unpack2(va2[r]);
        qa[2*r]=q.x; qa[2*r+1]=q.y;
        ka[2*r]=k.x; ka[2*r+1]=k.y;
        va[2*r]=v.x; va[2*r+1]=v.y;
    }

    float qk[16];
    #pragma unroll
    for (int r=0; r<16; r++) qk[r] = valid ? phif(qa[r])*phif(ka[r]) : 0.0f;

    if (valid){
        float4* vp4 = (float4*)&vsT[e*20];
        vp4[0] = make_float4(va[0],va[1],va[2],va[3]);
        vp4[1] = make_float4(va[4],va[5],va[6],va[7]);
        vp4[2] = make_float4(va[8],va[9],va[10],va[11]);
        vp4[3] = make_float4(va[12],va[13],va[14],va[15]);
    }

    #pragma unroll
    for (int off=16; off>0; off>>=1){
        #pragma unroll
        for (int r=0; r<16; r++) qk[r] += __shfl_down_sync(0xffffffffu, qk[r], off);
    }
    int w = tid >> 5, lane = tid & 31;
    if (lane == 0){
        #pragma unroll
        for (int r=0; r<16; r++) red1[w*16 + r] = qk[r];
    }
    __syncthreads();
    if (tid < 16){
        float s = red1[tid] + red1[16+tid] + red1[32+tid] + red1[48+tid];
        fac[tid] = s / fmaxf(s, 1e-6f);
    }
    __syncthreads();

    ull ma2[8];
    #pragma unroll
    for (int r=0; r<8; r++) ma2[r] = 0ull;
    const ull* vp2 = (const ull*)vsT;
    #pragma unroll 2
    for (int ee=0; ee<HB; ee++){
        ull wo2p = pack2(woT[ee*HB + e], woT[ee*HB + e]);
        #pragma unroll
        for (int r=0; r<8; r++) ffma2(ma2[r], wo2p, vp2[ee*10 + r]);
    }
    float ma[16];
    #pragma unroll
    for (int r=0; r<8; r++){
        float2 m = unpack2(ma2[r]);
        ma[2*r]=m.x; ma[2*r+1]=m.y;
    }

    float bov = bo4[e];
    float y[16], s1[16], s2[16];
    #pragma unroll
    for (int r=0; r<16; r++){
        y[r] = fmaf(fac[r], ma[r] + va[r], bov);
        s1[r] = valid ? y[r] : 0.f;
        s2[r] = valid ? y[r]*y[r] : 0.f;
    }
    #pragma unroll
    for (int off=16; off>0; off>>=1){
        #pragma unroll
        for (int r=0; r<16; r++){
            s1[r] += __shfl_down_sync(0xffffffffu, s1[r], off);
            s2[r] += __shfl_down_sync(0xffffffffu, s2[r], off);
        }
    }
    if (lane == 0){
        #pragma unroll
        for (int r=0; r<16; r++){ red1[w*16+r] = s1[r]; red2[w*16+r] = s2[r]; }
    }
    __syncthreads();
    if (tid < 16){
        float sy  = red1[tid]+red1[16+tid]+red1[32+tid]+red1[48+tid];
        float sy2 = red2[tid]+red2[16+tid]+red2[32+tid]+red2[48+tid];
        float mu = sy * (1.0f/120.0f);
        float var = sy2 * (1.0f/120.0f) - mu*mu;
        mus[tid] = mu;
        rss[tid] = rsqrtf(var + 1e-5f);
    }
    __syncthreads();
    if (valid){
        float lgv = lg4[e], lbv = lb4[e];
        #pragma unroll
        for (int r=0; r<16; r++){
            float yn = (y[r] - mus[r]) * rss[r];
            g_buf2[(size_t)(base + r)*HB + e] = yn*lgv + lbv;
        }
    }
}

// ---------------------------------------------------------------- CGLSTM (120 steps)
// One warp per SIX sequences; thread j owns hidden unit j of all six, sharing
// the register-resident weight rows. hbuf overlays the dead weight-staging
// SMEM (weights live in registers after the prologue) to stay under 48KB.
#define SEQW 6
#define SEQB (SEQW*8)   /* 48 seqs per block */
__global__ __launch_bounds__(256, 1) void k_cglstm(
    const float* __restrict__ w_ih, const float* __restrict__ w_hh,
    const float* __restrict__ b_ih, const float* __restrict__ b_hh,
    const float* __restrict__ cg_w, const float* __restrict__ cg_uw,
    const float* __restrict__ cg_ub,
    float* __restrict__ outh)
{
    // region A: weight staging (4352 floats = 17408B) -> later hbuf[2][48][32] (12288B)
    // region B: xsm (48*120 floats = 23040B)
    __shared__ __align__(16) char sraw[17408 + 23040];
    float* wstage = (float*)sraw;                 // [96*34] then [32*34]
    float* cgstage = wstage + 96*34;
    float* xsm = (float*)(sraw + 17408);          // [48][120]
    float (*hbuf)[SEQB][32] = (float (*)[SEQB][32])sraw;

    int tid = threadIdx.x, warp = tid >> 5, lane = tid & 31;

    for (int i = tid; i < 96*32; i += 256) wstage[(i>>5)*34 + (i&31)] = w_hh[i];
    for (int i = tid; i < 32*32; i += 256) cgstage[(i>>5)*34 + (i&31)] = cg_uw[i];
    for (int i = tid; i < SEQB*HB; i += 256) xsm[i] = g_buf2[(size_t)blockIdx.x*SEQB*HB + i];
    __syncthreads();

    // register-resident weight rows (packed along k) for hidden unit `lane`
    ull wi2[16], wf2[16], wg2[16], wc2[16];
    {
        const ull* ri = (const ull*)&wstage[lane*34];
        const ull* rf = (const ull*)&wstage[(32+lane)*34];
        const ull* rg = (const ull*)&wstage[(64+lane)*34];
        const ull* rc = (const ull*)&cgstage[lane*34];
        #pragma unroll
        for (int q = 0; q < 16; q++){
            wi2[q] = ri[q]; wf2[q] = rf[q]; wg2[q] = rg[q]; wc2[q] = rc[q];
        }
    }
    float wx_i = w_ih[lane], wx_f = w_ih[32+lane], wx_g = w_ih[64+lane];
    float bi = b_ih[lane] + b_hh[lane];
    float bf = b_ih[32+lane] + b_hh[32+lane];
    float bg = b_ih[64+lane] + b_hh[64+lane];
    float wx_c = cg_w[lane], bc = cg_ub[lane];

    __syncthreads();   // all weight reads done before hbuf overlays the region

    int s0 = SEQW*warp;
    #pragma unroll
    for (int s = 0; s < SEQW; s++) hbuf[0][s0+s][lane] = 0.0f;
    __syncwarp();      // each warp only touches its own rows

    float cS[SEQW], hnS[SEQW];
    #pragma unroll
    for (int s = 0; s < SEQW; s++){ cS[s]=0.f; hnS[s]=0.f; }
    int p = 0;

    for (int t = 0; t < HB; t++){
        ull Ai[SEQW], Af[SEQW], Ag[SEQW], Ac[SEQW];
        #pragma unroll
        for (int s = 0; s < SEQW; s++){
            float xv = xsm[(s0+s)*HB + t];
            Ai[s] = pack2(fmaf(xv, wx_i, bi), 0.0f);
            Af[s] = pack2(fmaf(xv, wx_f, bf), 0.0f);
            Ag[s] = pack2(fmaf(xv, wx_g, bg), 0.0f);
            Ac[s] = pack2(fmaf(xv, wx_c, bc), 0.0f);
        }

        #pragma unroll
        for (int q = 0; q < 8; q++){
            #pragma unroll
            for (int s = 0; s < SEQW; s++){
                ulonglong2 hh = ((const ulonglong2*)&hbuf[p][s0+s][0])[q];
                ffma2(Ai[s], wi2[2*q],   hh.x);
                ffma2(Ai[s], wi2[2*q+1], hh.y);
                ffma2(Af[s], wf2[2*q],   hh.x);
                ffma2(Af[s], wf2[2*q+1], hh.y);
                ffma2(Ag[s], wg2[2*q],   hh.x);
                ffma2(Ag[s], wg2[2*q+1], hh.y);
                ffma2(Ac[s], wc2[2*q],   hh.x);
                ffma2(Ac[s], wc2[2*q+1], hh.y);
            }
        }

        #pragma unroll
        for (int s = 0; s < SEQW; s++){
            float2 vi = unpack2(Ai[s]), vf = unpack2(Af[s]);
            float2 vg = unpack2(Ag[s]), vc = unpack2(Ac[s]);
            float ai = vi.x + vi.y, af = vf.x + vf.y;
            float ag = vg.x + vg.y, ac = vc.x + vc.y;
            float cn = sigt(af)*cS[s] + sigt(ai)*tanht(ag);
            cS[s] = cn;
            hnS[s] = sigt(ac)*tanht(cn);
            hbuf[1-p][s0+s][lane] = hnS[s];
        }
        __syncwarp();
        p ^= 1;
    }

    #pragma unroll
    for (int s = 0; s < SEQW; s++){
        int n = blockIdx.x*SEQB + s0 + s;
        outh[(size_t)n*32 + lane] = hnS[s];
    }
}

// ---------------------------------------------------------------- conv6/7 + permute + RevIN
__global__ __launch_bounds__(160) void k_head(
    const float* __restrict__ w6, const float* __restrict__ b6,
    const float* __restrict__ w7, const float* __restrict__ b7,
    const float* __restrict__ rev_w, const float* __restrict__ rev_b,
    const float* __restrict__ hin, float* __restrict__ enc)
{
    __shared__ float hs[288], w6s[60*32], w7s[15*60], b6s[60], b7s[15];
    __shared__ float t60s[9*60], t135[135];
    __shared__ float smu, sinv;
    __shared__ float part1[5], part2[5];
    int b = blockIdx.x, tid = threadIdx.x;

    for (int i = tid; i < 60*32; i += 160) w6s[i] = w6[i];
    for (int i = tid; i < 15*60; i += 160) w7s[i] = w7[i];
    if (tid < 60) b6s[tid] = b6[tid];
    if (tid < 15) b7s[tid] = b7[tid];
    for (int i = tid; i < 288; i += 160) hs[i] = hin[(size_t)b*288 + i];
    __syncthreads();

    for (int i = tid; i < 540; i += 160){
        int dd = i/60, u = i - dd*60;
        float acc = b6s[u];
        #pragma unroll 8
        for (int k=0; k<32; k++) acc = fmaf(w6s[u*32+k], hs[dd*32+k], acc);
        t60s[i] = fmaxf(acc, 0.0f) + log1pf(__expf(-fabsf(acc)));
    }
    __syncthreads();
    if (tid < 135){
        int dd = tid/15, f = tid - dd*15;
        float acc = b7s[f];
        #pragma unroll 6
        for (int u=0; u<60; u++) acc = fmaf(w7s[f*60+u], t60s[dd*60+u], acc);
        t135[tid] = tanhf(acc);
    }
    __syncthreads();
    float v  = (tid < 135) ? t135[tid] : 0.0f;
    float v2 = v*v;
    #pragma unroll
    for (int off=16; off>0; off>>=1){
        v  += __shfl_down_sync(0xffffffffu, v,  off);
        v2 += __shfl_down_sync(0xffffffffu, v2, off);
    }
    if ((tid & 31) == 0){ part1[tid>>5] = v; part2[tid>>5] = v2; }
    __syncthreads();
    if (tid == 0){
        float s1 = 0.f, s2 = 0.f;
        #pragma unroll
        for (int w=0; w<5; w++){ s1 += part1[w]; s2 += part2[w]; }
        float mu = s1 * (1.0f/135.0f);
        float var = fmaxf((s2 - 135.0f*mu*mu) * (1.0f/134.0f), 0.0f);
        float sd = fmaxf(sqrtf(var), 1e-5f);
        smu = mu; sinv = 1.0f/sd;
    }
    __syncthreads();
    if (tid < 135){
        int dp = tid/15, fp = tid - dp*15;
        float yv = t135[fp*9 + dp];       // transpose_8
        enc[(size_t)b*135 + tid] = (yv - smu)*sinv*rev_w[tid] + rev_b[tid];
    }
}

// ---------------------------------------------------------------- launch
extern "C" void kernel_launch(void* const* d_in, const int* in_sizes, int n_in,
                              void* d_out, int out_size)
{
    const float* x     = (const float*)d_in[0];
    const float* bn_g  = (const float*)d_in[1];
    const float* bn_b  = (const float*)d_in[2];
    const float* bn_m  = (const float*)d_in[3];
    const float* bn_v  = (const float*)d_in[4];
    const float* wq2   = (const float*)d_in[5];
    const float* wk2   = (const float*)d_in[6];
    const float* wv2   = (const float*)d_in[7];
    const float* wo2   = (const float*)d_in[8];
    const float* bo2   = (const float*)d_in[9];
    const float* ln2g  = (const float*)d_in[10];
    const float* ln2b  = (const float*)d_in[11];
    const float* wq4   = (const float*)d_in[12];
    const float* wk4   = (const float*)d_in[13];
    const float* wv4   = (const float*)d_in[14];
    const float* wo4   = (const float*)d_in[15];
    const float* bo4   = (const float*)d_in[16];
    const float* ln4g  = (const float*)d_in[17];
    const float* ln4b  = (const float*)d_in[18];
    const float* w_ih  = (const float*)d_in[19];
    const float* w_hh  = (const float*)d_in[20];
    const float* b_ih  = (const float*)d_in[21];
    const float* b_hh  = (const float*)d_in[22];
    const float* cg_w  = (const float*)d_in[23];
    const float* cg_uw = (const float*)d_in[24];
    const float* cg_ub = (const float*)d_in[25];
    const float* w6    = (const float*)d_in[26];
    const float* b6    = (const float*)d_in[27];
    const float* w7    = (const float*)d_in[28];
    const float* b7    = (const float*)d_in[29];
    const float* rev_w = (const float*)d_in[30];
    const float* rev_b = (const float*)d_in[31];
    float* out = (float*)d_out;

    k_transpose_w<<<(4*HB*HB + 255)/256, 256>>>(wq4, wk4, wv4, wo4);
    k_attn2<<<BATCH, 128>>>(x, bn_g, bn_b, bn_m, bn_v, wq2, wk2, wv2, wo2, bo2, ln2g, ln2b);
    k_attn4<<<NSEQ/16, 128>>>(bo4, ln4g, ln4b);
    k_cglstm<<<NSEQ/SEQB, 256>>>(w_ih, w_hh, b_ih, b_hh, cg_w, cg_uw, cg_ub, out);
    k_head<<<BATCH, 160>>>(w6, b6, w7, b7, rev_w, rev_b, out, out + (size_t)BATCH*288);
}

// round 7
// speedup vs baseline: 2.1567x; 1.0327x over previous
#include <cuda_runtime.h>

#define BATCH 16384
#define HB 120
#define BD 9
#define NSEQ (BATCH*BD)   /* 147456 */
#define NS 32
#define NF 15

// scratch (no cudaMalloc allowed)
__device__ float g_buf1[NSEQ*HB];      // attn2 output, transposed: [(b*9+d)*120 + s]
__device__ float g_buf2[NSEQ*HB];      // attn4 output: [n*120 + t]
__device__ float g_wT[4*HB*HB];        // transposed wq4,wk4,wv4,wo4

__device__ __forceinline__ float phif(float x){ return x>0.0f ? x+1.0f : __expf(x); }
// sigmoid from PRE-HALVED input: sig(2x) ... here a' = a/2 already: sig(a)=0.5*tanh(a/2)+0.5
__device__ __forceinline__ float sigp(float xh){
    float t;
    asm("tanh.approx.f32 %0, %1;" : "=f"(t) : "f"(xh));
    return fmaf(0.5f, t, 0.5f);
}
__device__ __forceinline__ float tanht(float x){
    float t;
    asm("tanh.approx.f32 %0, %1;" : "=f"(t) : "f"(x));
    return t;
}

typedef unsigned long long ull;
__device__ __forceinline__ ull pack2(float lo, float hi){
    ull r; asm("mov.b64 %0, {%1, %2};" : "=l"(r) : "f"(lo), "f"(hi)); return r;
}
__device__ __forceinline__ float2 unpack2(ull v){
    float2 f; asm("mov.b64 {%0, %1}, %2;" : "=f"(f.x), "=f"(f.y) : "l"(v)); return f;
}
__device__ __forceinline__ void ffma2(ull &d, ull a, ull b){
    asm("fma.rn.f32x2 %0, %1, %2, %0;" : "+l"(d) : "l"(a), "l"(b));
}

// ---------------------------------------------------------------- weights transpose
__global__ void k_transpose_w(const float* __restrict__ wq, const float* __restrict__ wk,
                              const float* __restrict__ wv, const float* __restrict__ wo){
    int idx = blockIdx.x*blockDim.x + threadIdx.x;
    if (idx >= 4*HB*HB) return;
    int m = idx/(HB*HB); int i = idx - m*(HB*HB);
    int a = i/HB, b = i - a*HB;
    const float* src = (m==0)?wq : (m==1)?wk : (m==2)?wv : wo;
    g_wT[idx] = src[b*HB + a];
}

// ---------------------------------------------------------------- BN + lin_attn_2 + transpose
__global__ __launch_bounds__(128) void k_attn2(
    const float* __restrict__ x,
    const float* __restrict__ bng, const float* __restrict__ bnb,
    const float* __restrict__ bnm, const float* __restrict__ bnv,
    const float* __restrict__ wq, const float* __restrict__ wk,
    const float* __restrict__ wv, const float* __restrict__ wo,
    const float* __restrict__ bo, const float* __restrict__ lg,
    const float* __restrict__ lb)
{
    __shared__ float xs[HB*13], qs[HB*13], ks[HB*13], vs[HB*13];
    __shared__ float wqs[81], wks[81], wvs[81], wos[81];
    __shared__ float kvs[81], ksum[9], bos[9], lgs[9], lbs[9];
    int b = blockIdx.x, tid = threadIdx.x;

    for (int i = tid; i < 1080; i += 128){
        float val = (x[(size_t)b*1080 + i] - bnm[i]) * rsqrtf(bnv[i] + 1e-5f) * bng[i] + bnb[i];
        xs[(i/9)*13 + (i%9)] = val;
    }
    if (tid < 81){ wqs[tid]=wq[tid]; wks[tid]=wk[tid]; wvs[tid]=wv[tid]; wos[tid]=wo[tid]; }
    if (tid < 9){ bos[tid]=bo[tid]; lgs[tid]=lg[tid]; lbs[tid]=lb[tid]; }
    __syncthreads();

    if (tid < HB){
        float xr[9];
        #pragma unroll
        for (int d=0; d<9; d++) xr[d] = xs[tid*13+d];
        #pragma unroll
        for (int e=0; e<9; e++){
            float aq=0.f, ak=0.f, av=0.f;
            #pragma unroll
            for (int d=0; d<9; d++){
                aq = fmaf(xr[d], wqs[e*9+d], aq);
                ak = fmaf(xr[d], wks[e*9+d], ak);
                av = fmaf(xr[d], wvs[e*9+d], av);
            }
            qs[tid*13+e] = phif(aq);
            ks[tid*13+e] = phif(ak);
            vs[tid*13+e] = av;
        }
    }
    __syncthreads();

    if (tid < 81){
        int d = tid/9, e = tid%9;
        float acc = 0.f;
        for (int s=0; s<HB; s++) acc = fmaf(ks[s*13+d], vs[s*13+e], acc);
        kvs[tid] = acc;
    } else if (tid < 90){
        int e = tid - 81;
        float acc = 0.f;
        for (int s=0; s<HB; s++) acc += ks[s*13+e];
        ksum[e] = acc;
    }
    __syncthreads();

    if (tid < HB){
        float q[9], o[9];
        float den = 0.f;
        #pragma unroll
        for (int e=0; e<9; e++){ q[e] = qs[tid*13+e]; den = fmaf(q[e], ksum[e], den); }
        float inv = 1.0f / fmaxf(den, 1e-6f);
        #pragma unroll
        for (int e=0; e<9; e++){
            float num = 0.f;
            #pragma unroll
            for (int d=0; d<9; d++) num = fmaf(q[d], kvs[d*9+e], num);
            o[e] = num * inv;
        }
        float y[9]; float mu = 0.f;
        #pragma unroll
        for (int f=0; f<9; f++){
            float acc = bos[f] + o[f];
            #pragma unroll
            for (int e=0; e<9; e++) acc = fmaf(o[e], wos[f*9+e], acc);
            y[f] = acc; mu += acc;
        }
        mu *= (1.0f/9.0f);
        float var = 0.f;
        #pragma unroll
        for (int f=0; f<9; f++){ float dd = y[f]-mu; var = fmaf(dd, dd, var); }
        var *= (1.0f/9.0f);
        float rs = rsqrtf(var + 1e-5f);
        #pragma unroll
        for (int f=0; f<9; f++){
            g_buf1[(size_t)b*1080 + f*HB + tid] = (y[f]-mu)*rs*lgs[f] + lbs[f];
        }
    }
}

// ---------------------------------------------------------------- lin_attn_4 (S=1 collapsed)
__global__ __launch_bounds__(128) void k_attn4(
    const float* __restrict__ bo4, const float* __restrict__ lg4,
    const float* __restrict__ lb4)
{
    __shared__ __align__(16) float xsT[HB*20];
    __shared__ __align__(16) float vsT[HB*20];
    __shared__ float red1[4*16], red2[4*16];
    __shared__ float fac[16], mus[16], rss[16];
    int tid = threadIdx.x;
    int base = blockIdx.x * 16;

    for (int i = tid; i < 16*HB; i += 128){
        int r = i / HB, d = i - r*HB;
        xsT[d*20 + r] = g_buf1[(size_t)(base + r)*HB + d];
    }
    __syncthreads();

    bool valid = tid < HB;
    int e = valid ? tid : 0;
    const float* wqT = g_wT;
    const float* wkT = g_wT + HB*HB;
    const float* wvT = g_wT + 2*HB*HB;
    const float* woT = g_wT + 3*HB*HB;

    ull qa2[8], ka2[8], va2[8];
    #pragma unroll
    for (int r=0; r<8; r++){ qa2[r]=0ull; ka2[r]=0ull; va2[r]=0ull; }

    const ulonglong2* xp2 = (const ulonglong2*)xsT;
    #pragma unroll 2
    for (int d=0; d<HB; d++){
        ull wq2p = pack2(wqT[d*HB + e], wqT[d*HB + e]);
        ull wk2p = pack2(wkT[d*HB + e], wkT[d*HB + e]);
        ull wv2p = pack2(wvT[d*HB + e], wvT[d*HB + e]);
        #pragma unroll
        for (int r=0; r<4; r++){
            ulonglong2 xv = xp2[d*5 + r];
            ffma2(qa2[2*r],   wq2p, xv.x);
            ffma2(qa2[2*r+1], wq2p, xv.y);
            ffma2(ka2[2*r],   wk2p, xv.x);
            ffma2(ka2[2*r+1], wk2p, xv.y);
            ffma2(va2[2*r],   wv2p, xv.x);
            ffma2(va2[2*r+1], wv2p, xv.y);
        }
    }

    float qa[16], ka[16], va[16];
    #pragma unroll
    for (int r=0; r<8; r++){
        float2 q = unpack2(qa2[r]), k = unpack2(ka2[r]), v = unpack2(va2[r]);
        qa[2*r]=q.x; qa[2*r+1]=q.y;
        ka[2*r]=k.x; ka[2*r+1]=k.y;
        va[2*r]=v.x; va[2*r+1]=v.y;
    }

    float qk[16];
    #pragma unroll
    for (int r=0; r<16; r++) qk[r] = valid ? phif(qa[r])*phif(ka[r]) : 0.0f;

    if (valid){
        float4* vp4 = (float4*)&vsT[e*20];
        vp4[0] = make_float4(va[0],va[1],va[2],va[3]);
        vp4[1] = make_float4(va[4],va[5],va[6],va[7]);
        vp4[2] = make_float4(va[8],va[9],va[10],va[11]);
        vp4[3] = make_float4(va[12],va[13],va[14],va[15]);
    }

    #pragma unroll
    for (int off=16; off>0; off>>=1){
        #pragma unroll
        for (int r=0; r<16; r++) qk[r] += __shfl_down_sync(0xffffffffu, qk[r], off);
    }
    int w = tid >> 5, lane = tid & 31;
    if (lane == 0){
        #pragma unroll
        for (int r=0; r<16; r++) red1[w*16 + r] = qk[r];
    }
    __syncthreads();
    if (tid < 16){
        float s = red1[tid] + red1[16+tid] + red1[32+tid] + red1[48+tid];
        fac[tid] = s / fmaxf(s, 1e-6f);
    }
    __syncthreads();

    ull ma2[8];
    #pragma unroll
    for (int r=0; r<8; r++) ma2[r] = 0ull;
    const ulonglong2* vp2 = (const ulonglong2*)vsT;
    #pragma unroll 2
    for (int ee=0; ee<HB; ee++){
        ull wo2p = pack2(woT[ee*HB + e], woT[ee*HB + e]);
        #pragma unroll
        for (int r=0; r<4; r++){
            ulonglong2 vv = vp2[ee*5 + r];
            ffma2(ma2[2*r],   wo2p, vv.x);
            ffma2(ma2[2*r+1], wo2p, vv.y);
        }
    }
    float ma[16];
    #pragma unroll
    for (int r=0; r<8; r++){
        float2 m = unpack2(ma2[r]);
        ma[2*r]=m.x; ma[2*r+1]=m.y;
    }

    float bov = bo4[e];
    float y[16], s1[16], s2[16];
    #pragma unroll
    for (int r=0; r<16; r++){
        y[r] = fmaf(fac[r], ma[r] + va[r], bov);
        s1[r] = valid ? y[r] : 0.f;
        s2[r] = valid ? y[r]*y[r] : 0.f;
    }
    #pragma unroll
    for (int off=16; off>0; off>>=1){
        #pragma unroll
        for (int r=0; r<16; r++){
            s1[r] += __shfl_down_sync(0xffffffffu, s1[r], off);
            s2[r] += __shfl_down_sync(0xffffffffu, s2[r], off);
        }
    }
    if (lane == 0){
        #pragma unroll
        for (int r=0; r<16; r++){ red1[w*16+r] = s1[r]; red2[w*16+r] = s2[r]; }
    }
    __syncthreads();
    if (tid < 16){
        float sy  = red1[tid]+red1[16+tid]+red1[32+tid]+red1[48+tid];
        float sy2 = red2[tid]+red2[16+tid]+red2[32+tid]+red2[48+tid];
        float mu = sy * (1.0f/120.0f);
        float var = sy2 * (1.0f/120.0f) - mu*mu;
        mus[tid] = mu;
        rss[tid] = rsqrtf(var + 1e-5f);
    }
    __syncthreads();
    if (valid){
        float lgv = lg4[e], lbv = lb4[e];
        #pragma unroll
        for (int r=0; r<16; r++){
            float yn = (y[r] - mus[r]) * rss[r];
            g_buf2[(size_t)(base + r)*HB + e] = yn*lgv + lbv;
        }
    }
}

// ---------------------------------------------------------------- CGLSTM (120 steps)
// One warp per SIX sequences; register-resident weights (FFMA2). Sigmoid-gate
// weights/biases pre-scaled by 0.5 (saves the FMUL in each sigmoid). Odd warps
// start ~512cyc late so the two warps per SMSP run anti-phase (FMA covers MUFU).
#define SEQW 6
#define SEQB (SEQW*8)   /* 48 seqs per block */
__global__ __launch_bounds__(256, 1) void k_cglstm(
    const float* __restrict__ w_ih, const float* __restrict__ w_hh,
    const float* __restrict__ b_ih, const float* __restrict__ b_hh,
    const float* __restrict__ cg_w, const float* __restrict__ cg_uw,
    const float* __restrict__ cg_ub,
    float* __restrict__ outh)
{
    // region A: weight staging (4352 floats = 17408B) -> later hbuf[2][48][32] (12288B)
    // region B: xsm transposed [t][seq] (48*120 floats = 23040B)
    __shared__ __align__(16) char sraw[17408 + 23040];
    float* wstage = (float*)sraw;                 // [96*34] then [32*34]
    float* cgstage = wstage + 96*34;
    float* xsm = (float*)(sraw + 17408);          // [120][48]
    float (*hbuf)[SEQB][32] = (float (*)[SEQB][32])sraw;

    int tid = threadIdx.x, warp = tid >> 5, lane = tid & 31;

    for (int i = tid; i < 96*32; i += 256){
        float v = w_hh[i];
        if (i < 64*32) v *= 0.5f;                 // i,f gate rows pre-halved
        wstage[(i>>5)*34 + (i&31)] = v;
    }
    for (int i = tid; i < 32*32; i += 256) cgstage[(i>>5)*34 + (i&31)] = cg_uw[i]*0.5f;
    for (int i = tid; i < SEQB*HB; i += 256){
        int seq = i / HB, t = i - seq*HB;
        xsm[t*SEQB + seq] = g_buf2[(size_t)blockIdx.x*SEQB*HB + i];
    }
    __syncthreads();

    // register-resident weight rows (packed along k) for hidden unit `lane`
    ull wi2[16], wf2[16], wg2[16], wc2[16];
    {
        const ull* ri = (const ull*)&wstage[lane*34];
        const ull* rf = (const ull*)&wstage[(32+lane)*34];
        const ull* rg = (const ull*)&wstage[(64+lane)*34];
        const ull* rc = (const ull*)&cgstage[lane*34];
        #pragma unroll
        for (int q = 0; q < 16; q++){
            wi2[q] = ri[q]; wf2[q] = rf[q]; wg2[q] = rg[q]; wc2[q] = rc[q];
        }
    }
    float wx_i = w_ih[lane]*0.5f, wx_f = w_ih[32+lane]*0.5f, wx_g = w_ih[64+lane];
    float bi = (b_ih[lane] + b_hh[lane])*0.5f;
    float bf = (b_ih[32+lane] + b_hh[32+lane])*0.5f;
    float bg = b_ih[64+lane] + b_hh[64+lane];
    float wx_c = cg_w[lane]*0.5f, bc = cg_ub[lane]*0.5f;

    __syncthreads();   // all weight reads done before hbuf overlays the region

    int s0 = SEQW*warp;
    #pragma unroll
    for (int s = 0; s < SEQW; s++) hbuf[0][s0+s][lane] = 0.0f;
    __syncwarp();      // each warp only touches its own rows

    // anti-phase stagger: odd warps start ~half a step late
    if (warp & 1){
        float z = bi + 1.5f;
        #pragma unroll
        for (int k = 0; k < 128; k++) z = fmaf(z, 1.0000001f, 1.0e-20f);
        asm volatile("" :: "f"(z));
    }

    float cS[SEQW], hnS[SEQW];
    #pragma unroll
    for (int s = 0; s < SEQW; s++){ cS[s]=0.f; hnS[s]=0.f; }
    int p = 0;

    for (int t = 0; t < HB; t++){
        float2 x01 = *(const float2*)&xsm[t*SEQB + s0];
        float2 x23 = *(const float2*)&xsm[t*SEQB + s0 + 2];
        float2 x45 = *(const float2*)&xsm[t*SEQB + s0 + 4];
        float xv[SEQW] = {x01.x, x01.y, x23.x, x23.y, x45.x, x45.y};

        ull Ai[SEQW], Af[SEQW], Ag[SEQW], Ac[SEQW];
        #pragma unroll
        for (int s = 0; s < SEQW; s++){
            Ai[s] = pack2(fmaf(xv[s], wx_i, bi), 0.0f);
            Af[s] = pack2(fmaf(xv[s], wx_f, bf), 0.0f);
            Ag[s] = pack2(fmaf(xv[s], wx_g, bg), 0.0f);
            Ac[s] = pack2(fmaf(xv[s], wx_c, bc), 0.0f);
        }

        #pragma unroll
        for (int q = 0; q < 8; q++){
            #pragma unroll
            for (int s = 0; s < SEQW; s++){
                ulonglong2 hh = ((const ulonglong2*)&hbuf[p][s0+s][0])[q];
                ffma2(Ai[s], wi2[2*q],   hh.x);
                ffma2(Ai[s], wi2[2*q+1], hh.y);
                ffma2(Af[s], wf2[2*q],   hh.x);
                ffma2(Af[s], wf2[2*q+1], hh.y);
                ffma2(Ag[s], wg2[2*q],   hh.x);
                ffma2(Ag[s], wg2[2*q+1], hh.y);
                ffma2(Ac[s], wc2[2*q],   hh.x);
                ffma2(Ac[s], wc2[2*q+1], hh.y);
            }
        }

        #pragma unroll
        for (int s = 0; s < SEQW; s++){
            float2 vi = unpack2(Ai[s]), vf = unpack2(Af[s]);
            float2 vg = unpack2(Ag[s]), vc = unpack2(Ac[s]);
            float ai = vi.x + vi.y, af = vf.x + vf.y;
            float ag = vg.x + vg.y, ac = vc.x + vc.y;
            float cn = sigp(af)*cS[s] + sigp(ai)*tanht(ag);
            cS[s] = cn;
            hnS[s] = sigp(ac)*tanht(cn);
            hbuf[1-p][s0+s][lane] = hnS[s];
        }
        __syncwarp();
        p ^= 1;
    }

    #pragma unroll
    for (int s = 0; s < SEQW; s++){
        int n = blockIdx.x*SEQB + s0 + s;
        outh[(size_t)n*32 + lane] = hnS[s];
    }
}

// ---------------------------------------------------------------- conv6/7 + permute + RevIN
__global__ __launch_bounds__(160) void k_head(
    const float* __restrict__ w6, const float* __restrict__ b6,
    const float* __restrict__ w7, const float* __restrict__ b7,
    const float* __restrict__ rev_w, const float* __restrict__ rev_b,
    const float* __restrict__ hin, float* __restrict__ enc)
{
    __shared__ float hs[288], w6s[60*32], w7s[15*60], b6s[60], b7s[15];
    __shared__ float t60s[9*60], t135[135];
    __shared__ float smu, sinv;
    __shared__ float part1[5], part2[5];
    int b = blockIdx.x, tid = threadIdx.x;

    for (int i = tid; i < 60*32; i += 160) w6s[i] = w6[i];
    for (int i = tid; i < 15*60; i += 160) w7s[i] = w7[i];
    if (tid < 60) b6s[tid] = b6[tid];
    if (tid < 15) b7s[tid] = b7[tid];
    for (int i = tid; i < 288; i += 160) hs[i] = hin[(size_t)b*288 + i];
    __syncthreads();

    for (int i = tid; i < 540; i += 160){
        int dd = i/60, u = i - dd*60;
        float acc = b6s[u];
        #pragma unroll 8
        for (int k=0; k<32; k++) acc = fmaf(w6s[u*32+k], hs[dd*32+k], acc);
        t60s[i] = fmaxf(acc, 0.0f) + log1pf(__expf(-fabsf(acc)));
    }
    __syncthreads();
    if (tid < 135){
        int dd = tid/15, f = tid - dd*15;
        float acc = b7s[f];
        #pragma unroll 6
        for (int u=0; u<60; u++) acc = fmaf(w7s[f*60+u], t60s[dd*60+u], acc);
        t135[tid] = tanhf(acc);
    }
    __syncthreads();
    float v  = (tid < 135) ? t135[tid] : 0.0f;
    float v2 = v*v;
    #pragma unroll
    for (int off=16; off>0; off>>=1){
        v  += __shfl_down_sync(0xffffffffu, v,  off);
        v2 += __shfl_down_sync(0xffffffffu, v2, off);
    }
    if ((tid & 31) == 0){ part1[tid>>5] = v; part2[tid>>5] = v2; }
    __syncthreads();
    if (tid == 0){
        float s1 = 0.f, s2 = 0.f;
        #pragma unroll
        for (int w=0; w<5; w++){ s1 += part1[w]; s2 += part2[w]; }
        float mu = s1 * (1.0f/135.0f);
        float var = fmaxf((s2 - 135.0f*mu*mu) * (1.0f/134.0f), 0.0f);
        float sd = fmaxf(sqrtf(var), 1e-5f);
        smu = mu; sinv = 1.0f/sd;
    }
    __syncthreads();
    if (tid < 135){
        int dp = tid/15, fp = tid - dp*15;
        float yv = t135[fp*9 + dp];       // transpose_8
        enc[(size_t)b*135 + tid] = (yv - smu)*sinv*rev_w[tid] + rev_b[tid];
    }
}

// ---------------------------------------------------------------- launch
extern "C" void kernel_launch(void* const* d_in, const int* in_sizes, int n_in,
                              void* d_out, int out_size)
{
    const float* x     = (const float*)d_in[0];
    const float* bn_g  = (const float*)d_in[1];
    const float* bn_b  = (const float*)d_in[2];
    const float* bn_m  = (const float*)d_in[3];
    const float* bn_v  = (const float*)d_in[4];
    const float* wq2   = (const float*)d_in[5];
    const float* wk2   = (const float*)d_in[6];
    const float* wv2   = (const float*)d_in[7];
    const float* wo2   = (const float*)d_in[8];
    const float* bo2   = (const float*)d_in[9];
    const float* ln2g  = (const float*)d_in[10];
    const float* ln2b  = (const float*)d_in[11];
    const float* wq4   = (const float*)d_in[12];
    const float* wk4   = (const float*)d_in[13];
    const float* wv4   = (const float*)d_in[14];
    const float* wo4   = (const float*)d_in[15];
    const float* bo4   = (const float*)d_in[16];
    const float* ln4g  = (const float*)d_in[17];
    const float* ln4b  = (const float*)d_in[18];
    const float* w_ih  = (const float*)d_in[19];
    const float* w_hh  = (const float*)d_in[20];
    const float* b_ih  = (const float*)d_in[21];
    const float* b_hh  = (const float*)d_in[22];
    const float* cg_w  = (const float*)d_in[23];
    const float* cg_uw = (const float*)d_in[24];
    const float* cg_ub = (const float*)d_in[25];
    const float* w6    = (const float*)d_in[26];
    const float* b6    = (const float*)d_in[27];
    const float* w7    = (const float*)d_in[28];
    const float* b7    = (const float*)d_in[29];
    const float* rev_w = (const float*)d_in[30];
    const float* rev_b = (const float*)d_in[31];
    float* out = (float*)d_out;

    k_transpose_w<<<(4*HB*HB + 255)/256, 256>>>(wq4, wk4, wv4, wo4);
    k_attn2<<<BATCH, 128>>>(x, bn_g, bn_b, bn_m, bn_v, wq2, wk2, wv2, wo2, bo2, ln2g, ln2b);
    k_attn4<<<NSEQ/16, 128>>>(bo4, ln4g, ln4b);
    k_cglstm<<<NSEQ/SEQB, 256>>>(w_ih, w_hh, b_ih, b_hh, cg_w, cg_uw, cg_ub, out);
    k_head<<<BATCH, 160>>>(w6, b6, w7, b7, rev_w, rev_b, out, out + (size_t)BATCH*288);
}

// round 9
// speedup vs baseline: 3.1142x; 1.4440x over previous
#include <cuda_runtime.h>
#include <cuda_bf16.h>
#include <cstdint>

#define BATCH 16384
#define HB 120
#define BD 9
#define NSEQ (BATCH*BD)   /* 147456 */
#define NS 32
#define NF 15

// scratch (no cudaMalloc allowed)
__device__ float g_buf1[NSEQ*HB];      // attn2 output, transposed: [(b*9+d)*120 + s]
__device__ float g_xT[HB*NSEQ];        // attn4 output, time-major: [t*NSEQ + n]
__device__ float g_wT[4*HB*HB];        // transposed wq4,wk4,wv4,wo4

__device__ __forceinline__ float phif(float x){ return x>0.0f ? x+1.0f : __expf(x); }
// sigmoid from PRE-HALVED pre-activation a' = a/2:  sig(a)=0.5*tanh(a/2)+0.5
__device__ __forceinline__ float sigp(float xh){
    float t;
    asm("tanh.approx.f32 %0, %1;" : "=f"(t) : "f"(xh));
    return fmaf(0.5f, t, 0.5f);
}
__device__ __forceinline__ float tanht(float x){
    float t;
    asm("tanh.approx.f32 %0, %1;" : "=f"(t) : "f"(x));
    return t;
}

typedef unsigned long long ull;
__device__ __forceinline__ ull pack2(float lo, float hi){
    ull r; asm("mov.b64 %0, {%1, %2};" : "=l"(r) : "f"(lo), "f"(hi)); return r;
}
__device__ __forceinline__ float2 unpack2(ull v){
    float2 f; asm("mov.b64 {%0, %1}, %2;" : "=f"(f.x), "=f"(f.y) : "l"(v)); return f;
}
__device__ __forceinline__ void ffma2(ull &d, ull a, ull b){
    asm("fma.rn.f32x2 %0, %1, %2, %0;" : "+l"(d) : "l"(a), "l"(b));
}

// warp-level bf16 MMA (generic PTX, sm_80+; compiles for plain compute_103)
__device__ __forceinline__ void mma16816(float* d, const uint32_t* a, const uint32_t* b, const float* c){
    asm volatile(
        "mma.sync.aligned.m16n8k16.row.col.f32.bf16.bf16.f32 "
        "{%0,%1,%2,%3}, {%4,%5,%6,%7}, {%8,%9}, {%10,%11,%12,%13};"
        : "=f"(d[0]), "=f"(d[1]), "=f"(d[2]), "=f"(d[3])
        : "r"(a[0]), "r"(a[1]), "r"(a[2]), "r"(a[3]),
          "r"(b[0]), "r"(b[1]),
          "f"(c[0]), "f"(c[1]), "f"(c[2]), "f"(c[3]));
}

// ---------------------------------------------------------------- weights transpose
__global__ void k_transpose_w(const float* __restrict__ wq, const float* __restrict__ wk,
                              const float* __restrict__ wv, const float* __restrict__ wo){
    int idx = blockIdx.x*blockDim.x + threadIdx.x;
    if (idx >= 4*HB*HB) return;
    int m = idx/(HB*HB); int i = idx - m*(HB*HB);
    int a = i/HB, b = i - a*HB;
    const float* src = (m==0)?wq : (m==1)?wk : (m==2)?wv : wo;
    g_wT[idx] = src[b*HB + a];
}

// ---------------------------------------------------------------- BN + lin_attn_2 + transpose
__global__ __launch_bounds__(128) void k_attn2(
    const float* __restrict__ x,
    const float* __restrict__ bng, const float* __restrict__ bnb,
    const float* __restrict__ bnm, const float* __restrict__ bnv,
    const float* __restrict__ wq, const float* __restrict__ wk,
    const float* __restrict__ wv, const float* __restrict__ wo,
    const float* __restrict__ bo, const float* __restrict__ lg,
    const float* __restrict__ lb)
{
    __shared__ float xs[HB*13], qs[HB*13], ks[HB*13], vs[HB*13];
    __shared__ float wqs[81], wks[81], wvs[81], wos[81];
    __shared__ float kvs[81], ksum[9], bos[9], lgs[9], lbs[9];
    int b = blockIdx.x, tid = threadIdx.x;

    for (int i = tid; i < 1080; i += 128){
        float val = (x[(size_t)b*1080 + i] - bnm[i]) * rsqrtf(bnv[i] + 1e-5f) * bng[i] + bnb[i];
        xs[(i/9)*13 + (i%9)] = val;
    }
    if (tid < 81){ wqs[tid]=wq[tid]; wks[tid]=wk[tid]; wvs[tid]=wv[tid]; wos[tid]=wo[tid]; }
    if (tid < 9){ bos[tid]=bo[tid]; lgs[tid]=lg[tid]; lbs[tid]=lb[tid]; }
    __syncthreads();

    if (tid < HB){
        float xr[9];
        #pragma unroll
        for (int d=0; d<9; d++) xr[d] = xs[tid*13+d];
        #pragma unroll
        for (int e=0; e<9; e++){
            float aq=0.f, ak=0.f, av=0.f;
            #pragma unroll
            for (int d=0; d<9; d++){
                aq = fmaf(xr[d], wqs[e*9+d], aq);
                ak = fmaf(xr[d], wks[e*9+d], ak);
                av = fmaf(xr[d], wvs[e*9+d], av);
            }
            qs[tid*13+e] = phif(aq);
            ks[tid*13+e] = phif(ak);
            vs[tid*13+e] = av;
        }
    }
    __syncthreads();

    if (tid < 81){
        int d = tid/9, e = tid%9;
        float acc = 0.f;
        for (int s=0; s<HB; s++) acc = fmaf(ks[s*13+d], vs[s*13+e], acc);
        kvs[tid] = acc;
    } else if (tid < 90){
        int e = tid - 81;
        float acc = 0.f;
        for (int s=0; s<HB; s++) acc += ks[s*13+e];
        ksum[e] = acc;
    }
    __syncthreads();

    if (tid < HB){
        float q[9], o[9];
        float den = 0.f;
        #pragma unroll
        for (int e=0; e<9; e++){ q[e] = qs[tid*13+e]; den = fmaf(q[e], ksum[e], den); }
        float inv = 1.0f / fmaxf(den, 1e-6f);
        #pragma unroll
        for (int e=0; e<9; e++){
            float num = 0.f;
            #pragma unroll
            for (int d=0; d<9; d++) num = fmaf(q[d], kvs[d*9+e], num);
            o[e] = num * inv;
        }
        float y[9]; float mu = 0.f;
        #pragma unroll
        for (int f=0; f<9; f++){
            float acc = bos[f] + o[f];
            #pragma unroll
            for (int e=0; e<9; e++) acc = fmaf(o[e], wos[f*9+e], acc);
            y[f] = acc; mu += acc;
        }
        mu *= (1.0f/9.0f);
        float var = 0.f;
        #pragma unroll
        for (int f=0; f<9; f++){ float dd = y[f]-mu; var = fmaf(dd, dd, var); }
        var *= (1.0f/9.0f);
        float rs = rsqrtf(var + 1e-5f);
        #pragma unroll
        for (int f=0; f<9; f++){
            g_buf1[(size_t)b*1080 + f*HB + tid] = (y[f]-mu)*rs*lgs[f] + lbs[f];
        }
    }
}

// ---------------------------------------------------------------- lin_attn_4 (S=1 collapsed)
__global__ __launch_bounds__(128) void k_attn4(
    const float* __restrict__ bo4, const float* __restrict__ lg4,
    const float* __restrict__ lb4)
{
    __shared__ __align__(16) float xsT[HB*20];
    __shared__ __align__(16) float vsT[HB*20];
    __shared__ float red1[4*16], red2[4*16];
    __shared__ float fac[16], mus[16], rss[16];
    int tid = threadIdx.x;
    int base = blockIdx.x * 16;

    for (int i = tid; i < 16*HB; i += 128){
        int r = i / HB, d = i - r*HB;
        xsT[d*20 + r] = g_buf1[(size_t)(base + r)*HB + d];
    }
    __syncthreads();

    bool valid = tid < HB;
    int e = valid ? tid : 0;
    const float* wqT = g_wT;
    const float* wkT = g_wT + HB*HB;
    const float* wvT = g_wT + 2*HB*HB;
    const float* woT = g_wT + 3*HB*HB;

    ull qa2[8], ka2[8], va2[8];
    #pragma unroll
    for (int r=0; r<8; r++){ qa2[r]=0ull; ka2[r]=0ull; va2[r]=0ull; }

    const ulonglong2* xp2 = (const ulonglong2*)xsT;
    #pragma unroll 2
    for (int d=0; d<HB; d++){
        ull wq2p = pack2(wqT[d*HB + e], wqT[d*HB + e]);
        ull wk2p = pack2(wkT[d*HB + e], wkT[d*HB + e]);
        ull wv2p = pack2(wvT[d*HB + e], wvT[d*HB + e]);
        #pragma unroll
        for (int r=0; r<4; r++){
            ulonglong2 xv = xp2[d*5 + r];
            ffma2(qa2[2*r],   wq2p, xv.x);
            ffma2(qa2[2*r+1], wq2p, xv.y);
            ffma2(ka2[2*r],   wk2p, xv.x);
            ffma2(ka2[2*r+1], wk2p, xv.y);
            ffma2(va2[2*r],   wv2p, xv.x);
            ffma2(va2[2*r+1], wv2p, xv.y);
        }
    }

    float qa[16], ka[16], va[16];
    #pragma unroll
    for (int r=0; r<8; r++){
        float2 q = unpack2(qa2[r]), k = unpack2(ka2[r]), v = unpack2(va2[r]);
        qa[2*r]=q.x; qa[2*r+1]=q.y;
        ka[2*r]=k.x; ka[2*r+1]=k.y;
        va[2*r]=v.x; va[2*r+1]=v.y;
    }

    float qk[16];
    #pragma unroll
    for (int r=0; r<16; r++) qk[r] = valid ? phif(qa[r])*phif(ka[r]) : 0.0f;

    if (valid){
        float4* vp4 = (float4*)&vsT[e*20];
        vp4[0] = make_float4(va[0],va[1],va[2],va[3]);
        vp4[1] = make_float4(va[4],va[5],va[6],va[7]);
        vp4[2] = make_float4(va[8],va[9],va[10],va[11]);
        vp4[3] = make_float4(va[12],va[13],va[14],va[15]);
    }

    #pragma unroll
    for (int off=16; off>0; off>>=1){
        #pragma unroll
        for (int r=0; r<16; r++) qk[r] += __shfl_down_sync(0xffffffffu, qk[r], off);
    }
    int w = tid >> 5, lane = tid & 31;
    if (lane == 0){
        #pragma unroll
        for (int r=0; r<16; r++) red1[w*16 + r] = qk[r];
    }
    __syncthreads();
    if (tid < 16){
        float s = red1[tid] + red1[16+tid] + red1[32+tid] + red1[48+tid];
        fac[tid] = s / fmaxf(s, 1e-6f);
    }
    __syncthreads();

    ull ma2[8];
    #pragma unroll
    for (int r=0; r<8; r++) ma2[r] = 0ull;
    const ulonglong2* vp2 = (const ulonglong2*)vsT;
    #pragma unroll 2
    for (int ee=0; ee<HB; ee++){
        ull wo2p = pack2(woT[ee*HB + e], woT[ee*HB + e]);
        #pragma unroll
        for (int r=0; r<4; r++){
            ulonglong2 vv = vp2[ee*5 + r];
            ffma2(ma2[2*r],   wo2p, vv.x);
            ffma2(ma2[2*r+1], wo2p, vv.y);
        }
    }
    float ma[16];
    #pragma unroll
    for (int r=0; r<8; r++){
        float2 m = unpack2(ma2[r]);
        ma[2*r]=m.x; ma[2*r+1]=m.y;
    }

    float bov = bo4[e];
    float y[16], s1[16], s2[16];
    #pragma unroll
    for (int r=0; r<16; r++){
        y[r] = fmaf(fac[r], ma[r] + va[r], bov);
        s1[r] = valid ? y[r] : 0.f;
        s2[r] = valid ? y[r]*y[r] : 0.f;
    }
    #pragma unroll
    for (int off=16; off>0; off>>=1){
        #pragma unroll
        for (int r=0; r<16; r++){
            s1[r] += __shfl_down_sync(0xffffffffu, s1[r], off);
            s2[r] += __shfl_down_sync(0xffffffffu, s2[r], off);
        }
    }
    if (lane == 0){
        #pragma unroll
        for (int r=0; r<16; r++){ red1[w*16+r] = s1[r]; red2[w*16+r] = s2[r]; }
    }
    __syncthreads();
    if (tid < 16){
        float sy  = red1[tid]+red1[16+tid]+red1[32+tid]+red1[48+tid];
        float sy2 = red2[tid]+red2[16+tid]+red2[32+tid]+red2[48+tid];
        float mu = sy * (1.0f/120.0f);
        float var = sy2 * (1.0f/120.0f) - mu*mu;
        mus[tid] = mu;
        rss[tid] = rsqrtf(var + 1e-5f);
    }
    __syncthreads();
    if (valid){
        float lgv = lg4[e], lbv = lb4[e];
        #pragma unroll
        for (int r=0; r<16; r++){
            float yn = (y[r] - mus[r]) * rss[r];
            g_xT[(size_t)e*NSEQ + base + r] = yn*lgv + lbv;   // time-major for LSTM
        }
    }
}

// ---------------------------------------------------------------- CGLSTM via warp-MMA (bf16 hi/lo)
// CTA = 128 threads, 64 sequences. D[128 gate-rows x 64 seqs] per step.
// A = W' (register-resident fragments: Wh0,Wh1,Wl0,Wl1,Wx; sigmoid rows pre-halved x0.5).
// B = state S[64 seqs][80 k] bf16 in SMEM: k 0-31 h_hi, 32-63 h_lo, 64 x_hi, 65 x_lo,
//     66 x_hi, 67/68 = 1.0 (bias hi/lo), 69-79 = 0.  Row stride 120 u16 (conflict-free).
// Gate rows: gate*32 + unit (i|f|g|cg). Warp = (unit-half uh, seq-half sh): all 4 gates
// of a (unit,seq) land in one thread -> c-state in registers.
__global__ __launch_bounds__(128, 2) void k_cglstm_mma(
    const float* __restrict__ w_ih, const float* __restrict__ w_hh,
    const float* __restrict__ b_ih, const float* __restrict__ b_hh,
    const float* __restrict__ cg_w, const float* __restrict__ cg_uw,
    const float* __restrict__ cg_ub,
    float* __restrict__ outh)
{
    __shared__ __align__(16) unsigned short sm16[128*80];   // W' staging, later S overlay
    uint32_t* sm32 = (uint32_t*)sm16;

    int tid = threadIdx.x;
    int warp = tid >> 5, lane = tid & 31;
    int g = lane >> 2, tg = lane & 3;
    int uh = warp & 1, sh = warp >> 1;

    // ---- build W' bf16 [128 rows][80 cols]
    for (int idx = tid; idx < 128*80; idx += 128){
        int r = idx / 80, cc = idx - r*80;
        int gate = r >> 5, j = r & 31;
        float scale = (gate == 2) ? 1.0f : 0.5f;
        float v = 0.0f;
        if (cc < 64){
            int k = cc & 31;
            float w = (gate==0) ? w_hh[j*32+k] : (gate==1) ? w_hh[(32+j)*32+k]
                    : (gate==2) ? w_hh[(64+j)*32+k] : cg_uw[j*32+k];
            w *= scale;
            float whi = __bfloat162float(__float2bfloat16(w));
            v = (cc < 32) ? whi : (w - whi);
        } else if (cc < 67){
            float wx = (gate==0) ? w_ih[j] : (gate==1) ? w_ih[32+j]
                     : (gate==2) ? w_ih[64+j] : cg_w[j];
            wx *= scale;
            float wxhi = __bfloat162float(__float2bfloat16(wx));
            v = (cc == 66) ? (wx - wxhi) : wxhi;
        } else if (cc < 69){
            float bb = (gate==0) ? b_ih[j]+b_hh[j] : (gate==1) ? b_ih[32+j]+b_hh[32+j]
                     : (gate==2) ? b_ih[64+j]+b_hh[64+j] : cg_ub[j];
            bb *= scale;
            float bhi = __bfloat162float(__float2bfloat16(bb));
            v = (cc == 67) ? bhi : (bb - bhi);
        }
        sm16[idx] = __bfloat16_as_ushort(__float2bfloat16(v));
    }
    __syncthreads();

    // ---- register-resident A fragments: [frag-group][gate m-tile][4]
    uint32_t afr[5][4][4];
    const int cb2[5] = {0, 8, 16, 24, 32};   // col-base/2 (u32 units): Wh0,Wh1,Wl0,Wl1,Wx
    #pragma unroll
    for (int fg = 0; fg < 5; fg++){
        #pragma unroll
        for (int mt = 0; mt < 4; mt++){
            int Rb = mt*32 + uh*16;
            afr[fg][mt][0] = sm32[(Rb+g)*40   + cb2[fg] + tg];
            afr[fg][mt][1] = sm32[(Rb+g+8)*40 + cb2[fg] + tg];
            afr[fg][mt][2] = sm32[(Rb+g)*40   + cb2[fg] + tg + 4];
            afr[fg][mt][3] = sm32[(Rb+g+8)*40 + cb2[fg] + tg + 4];
        }
    }
    __syncthreads();   // W' reads done — overlay S

    // ---- init S: zero 64 rows x 120 u16, then bias-ones
    for (int i = tid; i < 3840; i += 128) sm32[i] = 0u;
    __syncthreads();
    if (tid < 64){
        sm16[tid*120 + 67] = 0x3F80;   // 1.0 bf16 (bias hi row)
        sm16[tid*120 + 68] = 0x3F80;   // 1.0 bf16 (bias lo row)
    }

    int base = blockIdx.x * 64;
    float xv = 0.0f;
    if (tid < 64) xv = g_xT[base + tid];
    __syncthreads();

    float c[16], hn[16];
    #pragma unroll
    for (int i = 0; i < 16; i++){ c[i] = 0.f; hn[i] = 0.f; }
    const float z4[4] = {0.f, 0.f, 0.f, 0.f};

    for (int t = 0; t < HB; t++){
        // stage x (hi/lo + dup) for this step
        if (tid < 64){
            __nv_bfloat16 xh = __float2bfloat16(xv);
            __nv_bfloat16 xl = __float2bfloat16(xv - __bfloat162float(xh));
            uint32_t p = (uint32_t)__bfloat16_as_ushort(xh) | ((uint32_t)__bfloat16_as_ushort(xl) << 16);
            sm32[tid*60 + 32] = p;                               // cols 64,65
            sm16[tid*120 + 66] = __bfloat16_as_ushort(xh);       // col 66
        }
        __syncthreads();   // h stores (prev iter) + x visible to all B loads
        if (t + 1 < HB && tid < 64) xv = g_xT[(size_t)(t+1)*NSEQ + base + tid];

        float acc[4][4][4];   // [gate m-tile][n-tile][4]
        #pragma unroll
        for (int nt = 0; nt < 4; nt++){
            int rn = sh*32 + nt*8 + g;
            const uint32_t* Srow = &sm32[rn*60];
            uint32_t b[5][2];
            #pragma unroll
            for (int kt = 0; kt < 5; kt++){
                b[kt][0] = Srow[kt*8 + tg];
                b[kt][1] = Srow[kt*8 + tg + 4];
            }
            #pragma unroll
            for (int mt = 0; mt < 4; mt++){
                mma16816(acc[mt][nt], afr[0][mt], b[0], z4);          // Wh0 * h_hi0
                mma16816(acc[mt][nt], afr[1][mt], b[1], acc[mt][nt]); // Wh1 * h_hi1
                mma16816(acc[mt][nt], afr[0][mt], b[2], acc[mt][nt]); // Wh0 * h_lo0
                mma16816(acc[mt][nt], afr[1][mt], b[3], acc[mt][nt]); // Wh1 * h_lo1
                mma16816(acc[mt][nt], afr[2][mt], b[0], acc[mt][nt]); // Wl0 * h_hi0
                mma16816(acc[mt][nt], afr[3][mt], b[1], acc[mt][nt]); // Wl1 * h_hi1
                mma16816(acc[mt][nt], afr[4][mt], b[4], acc[mt][nt]); // Wx * x-block
            }
        }
        __syncthreads();   // all B reads done before h stores below

        // ---- epilogue: activations + c update + h hi/lo store
        #pragma unroll
        for (int nt = 0; nt < 4; nt++){
            #pragma unroll
            for (int j = 0; j < 4; j++){
                float gi = acc[0][nt][j], gf = acc[1][nt][j];
                float gg = acc[2][nt][j], gc = acc[3][nt][j];
                int ci = nt*4 + j;
                float cn = sigp(gf)*c[ci] + sigp(gi)*tanht(gg);
                c[ci] = cn;
                float h = sigp(gc)*tanht(cn);
                hn[ci] = h;
                int u = uh*16 + g + ((j >> 1) << 3);
                int srow = sh*32 + nt*8 + 2*tg + (j & 1);
                __nv_bfloat16 hh = __float2bfloat16(h);
                __nv_bfloat16 hl = __float2bfloat16(h - __bfloat162float(hh));
                sm16[srow*120 + u]      = __bfloat16_as_ushort(hh);
                sm16[srow*120 + 32 + u] = __bfloat16_as_ushort(hl);
            }
        }
    }

    // ---- write final h
    #pragma unroll
    for (int nt = 0; nt < 4; nt++){
        #pragma unroll
        for (int j = 0; j < 4; j++){
            int u = uh*16 + g + ((j >> 1) << 3);
            int srow = sh*32 + nt*8 + 2*tg + (j & 1);
            outh[(size_t)(base + srow)*32 + u] = hn[nt*4 + j];
        }
    }
}

// ---------------------------------------------------------------- conv6/7 + permute + RevIN
__global__ __launch_bounds__(160) void k_head(
    const float* __restrict__ w6, const float* __restrict__ b6,
    const float* __restrict__ w7, const float* __restrict__ b7,
    const float* __restrict__ rev_w, const float* __restrict__ rev_b,
    const float* __restrict__ hin, float* __restrict__ enc)
{
    __shared__ float hs[288], w6s[60*32], w7s[15*60], b6s[60], b7s[15];
    __shared__ float t60s[9*60], t135[135];
    __shared__ float smu, sinv;
    __shared__ float part1[5], part2[5];
    int b = blockIdx.x, tid = threadIdx.x;

    for (int i = tid; i < 60*32; i += 160) w6s[i] = w6[i];
    for (int i = tid; i < 15*60; i += 160) w7s[i] = w7[i];
    if (tid < 60) b6s[tid] = b6[tid];
    if (tid < 15) b7s[tid] = b7[tid];
    for (int i = tid; i < 288; i += 160) hs[i] = hin[(size_t)b*288 + i];
    __syncthreads();

    for (int i = tid; i < 540; i += 160){
        int dd = i/60, u = i - dd*60;
        float acc = b6s[u];
        #pragma unroll 8
        for (int k=0; k<32; k++) acc = fmaf(w6s[u*32+k], hs[dd*32+k], acc);
        t60s[i] = fmaxf(acc, 0.0f) + log1pf(__expf(-fabsf(acc)));
    }
    __syncthreads();
    if (tid < 135){
        int dd = tid/15, f = tid - dd*15;
        float acc = b7s[f];
        #pragma unroll 6
        for (int u=0; u<60; u++) acc = fmaf(w7s[f*60+u], t60s[dd*60+u], acc);
        t135[tid] = tanhf(acc);
    }
    __syncthreads();
    float v  = (tid < 135) ? t135[tid] : 0.0f;
    float v2 = v*v;
    #pragma unroll
    for (int off=16; off>0; off>>=1){
        v  += __shfl_down_sync(0xffffffffu, v,  off);
        v2 += __shfl_down_sync(0xffffffffu, v2, off);
    }
    if ((tid & 31) == 0){ part1[tid>>5] = v; part2[tid>>5] = v2; }
    __syncthreads();
    if (tid == 0){
        float s1 = 0.f, s2 = 0.f;
        #pragma unroll
        for (int w=0; w<5; w++){ s1 += part1[w]; s2 += part2[w]; }
        float mu = s1 * (1.0f/135.0f);
        float var = fmaxf((s2 - 135.0f*mu*mu) * (1.0f/134.0f), 0.0f);
        float sd = fmaxf(sqrtf(var), 1e-5f);
        smu = mu; sinv = 1.0f/sd;
    }
    __syncthreads();
    if (tid < 135){
        int dp = tid/15, fp = tid - dp*15;
        float yv = t135[fp*9 + dp];       // transpose_8
        enc[(size_t)b*135 + tid] = (yv - smu)*sinv*rev_w[tid] + rev_b[tid];
    }
}

// ---------------------------------------------------------------- launch
extern "C" void kernel_launch(void* const* d_in, const int* in_sizes, int n_in,
                              void* d_out, int out_size)
{
    const float* x     = (const float*)d_in[0];
    const float* bn_g  = (const float*)d_in[1];
    const float* bn_b  = (const float*)d_in[2];
    const float* bn_m  = (const float*)d_in[3];
    const float* bn_v  = (const float*)d_in[4];
    const float* wq2   = (const float*)d_in[5];
    const float* wk2   = (const float*)d_in[6];
    const float* wv2   = (const float*)d_in[7];
    const float* wo2   = (const float*)d_in[8];
    const float* bo2   = (const float*)d_in[9];
    const float* ln2g  = (const float*)d_in[10];
    const float* ln2b  = (const float*)d_in[11];
    const float* wq4   = (const float*)d_in[12];
    const float* wk4   = (const float*)d_in[13];
    const float* wv4   = (const float*)d_in[14];
    const float* wo4   = (const float*)d_in[15];
    const float* bo4   = (const float*)d_in[16];
    const float* ln4g  = (const float*)d_in[17];
    const float* ln4b  = (const float*)d_in[18];
    const float* w_ih  = (const float*)d_in[19];
    const float* w_hh  = (const float*)d_in[20];
    const float* b_ih  = (const float*)d_in[21];
    const float* b_hh  = (const float*)d_in[22];
    const float* cg_w  = (const float*)d_in[23];
    const float* cg_uw = (const float*)d_in[24];
    const float* cg_ub = (const float*)d_in[25];
    const float* w6    = (const float*)d_in[26];
    const float* b6    = (const float*)d_in[27];
    const float* w7    = (const float*)d_in[28];
    const float* b7    = (const float*)d_in[29];
    const float* rev_w = (const float*)d_in[30];
    const float* rev_b = (const float*)d_in[31];
    float* out = (float*)d_out;

    k_transpose_w<<<(4*HB*HB + 255)/256, 256>>>(wq4, wk4, wv4, wo4);
    k_attn2<<<BATCH, 128>>>(x, bn_g, bn_b, bn_m, bn_v, wq2, wk2, wv2, wo2, bo2, ln2g, ln2b);
    k_attn4<<<NSEQ/16, 128>>>(bo4, ln4g, ln4b);
    k_cglstm_mma<<<NSEQ/64, 128>>>(w_ih, w_hh, b_ih, b_hh, cg_w, cg_uw, cg_ub, out);
    k_head<<<BATCH, 160>>>(w6, b6, w7, b7, rev_w, rev_b, out, out + (size_t)BATCH*288);
}

// round 10
// speedup vs baseline: 3.3339x; 1.0706x over previous
#include <cuda_runtime.h>
#include <cuda_bf16.h>
#include <cstdint>

#define BATCH 16384
#define HB 120
#define BD 9
#define NSEQ (BATCH*BD)   /* 147456 */
#define NS 32
#define NF 15

// scratch (no cudaMalloc allowed)
__device__ float g_buf1[NSEQ*HB];      // attn2 output, transposed: [(b*9+d)*120 + s]
__device__ float g_xT[HB*NSEQ];        // attn4 output, time-major: [t*NSEQ + n]
__device__ float g_wT[4*HB*HB];        // transposed wq4,wk4,wv4,wo4

__device__ __forceinline__ float phif(float x){ return x>0.0f ? x+1.0f : __expf(x); }
// sigmoid from PRE-HALVED pre-activation a' = a/2:  sig(a)=0.5*tanh(a/2)+0.5
__device__ __forceinline__ float sigp(float xh){
    float t;
    asm("tanh.approx.f32 %0, %1;" : "=f"(t) : "f"(xh));
    return fmaf(0.5f, t, 0.5f);
}
__device__ __forceinline__ float tanht(float x){
    float t;
    asm("tanh.approx.f32 %0, %1;" : "=f"(t) : "f"(x));
    return t;
}

typedef unsigned long long ull;
__device__ __forceinline__ ull pack2(float lo, float hi){
    ull r; asm("mov.b64 %0, {%1, %2};" : "=l"(r) : "f"(lo), "f"(hi)); return r;
}
__device__ __forceinline__ float2 unpack2(ull v){
    float2 f; asm("mov.b64 {%0, %1}, %2;" : "=f"(f.x), "=f"(f.y) : "l"(v)); return f;
}
__device__ __forceinline__ void ffma2(ull &d, ull a, ull b){
    asm("fma.rn.f32x2 %0, %1, %2, %0;" : "+l"(d) : "l"(a), "l"(b));
}

// warp-level bf16 MMA (generic PTX, sm_80+; compiles for plain compute_103)
__device__ __forceinline__ void mma16816(float* d, const uint32_t* a, const uint32_t* b, const float* c){
    asm volatile(
        "mma.sync.aligned.m16n8k16.row.col.f32.bf16.bf16.f32 "
        "{%0,%1,%2,%3}, {%4,%5,%6,%7}, {%8,%9}, {%10,%11,%12,%13};"
        : "=f"(d[0]), "=f"(d[1]), "=f"(d[2]), "=f"(d[3])
        : "r"(a[0]), "r"(a[1]), "r"(a[2]), "r"(a[3]),
          "r"(b[0]), "r"(b[1]),
          "f"(c[0]), "f"(c[1]), "f"(c[2]), "f"(c[3]));
}

// ---------------------------------------------------------------- weights transpose
__global__ void k_transpose_w(const float* __restrict__ wq, const float* __restrict__ wk,
                              const float* __restrict__ wv, const float* __restrict__ wo){
    int idx = blockIdx.x*blockDim.x + threadIdx.x;
    if (idx >= 4*HB*HB) return;
    int m = idx/(HB*HB); int i = idx - m*(HB*HB);
    int a = i/HB, b = i - a*HB;
    const float* src = (m==0)?wq : (m==1)?wk : (m==2)?wv : wo;
    g_wT[idx] = src[b*HB + a];
}

// ---------------------------------------------------------------- BN + lin_attn_2 + transpose
__global__ __launch_bounds__(128) void k_attn2(
    const float* __restrict__ x,
    const float* __restrict__ bng, const float* __restrict__ bnb,
    const float* __restrict__ bnm, const float* __restrict__ bnv,
    const float* __restrict__ wq, const float* __restrict__ wk,
    const float* __restrict__ wv, const float* __restrict__ wo,
    const float* __restrict__ bo, const float* __restrict__ lg,
    const float* __restrict__ lb)
{
    __shared__ float xs[HB*13], qs[HB*13], ks[HB*13], vs[HB*13];
    __shared__ float wqs[81], wks[81], wvs[81], wos[81];
    __shared__ float kvs[81], ksum[9], bos[9], lgs[9], lbs[9];
    int b = blockIdx.x, tid = threadIdx.x;

    for (int i = tid; i < 1080; i += 128){
        float val = (x[(size_t)b*1080 + i] - bnm[i]) * rsqrtf(bnv[i] + 1e-5f) * bng[i] + bnb[i];
        xs[(i/9)*13 + (i%9)] = val;
    }
    if (tid < 81){ wqs[tid]=wq[tid]; wks[tid]=wk[tid]; wvs[tid]=wv[tid]; wos[tid]=wo[tid]; }
    if (tid < 9){ bos[tid]=bo[tid]; lgs[tid]=lg[tid]; lbs[tid]=lb[tid]; }
    __syncthreads();

    if (tid < HB){
        float xr[9];
        #pragma unroll
        for (int d=0; d<9; d++) xr[d] = xs[tid*13+d];
        #pragma unroll
        for (int e=0; e<9; e++){
            float aq=0.f, ak=0.f, av=0.f;
            #pragma unroll
            for (int d=0; d<9; d++){
                aq = fmaf(xr[d], wqs[e*9+d], aq);
                ak = fmaf(xr[d], wks[e*9+d], ak);
                av = fmaf(xr[d], wvs[e*9+d], av);
            }
            qs[tid*13+e] = phif(aq);
            ks[tid*13+e] = phif(ak);
            vs[tid*13+e] = av;
        }
    }
    __syncthreads();

    if (tid < 81){
        int d = tid/9, e = tid%9;
        float acc = 0.f;
        for (int s=0; s<HB; s++) acc = fmaf(ks[s*13+d], vs[s*13+e], acc);
        kvs[tid] = acc;
    } else if (tid < 90){
        int e = tid - 81;
        float acc = 0.f;
        for (int s=0; s<HB; s++) acc += ks[s*13+e];
        ksum[e] = acc;
    }
    __syncthreads();

    if (tid < HB){
        float q[9], o[9];
        float den = 0.f;
        #pragma unroll
        for (int e=0; e<9; e++){ q[e] = qs[tid*13+e]; den = fmaf(q[e], ksum[e], den); }
        float inv = 1.0f / fmaxf(den, 1e-6f);
        #pragma unroll
        for (int e=0; e<9; e++){
            float num = 0.f;
            #pragma unroll
            for (int d=0; d<9; d++) num = fmaf(q[d], kvs[d*9+e], num);
            o[e] = num * inv;
        }
        float y[9]; float mu = 0.f;
        #pragma unroll
        for (int f=0; f<9; f++){
            float acc = bos[f] + o[f];
            #pragma unroll
            for (int e=0; e<9; e++) acc = fmaf(o[e], wos[f*9+e], acc);
            y[f] = acc; mu += acc;
        }
        mu *= (1.0f/9.0f);
        float var = 0.f;
        #pragma unroll
        for (int f=0; f<9; f++){ float dd = y[f]-mu; var = fmaf(dd, dd, var); }
        var *= (1.0f/9.0f);
        float rs = rsqrtf(var + 1e-5f);
        #pragma unroll
        for (int f=0; f<9; f++){
            g_buf1[(size_t)b*1080 + f*HB + tid] = (y[f]-mu)*rs*lgs[f] + lbs[f];
        }
    }
}

// ---------------------------------------------------------------- lin_attn_4 (S=1 collapsed)
__global__ __launch_bounds__(128) void k_attn4(
    const float* __restrict__ bo4, const float* __restrict__ lg4,
    const float* __restrict__ lb4)
{
    __shared__ __align__(16) float xsT[HB*20];
    __shared__ __align__(16) float vsT[HB*20];
    __shared__ float red1[4*16], red2[4*16];
    __shared__ float fac[16], mus[16], rss[16];
    int tid = threadIdx.x;
    int base = blockIdx.x * 16;

    for (int i = tid; i < 16*HB; i += 128){
        int r = i / HB, d = i - r*HB;
        xsT[d*20 + r] = g_buf1[(size_t)(base + r)*HB + d];
    }
    __syncthreads();

    bool valid = tid < HB;
    int e = valid ? tid : 0;
    const float* wqT = g_wT;
    const float* wkT = g_wT + HB*HB;
    const float* wvT = g_wT + 2*HB*HB;
    const float* woT = g_wT + 3*HB*HB;

    ull qa2[8], ka2[8], va2[8];
    #pragma unroll
    for (int r=0; r<8; r++){ qa2[r]=0ull; ka2[r]=0ull; va2[r]=0ull; }

    const ulonglong2* xp2 = (const ulonglong2*)xsT;
    #pragma unroll 2
    for (int d=0; d<HB; d++){
        ull wq2p = pack2(wqT[d*HB + e], wqT[d*HB + e]);
        ull wk2p = pack2(wkT[d*HB + e], wkT[d*HB + e]);
        ull wv2p = pack2(wvT[d*HB + e], wvT[d*HB + e]);
        #pragma unroll
        for (int r=0; r<4; r++){
            ulonglong2 xv = xp2[d*5 + r];
            ffma2(qa2[2*r],   wq2p, xv.x);
            ffma2(qa2[2*r+1], wq2p, xv.y);
            ffma2(ka2[2*r],   wk2p, xv.x);
            ffma2(ka2[2*r+1], wk2p, xv.y);
            ffma2(va2[2*r],   wv2p, xv.x);
            ffma2(va2[2*r+1], wv2p, xv.y);
        }
    }

    float qa[16], ka[16], va[16];
    #pragma unroll
    for (int r=0; r<8; r++){
        float2 q = unpack2(qa2[r]), k = unpack2(ka2[r]), v = unpack2(va2[r]);
        qa[2*r]=q.x; qa[2*r+1]=q.y;
        ka[2*r]=k.x; ka[2*r+1]=k.y;
        va[2*r]=v.x; va[2*r+1]=v.y;
    }

    float qk[16];
    #pragma unroll
    for (int r=0; r<16; r++) qk[r] = valid ? phif(qa[r])*phif(ka[r]) : 0.0f;

    if (valid){
        float4* vp4 = (float4*)&vsT[e*20];
        vp4[0] = make_float4(va[0],va[1],va[2],va[3]);
        vp4[1] = make_float4(va[4],va[5],va[6],va[7]);
        vp4[2] = make_float4(va[8],va[9],va[10],va[11]);
        vp4[3] = make_float4(va[12],va[13],va[14],va[15]);
    }

    #pragma unroll
    for (int off=16; off>0; off>>=1){
        #pragma unroll
        for (int r=0; r<16; r++) qk[r] += __shfl_down_sync(0xffffffffu, qk[r], off);
    }
    int w = tid >> 5, lane = tid & 31;
    if (lane == 0){
        #pragma unroll
        for (int r=0; r<16; r++) red1[w*16 + r] = qk[r];
    }
    __syncthreads();
    if (tid < 16){
        float s = red1[tid] + red1[16+tid] + red1[32+tid] + red1[48+tid];
        fac[tid] = s / fmaxf(s, 1e-6f);
    }
    __syncthreads();

    ull ma2[8];
    #pragma unroll
    for (int r=0; r<8; r++) ma2[r] = 0ull;
    const ulonglong2* vp2 = (const ulonglong2*)vsT;
    #pragma unroll 2
    for (int ee=0; ee<HB; ee++){
        ull wo2p = pack2(woT[ee*HB + e], woT[ee*HB + e]);
        #pragma unroll
        for (int r=0; r<4; r++){
            ulonglong2 vv = vp2[ee*5 + r];
            ffma2(ma2[2*r],   wo2p, vv.x);
            ffma2(ma2[2*r+1], wo2p, vv.y);
        }
    }
    float ma[16];
    #pragma unroll
    for (int r=0; r<8; r++){
        float2 m = unpack2(ma2[r]);
        ma[2*r]=m.x; ma[2*r+1]=m.y;
    }

    float bov = bo4[e];
    float y[16], s1[16], s2[16];
    #pragma unroll
    for (int r=0; r<16; r++){
        y[r] = fmaf(fac[r], ma[r] + va[r], bov);
        s1[r] = valid ? y[r] : 0.f;
        s2[r] = valid ? y[r]*y[r] : 0.f;
    }
    #pragma unroll
    for (int off=16; off>0; off>>=1){
        #pragma unroll
        for (int r=0; r<16; r++){
            s1[r] += __shfl_down_sync(0xffffffffu, s1[r], off);
            s2[r] += __shfl_down_sync(0xffffffffu, s2[r], off);
        }
    }
    if (lane == 0){
        #pragma unroll
        for (int r=0; r<16; r++){ red1[w*16+r] = s1[r]; red2[w*16+r] = s2[r]; }
    }
    __syncthreads();
    if (tid < 16){
        float sy  = red1[tid]+red1[16+tid]+red1[32+tid]+red1[48+tid];
        float sy2 = red2[tid]+red2[16+tid]+red2[32+tid]+red2[48+tid];
        float mu = sy * (1.0f/120.0f);
        float var = sy2 * (1.0f/120.0f) - mu*mu;
        mus[tid] = mu;
        rss[tid] = rsqrtf(var + 1e-5f);
    }
    __syncthreads();
    if (valid){
        float lgv = lg4[e], lbv = lb4[e];
        #pragma unroll
        for (int r=0; r<16; r++){
            float yn = (y[r] - mus[r]) * rss[r];
            g_xT[(size_t)e*NSEQ + base + r] = yn*lgv + lbv;   // time-major for LSTM
        }
    }
}

// ---------------------------------------------------------------- CGLSTM via warp-MMA (bf16 hi/lo)
// CTA = 128 threads, 64 sequences; 3 CTAs/SM for MMA<->MUFU overlap.
// S[64 seqs][72 u16]: cols 0-31 h_hi, 32-63 h_lo, 64-71 pad. Stride 36 u32 (conflict-free).
// W' A-fragments register-resident (Wh0,Wh1,Wl0,Wl1); x*w_ih + bias folded into epilogue FMAs.
#define SST 36   /* S row stride in u32 */
__global__ __launch_bounds__(128, 3) void k_cglstm_mma(
    const float* __restrict__ w_ih, const float* __restrict__ w_hh,
    const float* __restrict__ b_ih, const float* __restrict__ b_hh,
    const float* __restrict__ cg_w, const float* __restrict__ cg_uw,
    const float* __restrict__ cg_ub,
    float* __restrict__ outh)
{
    __shared__ __align__(16) unsigned short sm16[128*72];   // W' staging (18KB), later S overlay
    __shared__ float xs[64];
    uint32_t* sm32 = (uint32_t*)sm16;

    int tid = threadIdx.x;
    int warp = tid >> 5, lane = tid & 31;
    int g = lane >> 2, tg = lane & 3;
    int uh = warp & 1, sh = warp >> 1;

    // ---- build W' bf16 [128 rows][72 cols]: 0-31 W_hi, 32-63 W_lo, 64-71 zero
    for (int idx = tid; idx < 128*72; idx += 128){
        int r = idx / 72, cc = idx - r*72;
        int gate = r >> 5, j = r & 31;
        float v = 0.0f;
        if (cc < 64){
            int k = cc & 31;
            float w = (gate==0) ? w_hh[j*32+k] : (gate==1) ? w_hh[(32+j)*32+k]
                    : (gate==2) ? w_hh[(64+j)*32+k] : cg_uw[j*32+k];
            if (gate != 2) w *= 0.5f;
            float whi = __bfloat162float(__float2bfloat16(w));
            v = (cc < 32) ? whi : (w - whi);
        }
        sm16[idx] = __bfloat16_as_ushort(__float2bfloat16(v));
    }
    __syncthreads();

    // ---- register-resident A fragments: [frag-group Wh0,Wh1,Wl0,Wl1][gate m-tile][4]
    uint32_t afr[4][4][4];
    const int cb2[4] = {0, 8, 16, 24};
    #pragma unroll
    for (int fg = 0; fg < 4; fg++){
        #pragma unroll
        for (int mt = 0; mt < 4; mt++){
            int Rb = mt*32 + uh*16;
            afr[fg][mt][0] = sm32[(Rb+g)*SST   + cb2[fg] + tg];
            afr[fg][mt][1] = sm32[(Rb+g+8)*SST + cb2[fg] + tg];
            afr[fg][mt][2] = sm32[(Rb+g)*SST   + cb2[fg] + tg + 4];
            afr[fg][mt][3] = sm32[(Rb+g+8)*SST + cb2[fg] + tg + 4];
        }
    }

    // ---- x-weights and biases for this thread's 2 units (pre-halved for sigmoid gates)
    float wxr[4][2], br[4][2];
    #pragma unroll
    for (int ui = 0; ui < 2; ui++){
        int u = uh*16 + g + ui*8;
        wxr[0][ui] = w_ih[u]*0.5f;     br[0][ui] = (b_ih[u]    + b_hh[u])*0.5f;
        wxr[1][ui] = w_ih[32+u]*0.5f;  br[1][ui] = (b_ih[32+u] + b_hh[32+u])*0.5f;
        wxr[2][ui] = w_ih[64+u];       br[2][ui] =  b_ih[64+u] + b_hh[64+u];
        wxr[3][ui] = cg_w[u]*0.5f;     br[3][ui] =  cg_ub[u]*0.5f;
    }
    __syncthreads();   // W' reads done — overlay S

    // ---- init S = 0 (h0 = 0), stage x(0), prefetch x(1)
    for (int i = tid; i < 64*SST; i += 128) sm32[i] = 0u;
    int base = blockIdx.x * 64;
    if (tid < 64) xs[tid] = g_xT[base + tid];
    float xv = (tid < 64) ? g_xT[(size_t)NSEQ + base + tid] : 0.0f;
    __syncthreads();

    float c[16], hn[16];
    #pragma unroll
    for (int i = 0; i < 16; i++){ c[i] = 0.f; hn[i] = 0.f; }
    const float z4[4] = {0.f, 0.f, 0.f, 0.f};

    for (int t = 0; t < HB; t++){
        #pragma unroll
        for (int nt = 0; nt < 4; nt++){
            int rn = sh*32 + nt*8 + g;
            const uint32_t* Srow = &sm32[rn*SST];
            uint32_t b[4][2];
            #pragma unroll
            for (int kt = 0; kt < 4; kt++){
                b[kt][0] = Srow[kt*8 + tg];
                b[kt][1] = Srow[kt*8 + tg + 4];
            }
            float acc[4][4];
            #pragma unroll
            for (int mt = 0; mt < 4; mt++){
                mma16816(acc[mt], afr[0][mt], b[0], z4);       // Wh0 * h_hi0
                mma16816(acc[mt], afr[1][mt], b[1], acc[mt]);  // Wh1 * h_hi1
                mma16816(acc[mt], afr[2][mt], b[0], acc[mt]);  // Wl0 * h_hi0
                mma16816(acc[mt], afr[3][mt], b[1], acc[mt]);  // Wl1 * h_hi1
                mma16816(acc[mt], afr[0][mt], b[2], acc[mt]);  // Wh0 * h_lo0
                mma16816(acc[mt], afr[1][mt], b[3], acc[mt]);  // Wh1 * h_lo1
            }
            // epilogue for this nt's 4 elements (x & bias folded here, fp32-exact)
            #pragma unroll
            for (int j = 0; j < 4; j++){
                int srow = sh*32 + nt*8 + 2*tg + (j & 1);
                float x = xs[srow];
                int ui = j >> 1;
                float gi = acc[0][j] + fmaf(wxr[0][ui], x, br[0][ui]);
                float gf = acc[1][j] + fmaf(wxr[1][ui], x, br[1][ui]);
                float gg = acc[2][j] + fmaf(wxr[2][ui], x, br[2][ui]);
                float gc = acc[3][j] + fmaf(wxr[3][ui], x, br[3][ui]);
                int ci = nt*4 + j;
                float cn = sigp(gf)*c[ci] + sigp(gi)*tanht(gg);
                c[ci] = cn;
                hn[ci] = sigp(gc)*tanht(cn);
            }
        }
        __syncthreads();   // all B + xs reads done before overwrites

        // ---- store h(t) hi/lo into S; stage x(t+1); prefetch x(t+2)
        #pragma unroll
        for (int nt = 0; nt < 4; nt++){
            #pragma unroll
            for (int j = 0; j < 4; j++){
                int u = uh*16 + g + ((j >> 1) << 3);
                int srow = sh*32 + nt*8 + 2*tg + (j & 1);
                float h = hn[nt*4 + j];
                __nv_bfloat16 hh = __float2bfloat16(h);
                __nv_bfloat16 hl = __float2bfloat16(h - __bfloat162float(hh));
                sm16[srow*72 + u]      = __bfloat16_as_ushort(hh);
                sm16[srow*72 + 32 + u] = __bfloat16_as_ushort(hl);
            }
        }
        if (tid < 64) xs[tid] = xv;
        if (t + 2 < HB && tid < 64) xv = g_xT[(size_t)(t+2)*NSEQ + base + tid];
        __syncthreads();
    }

    // ---- write final h
    #pragma unroll
    for (int nt = 0; nt < 4; nt++){
        #pragma unroll
        for (int j = 0; j < 4; j++){
            int u = uh*16 + g + ((j >> 1) << 3);
            int srow = sh*32 + nt*8 + 2*tg + (j & 1);
            outh[(size_t)(base + srow)*32 + u] = hn[nt*4 + j];
        }
    }
}

// ---------------------------------------------------------------- conv6/7 + permute + RevIN
__global__ __launch_bounds__(160) void k_head(
    const float* __restrict__ w6, const float* __restrict__ b6,
    const float* __restrict__ w7, const float* __restrict__ b7,
    const float* __restrict__ rev_w, const float* __restrict__ rev_b,
    const float* __restrict__ hin, float* __restrict__ enc)
{
    __shared__ float hs[288], w6s[60*32], w7s[15*60], b6s[60], b7s[15];
    __shared__ float t60s[9*60], t135[135];
    __shared__ float smu, sinv;
    __shared__ float part1[5], part2[5];
    int b = blockIdx.x, tid = threadIdx.x;

    for (int i = tid; i < 60*32; i += 160) w6s[i] = w6[i];
    for (int i = tid; i < 15*60; i += 160) w7s[i] = w7[i];
    if (tid < 60) b6s[tid] = b6[tid];
    if (tid < 15) b7s[tid] = b7[tid];
    for (int i = tid; i < 288; i += 160) hs[i] = hin[(size_t)b*288 + i];
    __syncthreads();

    for (int i = tid; i < 540; i += 160){
        int dd = i/60, u = i - dd*60;
        float acc = b6s[u];
        #pragma unroll 8
        for (int k=0; k<32; k++) acc = fmaf(w6s[u*32+k], hs[dd*32+k], acc);
        t60s[i] = fmaxf(acc, 0.0f) + log1pf(__expf(-fabsf(acc)));
    }
    __syncthreads();
    if (tid < 135){
        int dd = tid/15, f = tid - dd*15;
        float acc = b7s[f];
        #pragma unroll 6
        for (int u=0; u<60; u++) acc = fmaf(w7s[f*60+u], t60s[dd*60+u], acc);
        t135[tid] = tanhf(acc);
    }
    __syncthreads();
    float v  = (tid < 135) ? t135[tid] : 0.0f;
    float v2 = v*v;
    #pragma unroll
    for (int off=16; off>0; off>>=1){
        v  += __shfl_down_sync(0xffffffffu, v,  off);
        v2 += __shfl_down_sync(0xffffffffu, v2, off);
    }
    if ((tid & 31) == 0){ part1[tid>>5] = v; part2[tid>>5] = v2; }
    __syncthreads();
    if (tid == 0){
        float s1 = 0.f, s2 = 0.f;
        #pragma unroll
        for (int w=0; w<5; w++){ s1 += part1[w]; s2 += part2[w]; }
        float mu = s1 * (1.0f/135.0f);
        float var = fmaxf((s2 - 135.0f*mu*mu) * (1.0f/134.0f), 0.0f);
        float sd = fmaxf(sqrtf(var), 1e-5f);
        smu = mu; sinv = 1.0f/sd;
    }
    __syncthreads();
    if (tid < 135){
        int dp = tid/15, fp = tid - dp*15;
        float yv = t135[fp*9 + dp];       // transpose_8
        enc[(size_t)b*135 + tid] = (yv - smu)*sinv*rev_w[tid] + rev_b[tid];
    }
}

// ---------------------------------------------------------------- launch
extern "C" void kernel_launch(void* const* d_in, const int* in_sizes, int n_in,
                              void* d_out, int out_size)
{
    const float* x     = (const float*)d_in[0];
    const float* bn_g  = (const float*)d_in[1];
    const float* bn_b  = (const float*)d_in[2];
    const float* bn_m  = (const float*)d_in[3];
    const float* bn_v  = (const float*)d_in[4];
    const float* wq2   = (const float*)d_in[5];
    const float* wk2   = (const float*)d_in[6];
    const float* wv2   = (const float*)d_in[7];
    const float* wo2   = (const float*)d_in[8];
    const float* bo2   = (const float*)d_in[9];
    const float* ln2g  = (const float*)d_in[10];
    const float* ln2b  = (const float*)d_in[11];
    const float* wq4   = (const float*)d_in[12];
    const float* wk4   = (const float*)d_in[13];
    const float* wv4   = (const float*)d_in[14];
    const float* wo4   = (const float*)d_in[15];
    const float* bo4   = (const float*)d_in[16];
    const float* ln4g  = (const float*)d_in[17];
    const float* ln4b  = (const float*)d_in[18];
    const float* w_ih  = (const float*)d_in[19];
    const float* w_hh  = (const float*)d_in[20];
    const float* b_ih  = (const float*)d_in[21];
    const float* b_hh  = (const float*)d_in[22];
    const float* cg_w  = (const float*)d_in[23];
    const float* cg_uw = (const float*)d_in[24];
    const float* cg_ub = (const float*)d_in[25];
    const float* w6    = (const float*)d_in[26];
    const float* b6    = (const float*)d_in[27];
    const float* w7    = (const float*)d_in[28];
    const float* b7    = (const float*)d_in[29];
    const float* rev_w = (const float*)d_in[30];
    const float* rev_b = (const float*)d_in[31];
    float* out = (float*)d_out;

    k_transpose_w<<<(4*HB*HB + 255)/256, 256>>>(wq4, wk4, wv4, wo4);
    k_attn2<<<BATCH, 128>>>(x, bn_g, bn_b, bn_m, bn_v, wq2, wk2, wv2, wo2, bo2, ln2g, ln2b);
    k_attn4<<<NSEQ/16, 128>>>(bo4, ln4g, ln4b);
    k_cglstm_mma<<<NSEQ/64, 128>>>(w_ih, w_hh, b_ih, b_hh, cg_w, cg_uw, cg_ub, out);
    k_head<<<BATCH, 160>>>(w6, b6, w7, b7, rev_w, rev_b, out, out + (size_t)BATCH*288);
}

// round 11
// speedup vs baseline: 3.5486x; 1.0644x over previous
#include <cuda_runtime.h>
#include <cuda_bf16.h>
#include <cstdint>

#define BATCH 16384
#define HB 120
#define BD 9
#define NSEQ (BATCH*BD)   /* 147456 */
#define NS 32
#define NF 15

// scratch (no cudaMalloc allowed)
__device__ float g_buf1[NSEQ*HB];      // attn2 output, transposed: [(b*9+d)*120 + s]
__device__ float g_xT[HB*NSEQ];        // attn4 output, time-major: [t*NSEQ + n]
__device__ unsigned short g_wbf_hi[4*128*128];  // wq,wk,wv,wo bf16-hi, [m][n(128)][k(128)], zero-padded
__device__ unsigned short g_wbf_lo[4*128*128];  // bf16-lo residuals

__device__ __forceinline__ float phif(float x){ return x>0.0f ? x+1.0f : __expf(x); }
// sigmoid from PRE-HALVED pre-activation a' = a/2:  sig(a)=0.5*tanh(a/2)+0.5
__device__ __forceinline__ float sigp(float xh){
    float t;
    asm("tanh.approx.f32 %0, %1;" : "=f"(t) : "f"(xh));
    return fmaf(0.5f, t, 0.5f);
}
__device__ __forceinline__ float tanht(float x){
    float t;
    asm("tanh.approx.f32 %0, %1;" : "=f"(t) : "f"(x));
    return t;
}

// warp-level bf16 MMA (generic PTX, sm_80+; compiles for plain compute_103)
__device__ __forceinline__ void mma16816(float* d, const uint32_t* a, const uint32_t* b, const float* c){
    asm volatile(
        "mma.sync.aligned.m16n8k16.row.col.f32.bf16.bf16.f32 "
        "{%0,%1,%2,%3}, {%4,%5,%6,%7}, {%8,%9}, {%10,%11,%12,%13};"
        : "=f"(d[0]), "=f"(d[1]), "=f"(d[2]), "=f"(d[3])
        : "r"(a[0]), "r"(a[1]), "r"(a[2]), "r"(a[3]),
          "r"(b[0]), "r"(b[1]),
          "f"(c[0]), "f"(c[1]), "f"(c[2]), "f"(c[3]));
}

// ---------------------------------------------------------------- weights -> bf16 hi/lo (padded 128x128)
__global__ void k_wbf(const float* __restrict__ wq, const float* __restrict__ wk,
                      const float* __restrict__ wv, const float* __restrict__ wo){
    int idx = blockIdx.x*256 + threadIdx.x;
    if (idx >= 4*128*128) return;
    int m = idx >> 14, rem = idx & 16383, n = rem >> 7, k = rem & 127;
    const float* W = (m==0)?wq : (m==1)?wk : (m==2)?wv : wo;
    float v = (n < HB && k < HB) ? W[n*HB + k] : 0.0f;
    __nv_bfloat16 h = __float2bfloat16(v);
    g_wbf_hi[idx] = __bfloat16_as_ushort(h);
    g_wbf_lo[idx] = __bfloat16_as_ushort(__float2bfloat16(v - __bfloat162float(h)));
}

// ---------------------------------------------------------------- BN + lin_attn_2 + transpose
__global__ __launch_bounds__(128) void k_attn2(
    const float* __restrict__ x,
    const float* __restrict__ bng, const float* __restrict__ bnb,
    const float* __restrict__ bnm, const float* __restrict__ bnv,
    const float* __restrict__ wq, const float* __restrict__ wk,
    const float* __restrict__ wv, const float* __restrict__ wo,
    const float* __restrict__ bo, const float* __restrict__ lg,
    const float* __restrict__ lb)
{
    __shared__ float xs[HB*13], qs[HB*13], ks[HB*13], vs[HB*13];
    __shared__ float wqs[81], wks[81], wvs[81], wos[81];
    __shared__ float kvs[81], ksum[9], bos[9], lgs[9], lbs[9];
    int b = blockIdx.x, tid = threadIdx.x;

    for (int i = tid; i < 1080; i += 128){
        float val = (x[(size_t)b*1080 + i] - bnm[i]) * rsqrtf(bnv[i] + 1e-5f) * bng[i] + bnb[i];
        xs[(i/9)*13 + (i%9)] = val;
    }
    if (tid < 81){ wqs[tid]=wq[tid]; wks[tid]=wk[tid]; wvs[tid]=wv[tid]; wos[tid]=wo[tid]; }
    if (tid < 9){ bos[tid]=bo[tid]; lgs[tid]=lg[tid]; lbs[tid]=lb[tid]; }
    __syncthreads();

    if (tid < HB){
        float xr[9];
        #pragma unroll
        for (int d=0; d<9; d++) xr[d] = xs[tid*13+d];
        #pragma unroll
        for (int e=0; e<9; e++){
            float aq=0.f, ak=0.f, av=0.f;
            #pragma unroll
            for (int d=0; d<9; d++){
                aq = fmaf(xr[d], wqs[e*9+d], aq);
                ak = fmaf(xr[d], wks[e*9+d], ak);
                av = fmaf(xr[d], wvs[e*9+d], av);
            }
            qs[tid*13+e] = phif(aq);
            ks[tid*13+e] = phif(ak);
            vs[tid*13+e] = av;
        }
    }
    __syncthreads();

    if (tid < 81){
        int d = tid/9, e = tid%9;
        float a0=0.f, a1=0.f, a2=0.f, a3=0.f;
        #pragma unroll 4
        for (int s=0; s<HB; s+=4){
            a0 = fmaf(ks[(s  )*13+d], vs[(s  )*13+e], a0);
            a1 = fmaf(ks[(s+1)*13+d], vs[(s+1)*13+e], a1);
            a2 = fmaf(ks[(s+2)*13+d], vs[(s+2)*13+e], a2);
            a3 = fmaf(ks[(s+3)*13+d], vs[(s+3)*13+e], a3);
        }
        kvs[tid] = (a0+a1)+(a2+a3);
    } else if (tid < 90){
        int e = tid - 81;
        float a0=0.f, a1=0.f, a2=0.f, a3=0.f;
        #pragma unroll 4
        for (int s=0; s<HB; s+=4){
            a0 += ks[(s  )*13+e];
            a1 += ks[(s+1)*13+e];
            a2 += ks[(s+2)*13+e];
            a3 += ks[(s+3)*13+e];
        }
        ksum[e] = (a0+a1)+(a2+a3);
    }
    __syncthreads();

    if (tid < HB){
        float q[9], o[9];
        float den = 0.f;
        #pragma unroll
        for (int e=0; e<9; e++){ q[e] = qs[tid*13+e]; den = fmaf(q[e], ksum[e], den); }
        float inv = 1.0f / fmaxf(den, 1e-6f);
        #pragma unroll
        for (int e=0; e<9; e++){
            float num = 0.f;
            #pragma unroll
            for (int d=0; d<9; d++) num = fmaf(q[d], kvs[d*9+e], num);
            o[e] = num * inv;
        }
        float y[9]; float mu = 0.f;
        #pragma unroll
        for (int f=0; f<9; f++){
            float acc = bos[f] + o[f];
            #pragma unroll
            for (int e=0; e<9; e++) acc = fmaf(o[e], wos[f*9+e], acc);
            y[f] = acc; mu += acc;
        }
        mu *= (1.0f/9.0f);
        float var = 0.f;
        #pragma unroll
        for (int f=0; f<9; f++){ float dd = y[f]-mu; var = fmaf(dd, dd, var); }
        var *= (1.0f/9.0f);
        float rs = rsqrtf(var + 1e-5f);
        #pragma unroll
        for (int f=0; f<9; f++){
            g_buf1[(size_t)b*1080 + f*HB + tid] = (y[f]-mu)*rs*lgs[f] + lbs[f];
        }
    }
}

// ---------------------------------------------------------------- lin_attn_4 via warp-MMA (bf16 hi/lo)
// Block = 32 sequences (2 m-tiles), N=128 outputs (16 n-tiles, 4/warp), K=128 (8 k-tiles), 3 hi/lo passes.
// Fragment index patterns identical to the verified cglstm_mma kernel.
#define PL 2176   /* 32 rows * 68 u32 per plane */

__device__ __forceinline__ void proj_mma(
    float acc[4][2][4],
    const uint32_t* Ah, const uint32_t* Al,
    const uint32_t* __restrict__ Bh, const uint32_t* __restrict__ Bl,
    int g, int tg, int w)
{
    #pragma unroll
    for (int nt=0; nt<4; nt++)
        #pragma unroll
        for (int mt=0; mt<2; mt++)
            #pragma unroll
            for (int j=0; j<4; j++) acc[nt][mt][j] = 0.0f;

    #pragma unroll
    for (int kt=0; kt<8; kt++){
        uint32_t axh[2][4], axl[2][4];
        #pragma unroll
        for (int mt=0; mt<2; mt++){
            int Rb = mt*16;
            axh[mt][0]=Ah[(Rb+g  )*68 + kt*8+tg];   axh[mt][1]=Ah[(Rb+g+8)*68 + kt*8+tg];
            axh[mt][2]=Ah[(Rb+g  )*68 + kt*8+tg+4]; axh[mt][3]=Ah[(Rb+g+8)*68 + kt*8+tg+4];
            axl[mt][0]=Al[(Rb+g  )*68 + kt*8+tg];   axl[mt][1]=Al[(Rb+g+8)*68 + kt*8+tg];
            axl[mt][2]=Al[(Rb+g  )*68 + kt*8+tg+4]; axl[mt][3]=Al[(Rb+g+8)*68 + kt*8+tg+4];
        }
        #pragma unroll
        for (int nt=0; nt<4; nt++){
            int n = (w*4+nt)*8 + g;
            uint32_t bh[2], bl[2];
            bh[0]=Bh[n*64 + kt*8 + tg]; bh[1]=Bh[n*64 + kt*8 + tg + 4];
            bl[0]=Bl[n*64 + kt*8 + tg]; bl[1]=Bl[n*64 + kt*8 + tg + 4];
            #pragma unroll
            for (int mt=0; mt<2; mt++){
                mma16816(acc[nt][mt], axh[mt], bh, acc[nt][mt]);
                mma16816(acc[nt][mt], axl[mt], bh, acc[nt][mt]);
                mma16816(acc[nt][mt], axh[mt], bl, acc[nt][mt]);
            }
        }
    }
}

__global__ __launch_bounds__(128, 3) void k_attn4_mma(
    const float* __restrict__ bo4, const float* __restrict__ lg4,
    const float* __restrict__ lb4)
{
    __shared__ __align__(16) uint32_t planes[4*PL];   // xh | xl | vh | vl
    __shared__ float sdot[4][32], facs[32];
    __shared__ float red1[4][32], red2[4][32], mus[32], rss[32];
    __shared__ float sbo[HB], slg[HB], slb[HB];

    uint32_t* xh = planes;        uint32_t* xl = planes +   PL;
    uint32_t* vh = planes + 2*PL; uint32_t* vl = planes + 3*PL;
    unsigned short* xh16 = (unsigned short*)xh;
    unsigned short* xl16 = (unsigned short*)xl;

    int tid = threadIdx.x, w = tid >> 5, lane = tid & 31, g = lane >> 2, tg = lane & 3;
    int base = blockIdx.x * 32;

    for (int i = tid; i < 4*PL; i += 128) planes[i] = 0u;
    if (tid < HB){ sbo[tid] = bo4[tid]; slg[tid] = lg4[tid]; slb[tid] = lb4[tid]; }
    __syncthreads();

    // stage x as bf16 hi/lo, [row r][k d], stride 136 u16
    for (int idx = tid; idx < 32*HB; idx += 128){
        int r = idx/HB, d = idx - r*HB;
        float val = g_buf1[(size_t)(base+r)*HB + d];
        __nv_bfloat16 h = __float2bfloat16(val);
        xh16[r*136 + d] = __bfloat16_as_ushort(h);
        xl16[r*136 + d] = __bfloat16_as_ushort(__float2bfloat16(val - __bfloat162float(h)));
    }
    __syncthreads();

    const uint32_t* Wh = (const uint32_t*)g_wbf_hi;
    const uint32_t* Wl = (const uint32_t*)g_wbf_lo;

    // Q and K projections + masked phi-dot
    float qac[4][2][4];
    proj_mma(qac, xh, xl, Wh + 0*8192, Wl + 0*8192, g, tg, w);
    float kac[4][2][4];
    proj_mma(kac, xh, xl, Wh + 1*8192, Wl + 1*8192, g, tg, w);

    float dot[2][2] = {{0.f,0.f},{0.f,0.f}};
    #pragma unroll
    for (int nt=0; nt<4; nt++)
        #pragma unroll
        for (int mt=0; mt<2; mt++)
            #pragma unroll
            for (int j=0; j<4; j++){
                int e = w*32 + nt*8 + 2*tg + (j&1);
                if (e < HB)
                    dot[mt][j>>1] += phif(qac[nt][mt][j]) * phif(kac[nt][mt][j]);
            }
    #pragma unroll
    for (int mt=0; mt<2; mt++)
        #pragma unroll
        for (int jj=0; jj<2; jj++){
            float v = dot[mt][jj];
            v += __shfl_xor_sync(0xffffffffu, v, 1);
            v += __shfl_xor_sync(0xffffffffu, v, 2);
            if (tg == 0) sdot[w][mt*16 + g + 8*jj] = v;
        }
    __syncthreads();
    if (tid < 32){
        float s = sdot[0][tid] + sdot[1][tid] + sdot[2][tid] + sdot[3][tid];
        facs[tid] = s / fmaxf(s, 1e-6f);
    }

    // V projection: keep fp32 in regs + write bf16 hi/lo planes for the O-MMA
    float vac[4][2][4];
    proj_mma(vac, xh, xl, Wh + 2*8192, Wl + 2*8192, g, tg, w);
    #pragma unroll
    for (int nt=0; nt<4; nt++)
        #pragma unroll
        for (int mt=0; mt<2; mt++)
            #pragma unroll
            for (int jj=0; jj<2; jj++){
                float v0 = vac[nt][mt][2*jj], v1 = vac[nt][mt][2*jj+1];
                __nv_bfloat16 h0 = __float2bfloat16(v0), h1 = __float2bfloat16(v1);
                uint32_t hp = (uint32_t)__bfloat16_as_ushort(h0) | ((uint32_t)__bfloat16_as_ushort(h1) << 16);
                __nv_bfloat16 l0 = __float2bfloat16(v0 - __bfloat162float(h0));
                __nv_bfloat16 l1 = __float2bfloat16(v1 - __bfloat162float(h1));
                uint32_t lp = (uint32_t)__bfloat16_as_ushort(l0) | ((uint32_t)__bfloat16_as_ushort(l1) << 16);
                int r = mt*16 + g + 8*jj;
                int e2 = w*16 + nt*4 + tg;
                vh[r*68 + e2] = hp;
                vl[r*68 + e2] = lp;
            }
    __syncthreads();   // v planes + facs visible

    // O projection
    float oac[4][2][4];
    proj_mma(oac, vh, vl, Wh + 3*8192, Wl + 3*8192, g, tg, w);

    // y = fac*(O + V) + bo, then LN over 120 f's
    float fr[2][2];
    #pragma unroll
    for (int mt=0; mt<2; mt++)
        #pragma unroll
        for (int jj=0; jj<2; jj++) fr[mt][jj] = facs[mt*16 + g + 8*jj];

    float s1[2][2] = {{0.f,0.f},{0.f,0.f}}, s2[2][2] = {{0.f,0.f},{0.f,0.f}};
    #pragma unroll
    for (int nt=0; nt<4; nt++)
        #pragma unroll
        for (int mt=0; mt<2; mt++)
            #pragma unroll
            for (int j=0; j<4; j++){
                int f = w*32 + nt*8 + 2*tg + (j&1);
                int fc = (f < HB) ? f : 0;
                float y = fmaf(fr[mt][j>>1], oac[nt][mt][j] + vac[nt][mt][j], sbo[fc]);
                oac[nt][mt][j] = y;   // reuse as y storage
                if (f < HB){ s1[mt][j>>1] += y; s2[mt][j>>1] += y*y; }
            }
    #pragma unroll
    for (int mt=0; mt<2; mt++)
        #pragma unroll
        for (int jj=0; jj<2; jj++){
            float a = s1[mt][jj], b = s2[mt][jj];
            a += __shfl_xor_sync(0xffffffffu, a, 1);
            a += __shfl_xor_sync(0xffffffffu, a, 2);
            b += __shfl_xor_sync(0xffffffffu, b, 1);
            b += __shfl_xor_sync(0xffffffffu, b, 2);
            if (tg == 0){ red1[w][mt*16 + g + 8*jj] = a; red2[w][mt*16 + g + 8*jj] = b; }
        }
    __syncthreads();
    if (tid < 32){
        float a = red1[0][tid] + red1[1][tid] + red1[2][tid] + red1[3][tid];
        float b = red2[0][tid] + red2[1][tid] + red2[2][tid] + red2[3][tid];
        float mu = a * (1.0f/120.0f);
        float var = b * (1.0f/120.0f) - mu*mu;
        mus[tid] = mu;
        rss[tid] = rsqrtf(var + 1e-5f);
    }
    __syncthreads();

    #pragma unroll
    for (int nt=0; nt<4; nt++)
        #pragma unroll
        for (int mt=0; mt<2; mt++)
            #pragma unroll
            for (int j=0; j<4; j++){
                int f = w*32 + nt*8 + 2*tg + (j&1);
                if (f < HB){
                    int r = mt*16 + g + 8*(j>>1);
                    float yn = (oac[nt][mt][j] - mus[r]) * rss[r];
                    g_xT[(size_t)f*NSEQ + base + r] = yn*slg[f] + slb[f];
                }
            }
}

// ---------------------------------------------------------------- CGLSTM via warp-MMA (bf16 hi/lo)
#define SST 36   /* S row stride in u32 */
__global__ __launch_bounds__(128, 3) void k_cglstm_mma(
    const float* __restrict__ w_ih, const float* __restrict__ w_hh,
    const float* __restrict__ b_ih, const float* __restrict__ b_hh,
    const float* __restrict__ cg_w, const float* __restrict__ cg_uw,
    const float* __restrict__ cg_ub,
    float* __restrict__ outh)
{
    __shared__ __align__(16) unsigned short sm16[128*72];   // W' staging (18KB), later S overlay
    __shared__ float xs[64];
    uint32_t* sm32 = (uint32_t*)sm16;

    int tid = threadIdx.x;
    int warp = tid >> 5, lane = tid & 31;
    int g = lane >> 2, tg = lane & 3;
    int uh = warp & 1, sh = warp >> 1;

    for (int idx = tid; idx < 128*72; idx += 128){
        int r = idx / 72, cc = idx - r*72;
        int gate = r >> 5, j = r & 31;
        float v = 0.0f;
        if (cc < 64){
            int k = cc & 31;
            float w = (gate==0) ? w_hh[j*32+k] : (gate==1) ? w_hh[(32+j)*32+k]
                    : (gate==2) ? w_hh[(64+j)*32+k] : cg_uw[j*32+k];
            if (gate != 2) w *= 0.5f;
            float whi = __bfloat162float(__float2bfloat16(w));
            v = (cc < 32) ? whi : (w - whi);
        }
        sm16[idx] = __bfloat16_as_ushort(__float2bfloat16(v));
    }
    __syncthreads();

    uint32_t afr[4][4][4];
    const int cb2[4] = {0, 8, 16, 24};
    #pragma unroll
    for (int fg = 0; fg < 4; fg++){
        #pragma unroll
        for (int mt = 0; mt < 4; mt++){
            int Rb = mt*32 + uh*16;
            afr[fg][mt][0] = sm32[(Rb+g)*SST   + cb2[fg] + tg];
            afr[fg][mt][1] = sm32[(Rb+g+8)*SST + cb2[fg] + tg];
            afr[fg][mt][2] = sm32[(Rb+g)*SST   + cb2[fg] + tg + 4];
            afr[fg][mt][3] = sm32[(Rb+g+8)*SST + cb2[fg] + tg + 4];
        }
    }

    float wxr[4][2], br[4][2];
    #pragma unroll
    for (int ui = 0; ui < 2; ui++){
        int u = uh*16 + g + ui*8;
        wxr[0][ui] = w_ih[u]*0.5f;     br[0][ui] = (b_ih[u]    + b_hh[u])*0.5f;
        wxr[1][ui] = w_ih[32+u]*0.5f;  br[1][ui] = (b_ih[32+u] + b_hh[32+u])*0.5f;
        wxr[2][ui] = w_ih[64+u];       br[2][ui] =  b_ih[64+u] + b_hh[64+u];
        wxr[3][ui] = cg_w[u]*0.5f;     br[3][ui] =  cg_ub[u]*0.5f;
    }
    __syncthreads();

    for (int i = tid; i < 64*SST; i += 128) sm32[i] = 0u;
    int base = blockIdx.x * 64;
    if (tid < 64) xs[tid] = g_xT[base + tid];
    float xv = (tid < 64) ? g_xT[(size_t)NSEQ + base + tid] : 0.0f;
    __syncthreads();

    float c[16], hn[16];
    #pragma unroll
    for (int i = 0; i < 16; i++){ c[i] = 0.f; hn[i] = 0.f; }
    const float z4[4] = {0.f, 0.f, 0.f, 0.f};

    for (int t = 0; t < HB; t++){
        #pragma unroll
        for (int nt = 0; nt < 4; nt++){
            int rn = sh*32 + nt*8 + g;
            const uint32_t* Srow = &sm32[rn*SST];
            uint32_t b[4][2];
            #pragma unroll
            for (int kt = 0; kt < 4; kt++){
                b[kt][0] = Srow[kt*8 + tg];
                b[kt][1] = Srow[kt*8 + tg + 4];
            }
            float acc[4][4];
            #pragma unroll
            for (int mt = 0; mt < 4; mt++){
                mma16816(acc[mt], afr[0][mt], b[0], z4);
                mma16816(acc[mt], afr[1][mt], b[1], acc[mt]);
                mma16816(acc[mt], afr[2][mt], b[0], acc[mt]);
                mma16816(acc[mt], afr[3][mt], b[1], acc[mt]);
                mma16816(acc[mt], afr[0][mt], b[2], acc[mt]);
                mma16816(acc[mt], afr[1][mt], b[3], acc[mt]);
            }
            #pragma unroll
            for (int j = 0; j < 4; j++){
                int srow = sh*32 + nt*8 + 2*tg + (j & 1);
                float x = xs[srow];
                int ui = j >> 1;
                float gi = acc[0][j] + fmaf(wxr[0][ui], x, br[0][ui]);
                float gf = acc[1][j] + fmaf(wxr[1][ui], x, br[1][ui]);
                float gg = acc[2][j] + fmaf(wxr[2][ui], x, br[2][ui]);
                float gc = acc[3][j] + fmaf(wxr[3][ui], x, br[3][ui]);
                int ci = nt*4 + j;
                float cn = sigp(gf)*c[ci] + sigp(gi)*tanht(gg);
                c[ci] = cn;
                hn[ci] = sigp(gc)*tanht(cn);
            }
        }
        __syncthreads();

        #pragma unroll
        for (int nt = 0; nt < 4; nt++){
            #pragma unroll
            for (int j = 0; j < 4; j++){
                int u = uh*16 + g + ((j >> 1) << 3);
                int srow = sh*32 + nt*8 + 2*tg + (j & 1);
                float h = hn[nt*4 + j];
                __nv_bfloat16 hh = __float2bfloat16(h);
                __nv_bfloat16 hl = __float2bfloat16(h - __bfloat162float(hh));
                sm16[srow*72 + u]      = __bfloat16_as_ushort(hh);
                sm16[srow*72 + 32 + u] = __bfloat16_as_ushort(hl);
            }
        }
        if (tid < 64) xs[tid] = xv;
        if (t + 2 < HB && tid < 64) xv = g_xT[(size_t)(t+2)*NSEQ + base + tid];
        __syncthreads();
    }

    #pragma unroll
    for (int nt = 0; nt < 4; nt++){
        #pragma unroll
        for (int j = 0; j < 4; j++){
            int u = uh*16 + g + ((j >> 1) << 3);
            int srow = sh*32 + nt*8 + 2*tg + (j & 1);
            outh[(size_t)(base + srow)*32 + u] = hn[nt*4 + j];
        }
    }
}

// ---------------------------------------------------------------- conv6/7 + permute + RevIN
__global__ __launch_bounds__(160) void k_head(
    const float* __restrict__ w6, const float* __restrict__ b6,
    const float* __restrict__ w7, const float* __restrict__ b7,
    const float* __restrict__ rev_w, const float* __restrict__ rev_b,
    const float* __restrict__ hin, float* __restrict__ enc)
{
    __shared__ float hs[288], w6s[60*32], w7s[15*60], b6s[60], b7s[15];
    __shared__ float t60s[9*60], t135[135];
    __shared__ float smu, sinv;
    __shared__ float part1[5], part2[5];
    int b = blockIdx.x, tid = threadIdx.x;

    for (int i = tid; i < 60*32; i += 160) w6s[i] = w6[i];
    for (int i = tid; i < 15*60; i += 160) w7s[i] = w7[i];
    if (tid < 60) b6s[tid] = b6[tid];
    if (tid < 15) b7s[tid] = b7[tid];
    for (int i = tid; i < 288; i += 160) hs[i] = hin[(size_t)b*288 + i];
    __syncthreads();

    for (int i = tid; i < 540; i += 160){
        int dd = i/60, u = i - dd*60;
        float acc = b6s[u];
        #pragma unroll 8
        for (int k=0; k<32; k++) acc = fmaf(w6s[u*32+k], hs[dd*32+k], acc);
        t60s[i] = fmaxf(acc, 0.0f) + log1pf(__expf(-fabsf(acc)));
    }
    __syncthreads();
    if (tid < 135){
        int dd = tid/15, f = tid - dd*15;
        float acc = b7s[f];
        #pragma unroll 6
        for (int u=0; u<60; u++) acc = fmaf(w7s[f*60+u], t60s[dd*60+u], acc);
        t135[tid] = tanhf(acc);
    }
    __syncthreads();
    float v  = (tid < 135) ? t135[tid] : 0.0f;
    float v2 = v*v;
    #pragma unroll
    for (int off=16; off>0; off>>=1){
        v  += __shfl_down_sync(0xffffffffu, v,  off);
        v2 += __shfl_down_sync(0xffffffffu, v2, off);
    }
    if ((tid & 31) == 0){ part1[tid>>5] = v; part2[tid>>5] = v2; }
    __syncthreads();
    if (tid == 0){
        float s1 = 0.f, s2 = 0.f;
        #pragma unroll
        for (int w=0; w<5; w++){ s1 += part1[w]; s2 += part2[w]; }
        float mu = s1 * (1.0f/135.0f);
        float var = fmaxf((s2 - 135.0f*mu*mu) * (1.0f/134.0f), 0.0f);
        float sd = fmaxf(sqrtf(var), 1e-5f);
        smu = mu; sinv = 1.0f/sd;
    }
    __syncthreads();
    if (tid < 135){
        int dp = tid/15, fp = tid - dp*15;
        float yv = t135[fp*9 + dp];       // transpose_8
        enc[(size_t)b*135 + tid] = (yv - smu)*sinv*rev_w[tid] + rev_b[tid];
    }
}

// ---------------------------------------------------------------- launch
extern "C" void kernel_launch(void* const* d_in, const int* in_sizes, int n_in,
                              void* d_out, int out_size)
{
    const float* x     = (const float*)d_in[0];
    const float* bn_g  = (const float*)d_in[1];
    const float* bn_b  = (const float*)d_in[2];
    const float* bn_m  = (const float*)d_in[3];
    const float* bn_v  = (const float*)d_in[4];
    const float* wq2   = (const float*)d_in[5];
    const float* wk2   = (const float*)d_in[6];
    const float* wv2   = (const float*)d_in[7];
    const float* wo2   = (const float*)d_in[8];
    const float* bo2   = (const float*)d_in[9];
    const float* ln2g  = (const float*)d_in[10];
    const float* ln2b  = (const float*)d_in[11];
    const float* wq4   = (const float*)d_in[12];
    const float* wk4   = (const float*)d_in[13];
    const float* wv4   = (const float*)d_in[14];
    const float* wo4   = (const float*)d_in[15];
    const float* bo4   = (const float*)d_in[16];
    const float* ln4g  = (const float*)d_in[17];
    const float* ln4b  = (const float*)d_in[18];
    const float* w_ih  = (const float*)d_in[19];
    const float* w_hh  = (const float*)d_in[20];
    const float* b_ih  = (const float*)d_in[21];
    const float* b_hh  = (const float*)d_in[22];
    const float* cg_w  = (const float*)d_in[23];
    const float* cg_uw = (const float*)d_in[24];
    const float* cg_ub = (const float*)d_in[25];
    const float* w6    = (const float*)d_in[26];
    const float* b6    = (const float*)d_in[27];
    const float* w7    = (const float*)d_in[28];
    const float* b7    = (const float*)d_in[29];
    const float* rev_w = (const float*)d_in[30];
    const float* rev_b = (const float*)d_in[31];
    float* out = (float*)d_out;

    k_wbf<<<(4*128*128 + 255)/256, 256>>>(wq4, wk4, wv4, wo4);
    k_attn2<<<BATCH, 128>>>(x, bn_g, bn_b, bn_m, bn_v, wq2, wk2, wv2, wo2, bo2, ln2g, ln2b);
    k_attn4_mma<<<NSEQ/32, 128>>>(bo4, ln4g, ln4b);
    k_cglstm_mma<<<NSEQ/64, 128>>>(w_ih, w_hh, b_ih, b_hh, cg_w, cg_uw, cg_ub, out);
    k_head<<<BATCH, 160>>>(w6, b6, w7, b7, rev_w, rev_b, out, out + (size_t)BATCH*288);
}